// round 2
// baseline (speedup 1.0000x reference)
#include <cuda_runtime.h>

// Problem constants
#define BB   2
#define SSQ  2048
#define DDM  1024
#define HH   16
#define DKK  64

// Scratch: intermediates live in __device__ globals (no allocation allowed).
__device__ float g_Q[BB * SSQ * DDM];
__device__ float g_K[BB * SSQ * DDM];
__device__ float g_V[BB * SSQ * DDM];
__device__ float g_C[BB * SSQ * DDM];

// ---------------------------------------------------------------------------
// SGEMM: C[M,N] = A[M,K] @ W[N,K]^T + bias[N]
// A row-major [M,K], W row-major [N,K] (torch Linear weight layout).
// Tile 128x128, k-step 16, 256 threads, 8x8 per-thread micro-tile.
// Requires M%128==0, N%128==0, K%16==0 (true here: 4096/1024/1024).
// ---------------------------------------------------------------------------
__global__ __launch_bounds__(256) void gemm_xwT(
    const float* __restrict__ A, const float* __restrict__ W,
    const float* __restrict__ bias, float* __restrict__ C,
    int M, int N, int K)
{
    __shared__ float As[16][128];   // transposed stage: As[k][m]
    __shared__ float Ws[16][128];   // transposed stage: Ws[k][n]

    const int tid = threadIdx.x;
    const int tx  = tid & 15;       // 0..15 -> column group
    const int ty  = tid >> 4;       // 0..15 -> row group
    const int m0  = blockIdx.y * 128;
    const int n0  = blockIdx.x * 128;

    float acc[8][8];
    #pragma unroll
    for (int i = 0; i < 8; i++)
        #pragma unroll
        for (int j = 0; j < 8; j++)
            acc[i][j] = 0.0f;

    for (int k0 = 0; k0 < K; k0 += 16) {
        // Stage A and W tiles (128 rows x 16 k) transposed into smem.
        #pragma unroll
        for (int it = 0; it < 2; it++) {
            int idx = tid + it * 256;        // 0..511
            int r   = idx >> 2;              // 0..127
            int c   = (idx & 3) * 4;         // 0,4,8,12
            float4 va = *(const float4*)(A + (size_t)(m0 + r) * K + k0 + c);
            As[c + 0][r] = va.x; As[c + 1][r] = va.y;
            As[c + 2][r] = va.z; As[c + 3][r] = va.w;
            float4 vw = *(const float4*)(W + (size_t)(n0 + r) * K + k0 + c);
            Ws[c + 0][r] = vw.x; Ws[c + 1][r] = vw.y;
            Ws[c + 2][r] = vw.z; Ws[c + 3][r] = vw.w;
        }
        __syncthreads();

        #pragma unroll
        for (int kk = 0; kk < 16; kk++) {
            float4 a0 = *(const float4*)&As[kk][ty * 4];
            float4 a1 = *(const float4*)&As[kk][64 + ty * 4];
            float4 b0 = *(const float4*)&Ws[kk][tx * 4];
            float4 b1 = *(const float4*)&Ws[kk][64 + tx * 4];
            float av[8] = {a0.x, a0.y, a0.z, a0.w, a1.x, a1.y, a1.z, a1.w};
            float bv[8] = {b0.x, b0.y, b0.z, b0.w, b1.x, b1.y, b1.z, b1.w};
            #pragma unroll
            for (int i = 0; i < 8; i++)
                #pragma unroll
                for (int j = 0; j < 8; j++)
                    acc[i][j] = fmaf(av[i], bv[j], acc[i][j]);
        }
        __syncthreads();
    }

    // Epilogue: add bias, store float4.
    #pragma unroll
    for (int i = 0; i < 8; i++) {
        int r = m0 + ((i < 4) ? (ty * 4 + i) : (64 + ty * 4 + (i - 4)));
        #pragma unroll
        for (int jh = 0; jh < 2; jh++) {
            int cb = n0 + jh * 64 + tx * 4;
            float4 v;
            v.x = acc[i][jh * 4 + 0] + bias[cb + 0];
            v.y = acc[i][jh * 4 + 1] + bias[cb + 1];
            v.z = acc[i][jh * 4 + 2] + bias[cb + 2];
            v.w = acc[i][jh * 4 + 3] + bias[cb + 3];
            *(float4*)(C + (size_t)r * N + cb) = v;
        }
    }
}

// ---------------------------------------------------------------------------
// Flash attention (fp32, online softmax).
// Q/K/V layout: [B, S, D] with head h occupying columns [h*64, h*64+64).
// Block: 256 threads handle a 64-query tile for one (b,h).
// Bq=64, Bk=64, dk=64. racing_bias cancels in softmax -> skipped.
// ---------------------------------------------------------------------------
__global__ __launch_bounds__(256) void flash64(
    const float* __restrict__ Q, const float* __restrict__ K,
    const float* __restrict__ V, float* __restrict__ O)
{
    extern __shared__ float sm[];
    float* Qst = sm;                 // [64][68]: Qst[d][r]   (d-major)
    float* Kst = sm + 64 * 68;       // [64][68]: Kst[d][c]   (d-major)
    float* Vs  = sm + 2 * 64 * 68;   // [64][68]: Vs[k][c]    (natural)
    float* Pst = sm + 3 * 64 * 68;   // [64][68]: Pst[k][r]   (transposed P)

    const int tid = threadIdx.x;
    const int tx  = tid & 15;
    const int ty  = tid >> 4;
    const int b   = blockIdx.y / HH;
    const int h   = blockIdx.y % HH;
    const int q0  = blockIdx.x * 64;

    const float* Qbase = Q + ((size_t)(b * SSQ + q0)) * DDM + h * DKK;
    const float* Kbase = K + ((size_t)b * SSQ) * DDM + h * DKK;
    const float* Vbase = V + ((size_t)b * SSQ) * DDM + h * DKK;

    // Load Q tile (64x64) transposed: Qst[d][r].
    #pragma unroll
    for (int it = 0; it < 4; it++) {
        int idx = tid + it * 256;      // 0..1023 float4 slots
        int r   = idx >> 4;            // 0..63
        int c   = (idx & 15) * 4;      // 0..60
        float4 v = *(const float4*)(Qbase + (size_t)r * DDM + c);
        Qst[(c + 0) * 68 + r] = v.x; Qst[(c + 1) * 68 + r] = v.y;
        Qst[(c + 2) * 68 + r] = v.z; Qst[(c + 3) * 68 + r] = v.w;
    }

    float m_[4], l_[4], o_[4][4];
    #pragma unroll
    for (int i = 0; i < 4; i++) {
        m_[i] = -1e30f; l_[i] = 0.0f;
        #pragma unroll
        for (int j = 0; j < 4; j++) o_[i][j] = 0.0f;
    }

    for (int kt = 0; kt < SSQ; kt += 64) {
        __syncthreads();   // previous PV done before K/V/P overwrite
        // Load K transposed + V natural.
        #pragma unroll
        for (int it = 0; it < 4; it++) {
            int idx = tid + it * 256;
            int r   = idx >> 4;
            int c   = (idx & 15) * 4;
            float4 kv = *(const float4*)(Kbase + (size_t)(kt + r) * DDM + c);
            Kst[(c + 0) * 68 + r] = kv.x; Kst[(c + 1) * 68 + r] = kv.y;
            Kst[(c + 2) * 68 + r] = kv.z; Kst[(c + 3) * 68 + r] = kv.w;
            float4 vv = *(const float4*)(Vbase + (size_t)(kt + r) * DDM + c);
            *(float4*)&Vs[r * 68 + c] = vv;
        }
        __syncthreads();

        // Scores: s[i][j] = sum_d Q[r][d]*K[c][d]
        float s[4][4];
        #pragma unroll
        for (int i = 0; i < 4; i++)
            #pragma unroll
            for (int j = 0; j < 4; j++) s[i][j] = 0.0f;

        #pragma unroll 8
        for (int d = 0; d < 64; d++) {
            float4 qa = *(const float4*)&Qst[d * 68 + ty * 4];
            float4 kb = *(const float4*)&Kst[d * 68 + tx * 4];
            float qv[4] = {qa.x, qa.y, qa.z, qa.w};
            float kv[4] = {kb.x, kb.y, kb.z, kb.w};
            #pragma unroll
            for (int i = 0; i < 4; i++)
                #pragma unroll
                for (int j = 0; j < 4; j++)
                    s[i][j] = fmaf(qv[i], kv[j], s[i][j]);
        }

        // Online softmax per row (rows shared across the 16-thread tx group).
        #pragma unroll
        for (int i = 0; i < 4; i++) {
            float mx = -1e30f;
            #pragma unroll
            for (int j = 0; j < 4; j++) {
                s[i][j] *= 0.125f;          // 1/sqrt(64)
                mx = fmaxf(mx, s[i][j]);
            }
            #pragma unroll
            for (int off = 8; off >= 1; off >>= 1)
                mx = fmaxf(mx, __shfl_xor_sync(0xffffffffu, mx, off, 16));
            float newm = fmaxf(m_[i], mx);
            float corr = __expf(m_[i] - newm);
            float rsum = 0.0f;
            #pragma unroll
            for (int j = 0; j < 4; j++) {
                s[i][j] = __expf(s[i][j] - newm);
                rsum += s[i][j];
            }
            #pragma unroll
            for (int off = 8; off >= 1; off >>= 1)
                rsum += __shfl_xor_sync(0xffffffffu, rsum, off, 16);
            l_[i] = l_[i] * corr + rsum;
            m_[i] = newm;
            #pragma unroll
            for (int j = 0; j < 4; j++) o_[i][j] *= corr;
            // stage P transposed: Pst[k][r]
            #pragma unroll
            for (int j = 0; j < 4; j++)
                Pst[(tx * 4 + j) * 68 + (ty * 4 + i)] = s[i][j];
        }
        __syncthreads();

        // PV: o[r][c] += sum_k P[r][k] * V[k][c]
        #pragma unroll 8
        for (int k = 0; k < 64; k++) {
            float4 pa = *(const float4*)&Pst[k * 68 + ty * 4];
            float4 vb = *(const float4*)&Vs[k * 68 + tx * 4];
            float pv[4] = {pa.x, pa.y, pa.z, pa.w};
            float vv[4] = {vb.x, vb.y, vb.z, vb.w};
            #pragma unroll
            for (int i = 0; i < 4; i++)
                #pragma unroll
                for (int j = 0; j < 4; j++)
                    o_[i][j] = fmaf(pv[i], vv[j], o_[i][j]);
        }
    }

    // Epilogue: normalize and store to ctx [B,S,D].
    float* Obase = O + ((size_t)(b * SSQ + q0)) * DDM + h * DKK;
    #pragma unroll
    for (int i = 0; i < 4; i++) {
        float inv_l = 1.0f / l_[i];
        float4 v;
        v.x = o_[i][0] * inv_l; v.y = o_[i][1] * inv_l;
        v.z = o_[i][2] * inv_l; v.w = o_[i][3] * inv_l;
        *(float4*)(Obase + (size_t)(ty * 4 + i) * DDM + tx * 4) = v;
    }
}

// ---------------------------------------------------------------------------
extern "C" void kernel_launch(void* const* d_in, const int* in_sizes, int n_in,
                              void* d_out, int out_size)
{
    (void)in_sizes; (void)n_in; (void)out_size;
    const float* query = (const float*)d_in[0];
    const float* key_  = (const float*)d_in[1];
    const float* value = (const float*)d_in[2];
    const float* wq = (const float*)d_in[3];
    const float* bq = (const float*)d_in[4];
    const float* wk = (const float*)d_in[5];
    const float* bk = (const float*)d_in[6];
    const float* wv = (const float*)d_in[7];
    const float* bv = (const float*)d_in[8];
    const float* wo = (const float*)d_in[9];
    const float* bo = (const float*)d_in[10];
    // d_in[11] = racing_bias: constant over softmax axis -> cancels exactly.
    float* out = (float*)d_out;

    float *Qp, *Kp, *Vp, *Cp;
    cudaGetSymbolAddress((void**)&Qp, g_Q);
    cudaGetSymbolAddress((void**)&Kp, g_K);
    cudaGetSymbolAddress((void**)&Vp, g_V);
    cudaGetSymbolAddress((void**)&Cp, g_C);

    const int M = BB * SSQ;     // 4096
    const int N = DDM;          // 1024
    const int Kdim = DDM;       // 1024
    dim3 gGrid(N / 128, M / 128);   // (8, 32)
    dim3 gBlk(256);

    // Projections
    gemm_xwT<<<gGrid, gBlk>>>(query, wq, bq, Qp, M, N, Kdim);
    gemm_xwT<<<gGrid, gBlk>>>(key_,  wk, bk, Kp, M, N, Kdim);
    gemm_xwT<<<gGrid, gBlk>>>(value, wv, bv, Vp, M, N, Kdim);

    // Flash attention
    const int smemBytes = 4 * 64 * 68 * sizeof(float);   // 69632
    cudaFuncSetAttribute(flash64, cudaFuncAttributeMaxDynamicSharedMemorySize,
                         smemBytes);
    dim3 fGrid(SSQ / 64, BB * HH);   // (32, 32)
    flash64<<<fGrid, gBlk, smemBytes>>>(Qp, Kp, Vp, Cp);

    // Output projection
    gemm_xwT<<<gGrid, gBlk>>>(Cp, wo, bo, out, M, N, Kdim);
}

// round 3
// speedup vs baseline: 1.4178x; 1.4178x over previous
#include <cuda_runtime.h>
#include <cstdint>

// Problem constants
#define BB   2
#define SSQ  2048
#define DDM  1024
#define HH   16
#define DKK  64

// Scratch: intermediates live in __device__ globals (no allocation allowed).
__device__ float g_Q[BB * SSQ * DDM];
__device__ float g_K[BB * SSQ * DDM];
__device__ float g_V[BB * SSQ * DDM];
__device__ float g_C[BB * SSQ * DDM];

// ---------------------------------------------------------------------------
// tf32 helpers
// ---------------------------------------------------------------------------
__device__ __forceinline__ uint32_t f2tf32(float x) {
    uint32_t r;
    asm("cvt.rna.tf32.f32 %0, %1;" : "=r"(r) : "f"(x));
    return r;
}

__device__ __forceinline__ void mma_tf32(float d[4], const uint32_t a[4],
                                         const uint32_t b[2]) {
    asm volatile(
        "mma.sync.aligned.m16n8k8.row.col.f32.tf32.tf32.f32 "
        "{%0,%1,%2,%3}, {%4,%5,%6,%7}, {%8,%9}, {%0,%1,%2,%3};"
        : "+f"(d[0]), "+f"(d[1]), "+f"(d[2]), "+f"(d[3])
        : "r"(a[0]), "r"(a[1]), "r"(a[2]), "r"(a[3]), "r"(b[0]), "r"(b[1]));
}

// ---------------------------------------------------------------------------
// tf32 tensor-core GEMM core: C[M,N] = A[M,K] @ W[N,K]^T + bias[N]
// Block tile 128x128, k-chunk 32, 256 threads (8 warps, 2m x 4n),
// warp tile 64x32, mma m16n8k8. Requires M%128==0, N%128==0, K%32==0.
// ---------------------------------------------------------------------------
__device__ __forceinline__ void gemm_tf32_core(
    const float* __restrict__ A, const float* __restrict__ W,
    const float* __restrict__ bias, float* __restrict__ C,
    int M, int N, int K)
{
    __shared__ uint32_t As[128][36];   // [m][k] + pad
    __shared__ uint32_t Ws[128][36];   // [n][k] + pad

    const int tid  = threadIdx.x;
    const int warp = tid >> 5;
    const int lane = tid & 31;
    const int wm   = warp >> 2;      // 0..1
    const int wn   = warp & 3;       // 0..3
    const int gid  = lane >> 2;      // groupID 0..7
    const int tig  = lane & 3;       // thread-in-group 0..3
    const int m0   = blockIdx.y * 128;
    const int n0   = blockIdx.x * 128;

    float acc[4][4][4];
    #pragma unroll
    for (int mt = 0; mt < 4; mt++)
        #pragma unroll
        for (int nt = 0; nt < 4; nt++)
            #pragma unroll
            for (int i = 0; i < 4; i++)
                acc[mt][nt][i] = 0.0f;

    for (int k0 = 0; k0 < K; k0 += 32) {
        // Stage 128x32 tiles of A and W (converted to tf32).
        #pragma unroll
        for (int it = 0; it < 4; it++) {
            int slot = tid + it * 256;       // 0..1023
            int r    = slot >> 3;            // 0..127
            int c4   = (slot & 7) * 4;       // 0..28
            float4 va = *(const float4*)(A + (size_t)(m0 + r) * K + k0 + c4);
            uint4 ta = { f2tf32(va.x), f2tf32(va.y), f2tf32(va.z), f2tf32(va.w) };
            *(uint4*)&As[r][c4] = ta;
            float4 vw = *(const float4*)(W + (size_t)(n0 + r) * K + k0 + c4);
            uint4 tw = { f2tf32(vw.x), f2tf32(vw.y), f2tf32(vw.z), f2tf32(vw.w) };
            *(uint4*)&Ws[r][c4] = tw;
        }
        __syncthreads();

        #pragma unroll
        for (int kk = 0; kk < 32; kk += 8) {
            uint32_t a[4][4], b[4][2];
            #pragma unroll
            for (int mt = 0; mt < 4; mt++) {
                int r = wm * 64 + mt * 16 + gid;
                a[mt][0] = As[r][kk + tig];
                a[mt][1] = As[r + 8][kk + tig];
                a[mt][2] = As[r][kk + tig + 4];
                a[mt][3] = As[r + 8][kk + tig + 4];
            }
            #pragma unroll
            for (int nt = 0; nt < 4; nt++) {
                int cn = wn * 32 + nt * 8 + gid;
                b[nt][0] = Ws[cn][kk + tig];
                b[nt][1] = Ws[cn][kk + tig + 4];
            }
            #pragma unroll
            for (int mt = 0; mt < 4; mt++)
                #pragma unroll
                for (int nt = 0; nt < 4; nt++)
                    mma_tf32(acc[mt][nt], a[mt], b[nt]);
        }
        __syncthreads();
    }

    // Epilogue: add bias, store float2 pairs.
    #pragma unroll
    for (int mt = 0; mt < 4; mt++) {
        int r0 = m0 + wm * 64 + mt * 16 + gid;
        #pragma unroll
        for (int nt = 0; nt < 4; nt++) {
            int c = n0 + wn * 32 + nt * 8 + tig * 2;
            float bx = bias[c], by = bias[c + 1];
            float2 v0 = { acc[mt][nt][0] + bx, acc[mt][nt][1] + by };
            float2 v1 = { acc[mt][nt][2] + bx, acc[mt][nt][3] + by };
            *(float2*)(C + (size_t)r0 * N + c) = v0;
            *(float2*)(C + (size_t)(r0 + 8) * N + c) = v1;
        }
    }
}

// Fused Q/K/V projections: blockIdx.z selects which projection.
__global__ __launch_bounds__(256, 2) void gemm_qkv(
    const float* __restrict__ xq, const float* __restrict__ xk,
    const float* __restrict__ xv,
    const float* __restrict__ wq, const float* __restrict__ wk,
    const float* __restrict__ wv,
    const float* __restrict__ bq, const float* __restrict__ bk,
    const float* __restrict__ bv,
    float* __restrict__ Q, float* __restrict__ K, float* __restrict__ V,
    int M, int N, int Kd)
{
    const float *A, *W, *bias;
    float* C;
    if (blockIdx.z == 0)      { A = xq; W = wq; bias = bq; C = Q; }
    else if (blockIdx.z == 1) { A = xk; W = wk; bias = bk; C = K; }
    else                      { A = xv; W = wv; bias = bv; C = V; }
    gemm_tf32_core(A, W, bias, C, M, N, Kd);
}

__global__ __launch_bounds__(256, 2) void gemm_single(
    const float* __restrict__ A, const float* __restrict__ W,
    const float* __restrict__ bias, float* __restrict__ C,
    int M, int N, int Kd)
{
    gemm_tf32_core(A, W, bias, C, M, N, Kd);
}

// ---------------------------------------------------------------------------
// Flash attention (fp32, online softmax) — unchanged from R1.
// ---------------------------------------------------------------------------
__global__ __launch_bounds__(256) void flash64(
    const float* __restrict__ Q, const float* __restrict__ K,
    const float* __restrict__ V, float* __restrict__ O)
{
    extern __shared__ float sm[];
    float* Qst = sm;                 // [64][68]: Qst[d][r]
    float* Kst = sm + 64 * 68;       // [64][68]: Kst[d][c]
    float* Vs  = sm + 2 * 64 * 68;   // [64][68]: Vs[k][c]
    float* Pst = sm + 3 * 64 * 68;   // [64][68]: Pst[k][r]

    const int tid = threadIdx.x;
    const int tx  = tid & 15;
    const int ty  = tid >> 4;
    const int b   = blockIdx.y / HH;
    const int h   = blockIdx.y % HH;
    const int q0  = blockIdx.x * 64;

    const float* Qbase = Q + ((size_t)(b * SSQ + q0)) * DDM + h * DKK;
    const float* Kbase = K + ((size_t)b * SSQ) * DDM + h * DKK;
    const float* Vbase = V + ((size_t)b * SSQ) * DDM + h * DKK;

    #pragma unroll
    for (int it = 0; it < 4; it++) {
        int idx = tid + it * 256;
        int r   = idx >> 4;
        int c   = (idx & 15) * 4;
        float4 v = *(const float4*)(Qbase + (size_t)r * DDM + c);
        Qst[(c + 0) * 68 + r] = v.x; Qst[(c + 1) * 68 + r] = v.y;
        Qst[(c + 2) * 68 + r] = v.z; Qst[(c + 3) * 68 + r] = v.w;
    }

    float m_[4], l_[4], o_[4][4];
    #pragma unroll
    for (int i = 0; i < 4; i++) {
        m_[i] = -1e30f; l_[i] = 0.0f;
        #pragma unroll
        for (int j = 0; j < 4; j++) o_[i][j] = 0.0f;
    }

    for (int kt = 0; kt < SSQ; kt += 64) {
        __syncthreads();
        #pragma unroll
        for (int it = 0; it < 4; it++) {
            int idx = tid + it * 256;
            int r   = idx >> 4;
            int c   = (idx & 15) * 4;
            float4 kv = *(const float4*)(Kbase + (size_t)(kt + r) * DDM + c);
            Kst[(c + 0) * 68 + r] = kv.x; Kst[(c + 1) * 68 + r] = kv.y;
            Kst[(c + 2) * 68 + r] = kv.z; Kst[(c + 3) * 68 + r] = kv.w;
            float4 vv = *(const float4*)(Vbase + (size_t)(kt + r) * DDM + c);
            *(float4*)&Vs[r * 68 + c] = vv;
        }
        __syncthreads();

        float s[4][4];
        #pragma unroll
        for (int i = 0; i < 4; i++)
            #pragma unroll
            for (int j = 0; j < 4; j++) s[i][j] = 0.0f;

        #pragma unroll 8
        for (int d = 0; d < 64; d++) {
            float4 qa = *(const float4*)&Qst[d * 68 + ty * 4];
            float4 kb = *(const float4*)&Kst[d * 68 + tx * 4];
            float qv[4] = {qa.x, qa.y, qa.z, qa.w};
            float kv[4] = {kb.x, kb.y, kb.z, kb.w};
            #pragma unroll
            for (int i = 0; i < 4; i++)
                #pragma unroll
                for (int j = 0; j < 4; j++)
                    s[i][j] = fmaf(qv[i], kv[j], s[i][j]);
        }

        #pragma unroll
        for (int i = 0; i < 4; i++) {
            float mx = -1e30f;
            #pragma unroll
            for (int j = 0; j < 4; j++) {
                s[i][j] *= 0.125f;
                mx = fmaxf(mx, s[i][j]);
            }
            #pragma unroll
            for (int off = 8; off >= 1; off >>= 1)
                mx = fmaxf(mx, __shfl_xor_sync(0xffffffffu, mx, off, 16));
            float newm = fmaxf(m_[i], mx);
            float corr = __expf(m_[i] - newm);
            float rsum = 0.0f;
            #pragma unroll
            for (int j = 0; j < 4; j++) {
                s[i][j] = __expf(s[i][j] - newm);
                rsum += s[i][j];
            }
            #pragma unroll
            for (int off = 8; off >= 1; off >>= 1)
                rsum += __shfl_xor_sync(0xffffffffu, rsum, off, 16);
            l_[i] = l_[i] * corr + rsum;
            m_[i] = newm;
            #pragma unroll
            for (int j = 0; j < 4; j++) o_[i][j] *= corr;
            #pragma unroll
            for (int j = 0; j < 4; j++)
                Pst[(tx * 4 + j) * 68 + (ty * 4 + i)] = s[i][j];
        }
        __syncthreads();

        #pragma unroll 8
        for (int k = 0; k < 64; k++) {
            float4 pa = *(const float4*)&Pst[k * 68 + ty * 4];
            float4 vb = *(const float4*)&Vs[k * 68 + tx * 4];
            float pv[4] = {pa.x, pa.y, pa.z, pa.w};
            float vv[4] = {vb.x, vb.y, vb.z, vb.w};
            #pragma unroll
            for (int i = 0; i < 4; i++)
                #pragma unroll
                for (int j = 0; j < 4; j++)
                    o_[i][j] = fmaf(pv[i], vv[j], o_[i][j]);
        }
    }

    float* Obase = O + ((size_t)(b * SSQ + q0)) * DDM + h * DKK;
    #pragma unroll
    for (int i = 0; i < 4; i++) {
        float inv_l = 1.0f / l_[i];
        float4 v;
        v.x = o_[i][0] * inv_l; v.y = o_[i][1] * inv_l;
        v.z = o_[i][2] * inv_l; v.w = o_[i][3] * inv_l;
        *(float4*)(Obase + (size_t)(ty * 4 + i) * DDM + tx * 4) = v;
    }
}

// ---------------------------------------------------------------------------
extern "C" void kernel_launch(void* const* d_in, const int* in_sizes, int n_in,
                              void* d_out, int out_size)
{
    (void)in_sizes; (void)n_in; (void)out_size;
    const float* query = (const float*)d_in[0];
    const float* key_  = (const float*)d_in[1];
    const float* value = (const float*)d_in[2];
    const float* wq = (const float*)d_in[3];
    const float* bq = (const float*)d_in[4];
    const float* wk = (const float*)d_in[5];
    const float* bk = (const float*)d_in[6];
    const float* wv = (const float*)d_in[7];
    const float* bv = (const float*)d_in[8];
    const float* wo = (const float*)d_in[9];
    const float* bo = (const float*)d_in[10];
    // d_in[11] = racing_bias: constant over softmax axis -> cancels exactly.
    float* out = (float*)d_out;

    float *Qp, *Kp, *Vp, *Cp;
    cudaGetSymbolAddress((void**)&Qp, g_Q);
    cudaGetSymbolAddress((void**)&Kp, g_K);
    cudaGetSymbolAddress((void**)&Vp, g_V);
    cudaGetSymbolAddress((void**)&Cp, g_C);

    const int M = BB * SSQ;     // 4096
    const int N = DDM;          // 1024
    const int Kdim = DDM;       // 1024

    // Fused Q/K/V projections on tensor cores (tf32).
    dim3 qkvGrid(N / 128, M / 128, 3);   // (8, 32, 3) = 768 blocks
    gemm_qkv<<<qkvGrid, 256>>>(query, key_, value, wq, wk, wv, bq, bk, bv,
                               Qp, Kp, Vp, M, N, Kdim);

    // Flash attention (fp32)
    const int smemBytes = 4 * 64 * 68 * sizeof(float);
    cudaFuncSetAttribute(flash64, cudaFuncAttributeMaxDynamicSharedMemorySize,
                         smemBytes);
    dim3 fGrid(SSQ / 64, BB * HH);
    flash64<<<fGrid, 256, smemBytes>>>(Qp, Kp, Vp, Cp);

    // Output projection (tf32 tensor cores).
    dim3 oGrid(N / 128, M / 128, 1);
    gemm_single<<<oGrid, 256>>>(Cp, wo, bo, out, M, N, Kdim);
}

// round 4
// speedup vs baseline: 2.7197x; 1.9183x over previous
#include <cuda_runtime.h>
#include <cstdint>

// Problem constants
#define BB   2
#define SSQ  2048
#define DDM  1024
#define HH   16
#define DKK  64

// Scratch: intermediates live in __device__ globals (no allocation allowed).
__device__ float g_Q[BB * SSQ * DDM];
__device__ float g_K[BB * SSQ * DDM];
__device__ float g_V[BB * SSQ * DDM];
__device__ float g_C[BB * SSQ * DDM];

// ---------------------------------------------------------------------------
// tf32 helpers
// ---------------------------------------------------------------------------
__device__ __forceinline__ uint32_t f2tf32(float x) {
    uint32_t r;
    asm("cvt.rna.tf32.f32 %0, %1;" : "=r"(r) : "f"(x));
    return r;
}

__device__ __forceinline__ void mma_tf32(float d[4], const uint32_t a[4],
                                         const uint32_t b[2]) {
    asm volatile(
        "mma.sync.aligned.m16n8k8.row.col.f32.tf32.tf32.f32 "
        "{%0,%1,%2,%3}, {%4,%5,%6,%7}, {%8,%9}, {%0,%1,%2,%3};"
        : "+f"(d[0]), "+f"(d[1]), "+f"(d[2]), "+f"(d[3])
        : "r"(a[0]), "r"(a[1]), "r"(a[2]), "r"(a[3]), "r"(b[0]), "r"(b[1]));
}

// ---------------------------------------------------------------------------
// tf32 tensor-core GEMM core: C[M,N] = A[M,K] @ W[N,K]^T + bias[N]
// Block tile 128x128, k-chunk 32, 256 threads (8 warps, 2m x 4n),
// warp tile 64x32, mma m16n8k8.
// ---------------------------------------------------------------------------
__device__ __forceinline__ void gemm_tf32_core(
    const float* __restrict__ A, const float* __restrict__ W,
    const float* __restrict__ bias, float* __restrict__ C,
    int M, int N, int K)
{
    __shared__ uint32_t As[128][36];   // [m][k] + pad
    __shared__ uint32_t Ws[128][36];   // [n][k] + pad

    const int tid  = threadIdx.x;
    const int warp = tid >> 5;
    const int lane = tid & 31;
    const int wm   = warp >> 2;
    const int wn   = warp & 3;
    const int gid  = lane >> 2;
    const int tig  = lane & 3;
    const int m0   = blockIdx.y * 128;
    const int n0   = blockIdx.x * 128;

    float acc[4][4][4];
    #pragma unroll
    for (int mt = 0; mt < 4; mt++)
        #pragma unroll
        for (int nt = 0; nt < 4; nt++)
            #pragma unroll
            for (int i = 0; i < 4; i++)
                acc[mt][nt][i] = 0.0f;

    for (int k0 = 0; k0 < K; k0 += 32) {
        #pragma unroll
        for (int it = 0; it < 4; it++) {
            int slot = tid + it * 256;
            int r    = slot >> 3;
            int c4   = (slot & 7) * 4;
            float4 va = *(const float4*)(A + (size_t)(m0 + r) * K + k0 + c4);
            uint4 ta = { f2tf32(va.x), f2tf32(va.y), f2tf32(va.z), f2tf32(va.w) };
            *(uint4*)&As[r][c4] = ta;
            float4 vw = *(const float4*)(W + (size_t)(n0 + r) * K + k0 + c4);
            uint4 tw = { f2tf32(vw.x), f2tf32(vw.y), f2tf32(vw.z), f2tf32(vw.w) };
            *(uint4*)&Ws[r][c4] = tw;
        }
        __syncthreads();

        #pragma unroll
        for (int kk = 0; kk < 32; kk += 8) {
            uint32_t a[4][4], b[4][2];
            #pragma unroll
            for (int mt = 0; mt < 4; mt++) {
                int r = wm * 64 + mt * 16 + gid;
                a[mt][0] = As[r][kk + tig];
                a[mt][1] = As[r + 8][kk + tig];
                a[mt][2] = As[r][kk + tig + 4];
                a[mt][3] = As[r + 8][kk + tig + 4];
            }
            #pragma unroll
            for (int nt = 0; nt < 4; nt++) {
                int cn = wn * 32 + nt * 8 + gid;
                b[nt][0] = Ws[cn][kk + tig];
                b[nt][1] = Ws[cn][kk + tig + 4];
            }
            #pragma unroll
            for (int mt = 0; mt < 4; mt++)
                #pragma unroll
                for (int nt = 0; nt < 4; nt++)
                    mma_tf32(acc[mt][nt], a[mt], b[nt]);
        }
        __syncthreads();
    }

    #pragma unroll
    for (int mt = 0; mt < 4; mt++) {
        int r0 = m0 + wm * 64 + mt * 16 + gid;
        #pragma unroll
        for (int nt = 0; nt < 4; nt++) {
            int c = n0 + wn * 32 + nt * 8 + tig * 2;
            float bx = bias[c], by = bias[c + 1];
            float2 v0 = { acc[mt][nt][0] + bx, acc[mt][nt][1] + by };
            float2 v1 = { acc[mt][nt][2] + bx, acc[mt][nt][3] + by };
            *(float2*)(C + (size_t)r0 * N + c) = v0;
            *(float2*)(C + (size_t)(r0 + 8) * N + c) = v1;
        }
    }
}

__global__ __launch_bounds__(256, 2) void gemm_qkv(
    const float* __restrict__ xq, const float* __restrict__ xk,
    const float* __restrict__ xv,
    const float* __restrict__ wq, const float* __restrict__ wk,
    const float* __restrict__ wv,
    const float* __restrict__ bq, const float* __restrict__ bk,
    const float* __restrict__ bv,
    float* __restrict__ Q, float* __restrict__ K, float* __restrict__ V,
    int M, int N, int Kd)
{
    const float *A, *W, *bias;
    float* C;
    if (blockIdx.z == 0)      { A = xq; W = wq; bias = bq; C = Q; }
    else if (blockIdx.z == 1) { A = xk; W = wk; bias = bk; C = K; }
    else                      { A = xv; W = wv; bias = bv; C = V; }
    gemm_tf32_core(A, W, bias, C, M, N, Kd);
}

__global__ __launch_bounds__(256, 2) void gemm_single(
    const float* __restrict__ A, const float* __restrict__ W,
    const float* __restrict__ bias, float* __restrict__ C,
    int M, int N, int Kd)
{
    gemm_tf32_core(A, W, bias, C, M, N, Kd);
}

// ---------------------------------------------------------------------------
// Flash attention on tf32 tensor cores.
// CTA = 128 query rows, 8 warps (16 rows each). Bk = 64, dk = 64.
// K staged natural [key][d] (B-operand layout for QK), V staged transposed
// [d][key] (B-operand layout for PV). P round-trips through smem as tf32.
// racing_bias cancels in softmax -> skipped.
// ---------------------------------------------------------------------------
#define FB_PAD 68

__global__ __launch_bounds__(256) void flash_mma(
    const float* __restrict__ Q, const float* __restrict__ K,
    const float* __restrict__ V, float* __restrict__ O)
{
    extern __shared__ uint32_t smu[];
    uint32_t* Ksm = smu;                 // [64][FB_PAD]   K[key][d]
    uint32_t* Vt  = smu + 64 * FB_PAD;   // [64][FB_PAD]   V^T[d][key]
    uint32_t* Psm = smu + 128 * FB_PAD;  // [128][FB_PAD]  P[row][key]

    const int tid  = threadIdx.x;
    const int warp = tid >> 5;
    const int lane = tid & 31;
    const int gid  = lane >> 2;
    const int tig  = lane & 3;
    const int b    = blockIdx.y / HH;
    const int h    = blockIdx.y % HH;
    const int q0   = blockIdx.x * 128;

    const float* Qb = Q + ((size_t)(b * SSQ + q0 + warp * 16)) * DDM + h * DKK;
    const float* Kb = K + ((size_t)(b * SSQ)) * DDM + h * DKK;
    const float* Vb = V + ((size_t)(b * SSQ)) * DDM + h * DKK;

    // Q fragments in registers for the whole loop, pre-scaled by 1/sqrt(dk).
    uint32_t qf[8][4];
    #pragma unroll
    for (int kk = 0; kk < 8; kk++) {
        int c = kk * 8 + tig;
        qf[kk][0] = f2tf32(0.125f * Qb[(size_t)gid * DDM + c]);
        qf[kk][1] = f2tf32(0.125f * Qb[(size_t)(gid + 8) * DDM + c]);
        qf[kk][2] = f2tf32(0.125f * Qb[(size_t)gid * DDM + c + 4]);
        qf[kk][3] = f2tf32(0.125f * Qb[(size_t)(gid + 8) * DDM + c + 4]);
    }

    float m0 = -1e30f, m1 = -1e30f, l0 = 0.0f, l1 = 0.0f;
    float o[8][4];
    #pragma unroll
    for (int nt = 0; nt < 8; nt++)
        #pragma unroll
        for (int i = 0; i < 4; i++) o[nt][i] = 0.0f;

    const int prow = warp * 16 + gid;

    for (int kt = 0; kt < SSQ; kt += 64) {
        __syncthreads();   // previous PV done before K/Vt overwrite
        #pragma unroll
        for (int it = 0; it < 4; it++) {
            int idx = tid + it * 256;     // 0..1023 float4 slots
            int r   = idx >> 4;           // key 0..63
            int c   = (idx & 15) * 4;     // d 0..60
            float4 kv = *(const float4*)(Kb + (size_t)(kt + r) * DDM + c);
            Ksm[r * FB_PAD + c + 0] = f2tf32(kv.x);
            Ksm[r * FB_PAD + c + 1] = f2tf32(kv.y);
            Ksm[r * FB_PAD + c + 2] = f2tf32(kv.z);
            Ksm[r * FB_PAD + c + 3] = f2tf32(kv.w);
            float4 vv = *(const float4*)(Vb + (size_t)(kt + r) * DDM + c);
            Vt[(c + 0) * FB_PAD + r] = f2tf32(vv.x);
            Vt[(c + 1) * FB_PAD + r] = f2tf32(vv.y);
            Vt[(c + 2) * FB_PAD + r] = f2tf32(vv.z);
            Vt[(c + 3) * FB_PAD + r] = f2tf32(vv.w);
        }
        __syncthreads();

        // S = (Q/8) @ K^T  : 8 k-steps x 8 n-tiles of m16n8k8
        float s[8][4];
        #pragma unroll
        for (int nt = 0; nt < 8; nt++)
            #pragma unroll
            for (int i = 0; i < 4; i++) s[nt][i] = 0.0f;

        #pragma unroll
        for (int kk = 0; kk < 8; kk++) {
            #pragma unroll
            for (int nt = 0; nt < 8; nt++) {
                uint32_t bf[2];
                bf[0] = Ksm[(nt * 8 + gid) * FB_PAD + kk * 8 + tig];
                bf[1] = Ksm[(nt * 8 + gid) * FB_PAD + kk * 8 + tig + 4];
                mma_tf32(s[nt], qf[kk], bf);
            }
        }

        // Online softmax: rows gid (c0,c1) and gid+8 (c2,c3).
        float mx0 = -1e30f, mx1 = -1e30f;
        #pragma unroll
        for (int nt = 0; nt < 8; nt++) {
            mx0 = fmaxf(mx0, fmaxf(s[nt][0], s[nt][1]));
            mx1 = fmaxf(mx1, fmaxf(s[nt][2], s[nt][3]));
        }
        mx0 = fmaxf(mx0, __shfl_xor_sync(0xffffffffu, mx0, 1));
        mx0 = fmaxf(mx0, __shfl_xor_sync(0xffffffffu, mx0, 2));
        mx1 = fmaxf(mx1, __shfl_xor_sync(0xffffffffu, mx1, 1));
        mx1 = fmaxf(mx1, __shfl_xor_sync(0xffffffffu, mx1, 2));

        float nm0 = fmaxf(m0, mx0), nm1 = fmaxf(m1, mx1);
        float cr0 = __expf(m0 - nm0), cr1 = __expf(m1 - nm1);
        float rs0 = 0.0f, rs1 = 0.0f;

        #pragma unroll
        for (int nt = 0; nt < 8; nt++) {
            uint32_t t0 = f2tf32(__expf(s[nt][0] - nm0));
            uint32_t t1 = f2tf32(__expf(s[nt][1] - nm0));
            uint32_t t2 = f2tf32(__expf(s[nt][2] - nm1));
            uint32_t t3 = f2tf32(__expf(s[nt][3] - nm1));
            // accumulate the exact tf32-rounded values used by the PV mma
            rs0 += __uint_as_float(t0) + __uint_as_float(t1);
            rs1 += __uint_as_float(t2) + __uint_as_float(t3);
            int cb = nt * 8 + tig * 2;
            Psm[prow * FB_PAD + cb]           = t0;
            Psm[prow * FB_PAD + cb + 1]       = t1;
            Psm[(prow + 8) * FB_PAD + cb]     = t2;
            Psm[(prow + 8) * FB_PAD + cb + 1] = t3;
        }
        rs0 += __shfl_xor_sync(0xffffffffu, rs0, 1);
        rs0 += __shfl_xor_sync(0xffffffffu, rs0, 2);
        rs1 += __shfl_xor_sync(0xffffffffu, rs1, 1);
        rs1 += __shfl_xor_sync(0xffffffffu, rs1, 2);

        l0 = l0 * cr0 + rs0;  m0 = nm0;
        l1 = l1 * cr1 + rs1;  m1 = nm1;
        #pragma unroll
        for (int nt = 0; nt < 8; nt++) {
            o[nt][0] *= cr0; o[nt][1] *= cr0;
            o[nt][2] *= cr1; o[nt][3] *= cr1;
        }
        __syncwarp();   // P visible across lanes of this warp

        // O += P @ V : 8 k-steps (keys) x 8 n-tiles (dk)
        #pragma unroll
        for (int kk = 0; kk < 8; kk++) {
            uint32_t af[4];
            af[0] = Psm[prow * FB_PAD + kk * 8 + tig];
            af[1] = Psm[(prow + 8) * FB_PAD + kk * 8 + tig];
            af[2] = Psm[prow * FB_PAD + kk * 8 + tig + 4];
            af[3] = Psm[(prow + 8) * FB_PAD + kk * 8 + tig + 4];
            #pragma unroll
            for (int nt = 0; nt < 8; nt++) {
                uint32_t bf[2];
                bf[0] = Vt[(nt * 8 + gid) * FB_PAD + kk * 8 + tig];
                bf[1] = Vt[(nt * 8 + gid) * FB_PAD + kk * 8 + tig + 4];
                mma_tf32(o[nt], af, bf);
            }
        }
    }

    // Epilogue: normalize, store ctx.
    float il0 = 1.0f / l0, il1 = 1.0f / l1;
    float* Ob = O + ((size_t)(b * SSQ + q0 + warp * 16)) * DDM + h * DKK;
    #pragma unroll
    for (int nt = 0; nt < 8; nt++) {
        int c = nt * 8 + tig * 2;
        float2 v0 = { o[nt][0] * il0, o[nt][1] * il0 };
        float2 v1 = { o[nt][2] * il1, o[nt][3] * il1 };
        *(float2*)(Ob + (size_t)gid * DDM + c) = v0;
        *(float2*)(Ob + (size_t)(gid + 8) * DDM + c) = v1;
    }
}

// ---------------------------------------------------------------------------
extern "C" void kernel_launch(void* const* d_in, const int* in_sizes, int n_in,
                              void* d_out, int out_size)
{
    (void)in_sizes; (void)n_in; (void)out_size;
    const float* query = (const float*)d_in[0];
    const float* key_  = (const float*)d_in[1];
    const float* value = (const float*)d_in[2];
    const float* wq = (const float*)d_in[3];
    const float* bq = (const float*)d_in[4];
    const float* wk = (const float*)d_in[5];
    const float* bk = (const float*)d_in[6];
    const float* wv = (const float*)d_in[7];
    const float* bv = (const float*)d_in[8];
    const float* wo = (const float*)d_in[9];
    const float* bo = (const float*)d_in[10];
    // d_in[11] = racing_bias: constant over softmax axis -> cancels exactly.
    float* out = (float*)d_out;

    float *Qp, *Kp, *Vp, *Cp;
    cudaGetSymbolAddress((void**)&Qp, g_Q);
    cudaGetSymbolAddress((void**)&Kp, g_K);
    cudaGetSymbolAddress((void**)&Vp, g_V);
    cudaGetSymbolAddress((void**)&Cp, g_C);

    const int M = BB * SSQ;
    const int N = DDM;
    const int Kdim = DDM;

    // Fused Q/K/V projections (tf32 tensor cores).
    dim3 qkvGrid(N / 128, M / 128, 3);
    gemm_qkv<<<qkvGrid, 256>>>(query, key_, value, wq, wk, wv, bq, bk, bv,
                               Qp, Kp, Vp, M, N, Kdim);

    // Flash attention on tensor cores.
    const int smemBytes = (64 + 64 + 128) * FB_PAD * sizeof(uint32_t); // 69632
    cudaFuncSetAttribute(flash_mma, cudaFuncAttributeMaxDynamicSharedMemorySize,
                         smemBytes);
    dim3 fGrid(SSQ / 128, BB * HH);   // (16, 32) = 512 CTAs
    flash_mma<<<fGrid, 256, smemBytes>>>(Qp, Kp, Vp, Cp);

    // Output projection (tf32 tensor cores).
    dim3 oGrid(N / 128, M / 128, 1);
    gemm_single<<<oGrid, 256>>>(Cp, wo, bo, out, M, N, Kdim);
}

// round 5
// speedup vs baseline: 3.3115x; 1.2176x over previous
#include <cuda_runtime.h>
#include <cstdint>

// Problem constants
#define BB   2
#define SSQ  2048
#define DDM  1024
#define HH   16
#define DKK  64

// Scratch: intermediates live in __device__ globals (no allocation allowed).
__device__ float g_Q[BB * SSQ * DDM];
__device__ float g_K[BB * SSQ * DDM];
__device__ float g_V[BB * SSQ * DDM];
__device__ float g_C[BB * SSQ * DDM];

// ---------------------------------------------------------------------------
// helpers
// ---------------------------------------------------------------------------
__device__ __forceinline__ uint32_t f2tf32(float x) {
    uint32_t r;
    asm("cvt.rna.tf32.f32 %0, %1;" : "=r"(r) : "f"(x));
    return r;
}

__device__ __forceinline__ void mma_tf32(float d[4], const uint32_t a[4],
                                         const uint32_t b[2]) {
    asm volatile(
        "mma.sync.aligned.m16n8k8.row.col.f32.tf32.tf32.f32 "
        "{%0,%1,%2,%3}, {%4,%5,%6,%7}, {%8,%9}, {%0,%1,%2,%3};"
        : "+f"(d[0]), "+f"(d[1]), "+f"(d[2]), "+f"(d[3])
        : "r"(a[0]), "r"(a[1]), "r"(a[2]), "r"(a[3]), "r"(b[0]), "r"(b[1]));
}

__device__ __forceinline__ void cp16(void* smem_dst, const void* gsrc) {
    asm volatile("cp.async.ca.shared.global [%0], [%1], 16;"
                 :: "r"((uint32_t)__cvta_generic_to_shared(smem_dst)),
                    "l"(gsrc));
}
#define CP_COMMIT() asm volatile("cp.async.commit_group;")
#define CP_WAIT1()  asm volatile("cp.async.wait_group 1;")

// ---------------------------------------------------------------------------
// tf32 GEMM: C[M,N] = A[M,K] @ W[N,K]^T + bias[N]
// 2-stage cp.async pipeline, fp32 smem, cvt.rna at fragment consume.
// Block tile 128x128, k-chunk 32, 256 threads, warp tile 64x32.
// ---------------------------------------------------------------------------
#define GP 36
#define GA_STRIDE (128 * GP)          // one stage of one matrix

__device__ __forceinline__ void gemm_tf32_core(
    const float* __restrict__ A, const float* __restrict__ W,
    const float* __restrict__ bias, float* __restrict__ C,
    int M, int N, int K)
{
    extern __shared__ float gsm[];
    float* Aa = gsm;                       // [2][128][GP]
    float* Ww = gsm + 2 * GA_STRIDE;       // [2][128][GP]

    const int tid  = threadIdx.x;
    const int warp = tid >> 5;
    const int lane = tid & 31;
    const int wm   = warp >> 2;
    const int wn   = warp & 3;
    const int gid  = lane >> 2;
    const int tig  = lane & 3;
    const int m0   = blockIdx.y * 128;
    const int n0   = blockIdx.x * 128;

    float acc[4][4][4];
    #pragma unroll
    for (int mt = 0; mt < 4; mt++)
        #pragma unroll
        for (int nt = 0; nt < 4; nt++)
            #pragma unroll
            for (int i = 0; i < 4; i++)
                acc[mt][nt][i] = 0.0f;

    const int nchunk = K >> 5;

    // stage chunk `ck` into buffer `buf`
    auto stage = [&](int ck, int buf) {
        int k0 = ck * 32;
        #pragma unroll
        for (int it = 0; it < 4; it++) {
            int slot = tid + it * 256;       // 0..1023
            int r    = slot >> 3;            // 0..127
            int c4   = (slot & 7) * 4;       // 0..28
            cp16(&Aa[buf * GA_STRIDE + r * GP + c4],
                 A + (size_t)(m0 + r) * K + k0 + c4);
            cp16(&Ww[buf * GA_STRIDE + r * GP + c4],
                 W + (size_t)(n0 + r) * K + k0 + c4);
        }
    };

    stage(0, 0);
    CP_COMMIT();

    for (int ck = 0; ck < nchunk; ck++) {
        int cur = ck & 1;
        if (ck + 1 < nchunk) stage(ck + 1, cur ^ 1);
        CP_COMMIT();
        CP_WAIT1();
        __syncthreads();

        const float* Af = Aa + cur * GA_STRIDE;
        const float* Wf = Ww + cur * GA_STRIDE;
        #pragma unroll
        for (int kk = 0; kk < 32; kk += 8) {
            uint32_t a[4][4], b[4][2];
            #pragma unroll
            for (int mt = 0; mt < 4; mt++) {
                int r = wm * 64 + mt * 16 + gid;
                a[mt][0] = f2tf32(Af[r * GP + kk + tig]);
                a[mt][1] = f2tf32(Af[(r + 8) * GP + kk + tig]);
                a[mt][2] = f2tf32(Af[r * GP + kk + tig + 4]);
                a[mt][3] = f2tf32(Af[(r + 8) * GP + kk + tig + 4]);
            }
            #pragma unroll
            for (int nt = 0; nt < 4; nt++) {
                int cn = wn * 32 + nt * 8 + gid;
                b[nt][0] = f2tf32(Wf[cn * GP + kk + tig]);
                b[nt][1] = f2tf32(Wf[cn * GP + kk + tig + 4]);
            }
            #pragma unroll
            for (int mt = 0; mt < 4; mt++)
                #pragma unroll
                for (int nt = 0; nt < 4; nt++)
                    mma_tf32(acc[mt][nt], a[mt], b[nt]);
        }
        __syncthreads();
    }

    #pragma unroll
    for (int mt = 0; mt < 4; mt++) {
        int r0 = m0 + wm * 64 + mt * 16 + gid;
        #pragma unroll
        for (int nt = 0; nt < 4; nt++) {
            int c = n0 + wn * 32 + nt * 8 + tig * 2;
            float bx = bias[c], by = bias[c + 1];
            float2 v0 = { acc[mt][nt][0] + bx, acc[mt][nt][1] + by };
            float2 v1 = { acc[mt][nt][2] + bx, acc[mt][nt][3] + by };
            *(float2*)(C + (size_t)r0 * N + c) = v0;
            *(float2*)(C + (size_t)(r0 + 8) * N + c) = v1;
        }
    }
}

#define GEMM_SMEM (4 * GA_STRIDE * (int)sizeof(float))   // 73728 B

__global__ __launch_bounds__(256, 2) void gemm_qkv(
    const float* __restrict__ xq, const float* __restrict__ xk,
    const float* __restrict__ xv,
    const float* __restrict__ wq, const float* __restrict__ wk,
    const float* __restrict__ wv,
    const float* __restrict__ bq, const float* __restrict__ bk,
    const float* __restrict__ bv,
    float* __restrict__ Q, float* __restrict__ K, float* __restrict__ V,
    int M, int N, int Kd)
{
    const float *A, *W, *bias;
    float* C;
    if (blockIdx.z == 0)      { A = xq; W = wq; bias = bq; C = Q; }
    else if (blockIdx.z == 1) { A = xk; W = wk; bias = bk; C = K; }
    else                      { A = xv; W = wv; bias = bv; C = V; }
    gemm_tf32_core(A, W, bias, C, M, N, Kd);
}

__global__ __launch_bounds__(256, 2) void gemm_single(
    const float* __restrict__ A, const float* __restrict__ W,
    const float* __restrict__ bias, float* __restrict__ C,
    int M, int N, int Kd)
{
    gemm_tf32_core(A, W, bias, C, M, N, Kd);
}

// ---------------------------------------------------------------------------
// Flash attention on tf32 mma, 2-stage cp.async K/V pipeline.
// CTA = 256 query rows, 512 threads (16 warps x 16 rows). Bk = 64, dk = 64.
// K staged natural [key][d] pad 68 (QK B-operand, conflict-free rows);
// V staged natural [key][d] pad 72 (PV B-operand, conflict-free columns).
// P round-trips through smem as tf32. racing_bias cancels -> skipped.
// ---------------------------------------------------------------------------
#define KP 68
#define VP 72
#define KSTR (64 * KP)
#define VSTR (64 * VP)

__global__ __launch_bounds__(512, 1) void flash_mma(
    const float* __restrict__ Q, const float* __restrict__ K,
    const float* __restrict__ V, float* __restrict__ O)
{
    extern __shared__ float fsm[];
    float* Kf = fsm;                         // [2][64][KP]
    float* Vf = fsm + 2 * KSTR;              // [2][64][VP]
    uint32_t* Pu = (uint32_t*)(fsm + 2 * KSTR + 2 * VSTR);  // [256][KP]

    const int tid  = threadIdx.x;
    const int warp = tid >> 5;
    const int lane = tid & 31;
    const int gid  = lane >> 2;
    const int tig  = lane & 3;
    const int b    = blockIdx.y / HH;
    const int h    = blockIdx.y % HH;
    const int q0   = blockIdx.x * 256;

    const float* Qb = Q + ((size_t)(b * SSQ + q0 + warp * 16)) * DDM + h * DKK;
    const float* Kb = K + ((size_t)(b * SSQ)) * DDM + h * DKK;
    const float* Vb = V + ((size_t)(b * SSQ)) * DDM + h * DKK;

    // Q fragments in registers for the whole loop, pre-scaled by 1/sqrt(dk).
    uint32_t qf[8][4];
    #pragma unroll
    for (int kk = 0; kk < 8; kk++) {
        int c = kk * 8 + tig;
        qf[kk][0] = f2tf32(0.125f * Qb[(size_t)gid * DDM + c]);
        qf[kk][1] = f2tf32(0.125f * Qb[(size_t)(gid + 8) * DDM + c]);
        qf[kk][2] = f2tf32(0.125f * Qb[(size_t)gid * DDM + c + 4]);
        qf[kk][3] = f2tf32(0.125f * Qb[(size_t)(gid + 8) * DDM + c + 4]);
    }

    float m0 = -1e30f, m1 = -1e30f, l0 = 0.0f, l1 = 0.0f;
    float o[8][4];
    #pragma unroll
    for (int nt = 0; nt < 8; nt++)
        #pragma unroll
        for (int i = 0; i < 4; i++) o[nt][i] = 0.0f;

    const int prow = warp * 16 + gid;

    auto stage = [&](int ck, int buf) {
        const float* Kg = Kb + (size_t)(ck * 64) * DDM;
        const float* Vg = Vb + (size_t)(ck * 64) * DDM;
        #pragma unroll
        for (int it = 0; it < 2; it++) {
            int seg = tid + it * 512;       // 0..1023
            int r   = seg >> 4;             // key 0..63
            int c   = (seg & 15) * 4;       // d 0..60
            cp16(&Kf[buf * KSTR + r * KP + c], Kg + (size_t)r * DDM + c);
            cp16(&Vf[buf * VSTR + r * VP + c], Vg + (size_t)r * DDM + c);
        }
    };

    stage(0, 0);
    CP_COMMIT();

    const int niter = SSQ / 64;   // 32
    for (int ck = 0; ck < niter; ck++) {
        int cur = ck & 1;
        if (ck + 1 < niter) stage(ck + 1, cur ^ 1);
        CP_COMMIT();
        CP_WAIT1();
        __syncthreads();

        const float* Kc = Kf + cur * KSTR;
        const float* Vc = Vf + cur * VSTR;

        // S = (Q/8) @ K^T
        float s[8][4];
        #pragma unroll
        for (int nt = 0; nt < 8; nt++)
            #pragma unroll
            for (int i = 0; i < 4; i++) s[nt][i] = 0.0f;

        #pragma unroll
        for (int kk = 0; kk < 8; kk++) {
            #pragma unroll
            for (int nt = 0; nt < 8; nt++) {
                uint32_t bf[2];
                bf[0] = f2tf32(Kc[(nt * 8 + gid) * KP + kk * 8 + tig]);
                bf[1] = f2tf32(Kc[(nt * 8 + gid) * KP + kk * 8 + tig + 4]);
                mma_tf32(s[nt], qf[kk], bf);
            }
        }

        // Online softmax: rows gid (c0,c1) and gid+8 (c2,c3).
        float mx0 = -1e30f, mx1 = -1e30f;
        #pragma unroll
        for (int nt = 0; nt < 8; nt++) {
            mx0 = fmaxf(mx0, fmaxf(s[nt][0], s[nt][1]));
            mx1 = fmaxf(mx1, fmaxf(s[nt][2], s[nt][3]));
        }
        mx0 = fmaxf(mx0, __shfl_xor_sync(0xffffffffu, mx0, 1));
        mx0 = fmaxf(mx0, __shfl_xor_sync(0xffffffffu, mx0, 2));
        mx1 = fmaxf(mx1, __shfl_xor_sync(0xffffffffu, mx1, 1));
        mx1 = fmaxf(mx1, __shfl_xor_sync(0xffffffffu, mx1, 2));

        float nm0 = fmaxf(m0, mx0), nm1 = fmaxf(m1, mx1);
        float cr0 = __expf(m0 - nm0), cr1 = __expf(m1 - nm1);
        float rs0 = 0.0f, rs1 = 0.0f;

        #pragma unroll
        for (int nt = 0; nt < 8; nt++) {
            uint32_t t0 = f2tf32(__expf(s[nt][0] - nm0));
            uint32_t t1 = f2tf32(__expf(s[nt][1] - nm0));
            uint32_t t2 = f2tf32(__expf(s[nt][2] - nm1));
            uint32_t t3 = f2tf32(__expf(s[nt][3] - nm1));
            rs0 += __uint_as_float(t0) + __uint_as_float(t1);
            rs1 += __uint_as_float(t2) + __uint_as_float(t3);
            int cb = nt * 8 + tig * 2;
            Pu[prow * KP + cb]           = t0;
            Pu[prow * KP + cb + 1]       = t1;
            Pu[(prow + 8) * KP + cb]     = t2;
            Pu[(prow + 8) * KP + cb + 1] = t3;
        }
        rs0 += __shfl_xor_sync(0xffffffffu, rs0, 1);
        rs0 += __shfl_xor_sync(0xffffffffu, rs0, 2);
        rs1 += __shfl_xor_sync(0xffffffffu, rs1, 1);
        rs1 += __shfl_xor_sync(0xffffffffu, rs1, 2);

        l0 = l0 * cr0 + rs0;  m0 = nm0;
        l1 = l1 * cr1 + rs1;  m1 = nm1;
        #pragma unroll
        for (int nt = 0; nt < 8; nt++) {
            o[nt][0] *= cr0; o[nt][1] *= cr0;
            o[nt][2] *= cr1; o[nt][3] *= cr1;
        }
        __syncwarp();   // P visible across lanes of this warp

        // O += P @ V
        #pragma unroll
        for (int kk = 0; kk < 8; kk++) {
            uint32_t af[4];
            af[0] = Pu[prow * KP + kk * 8 + tig];
            af[1] = Pu[(prow + 8) * KP + kk * 8 + tig];
            af[2] = Pu[prow * KP + kk * 8 + tig + 4];
            af[3] = Pu[(prow + 8) * KP + kk * 8 + tig + 4];
            #pragma unroll
            for (int nt = 0; nt < 8; nt++) {
                uint32_t bf[2];
                bf[0] = f2tf32(Vc[(kk * 8 + tig) * VP + nt * 8 + gid]);
                bf[1] = f2tf32(Vc[(kk * 8 + tig + 4) * VP + nt * 8 + gid]);
                mma_tf32(o[nt], af, bf);
            }
        }
        __syncthreads();   // all reads of buf `cur` done before restage
    }

    // Epilogue: normalize, store ctx.
    float il0 = 1.0f / l0, il1 = 1.0f / l1;
    float* Ob = O + ((size_t)(b * SSQ + q0 + warp * 16)) * DDM + h * DKK;
    #pragma unroll
    for (int nt = 0; nt < 8; nt++) {
        int c = nt * 8 + tig * 2;
        float2 v0 = { o[nt][0] * il0, o[nt][1] * il0 };
        float2 v1 = { o[nt][2] * il1, o[nt][3] * il1 };
        *(float2*)(Ob + (size_t)gid * DDM + c) = v0;
        *(float2*)(Ob + (size_t)(gid + 8) * DDM + c) = v1;
    }
}

#define FLASH_SMEM ((2 * KSTR + 2 * VSTR + 256 * KP) * (int)sizeof(float))

// ---------------------------------------------------------------------------
extern "C" void kernel_launch(void* const* d_in, const int* in_sizes, int n_in,
                              void* d_out, int out_size)
{
    (void)in_sizes; (void)n_in; (void)out_size;
    const float* query = (const float*)d_in[0];
    const float* key_  = (const float*)d_in[1];
    const float* value = (const float*)d_in[2];
    const float* wq = (const float*)d_in[3];
    const float* bq = (const float*)d_in[4];
    const float* wk = (const float*)d_in[5];
    const float* bk = (const float*)d_in[6];
    const float* wv = (const float*)d_in[7];
    const float* bv = (const float*)d_in[8];
    const float* wo = (const float*)d_in[9];
    const float* bo = (const float*)d_in[10];
    // d_in[11] = racing_bias: constant over softmax axis -> cancels exactly.
    float* out = (float*)d_out;

    float *Qp, *Kp, *Vp, *Cp;
    cudaGetSymbolAddress((void**)&Qp, g_Q);
    cudaGetSymbolAddress((void**)&Kp, g_K);
    cudaGetSymbolAddress((void**)&Vp, g_V);
    cudaGetSymbolAddress((void**)&Cp, g_C);

    const int M = BB * SSQ;
    const int N = DDM;
    const int Kdim = DDM;

    static int attr_done = 0;
    if (!attr_done) {
        cudaFuncSetAttribute(gemm_qkv,
            cudaFuncAttributeMaxDynamicSharedMemorySize, GEMM_SMEM);
        cudaFuncSetAttribute(gemm_single,
            cudaFuncAttributeMaxDynamicSharedMemorySize, GEMM_SMEM);
        cudaFuncSetAttribute(flash_mma,
            cudaFuncAttributeMaxDynamicSharedMemorySize, FLASH_SMEM);
        attr_done = 1;
    }

    // Fused Q/K/V projections (tf32 tensor cores, cp.async pipelined).
    dim3 qkvGrid(N / 128, M / 128, 3);
    gemm_qkv<<<qkvGrid, 256, GEMM_SMEM>>>(query, key_, value, wq, wk, wv,
                                          bq, bk, bv, Qp, Kp, Vp, M, N, Kdim);

    // Flash attention on tensor cores (cp.async pipelined).
    dim3 fGrid(SSQ / 256, BB * HH);   // (8, 32) = 256 CTAs
    flash_mma<<<fGrid, 512, FLASH_SMEM>>>(Qp, Kp, Vp, Cp);

    // Output projection.
    dim3 oGrid(N / 128, M / 128, 1);
    gemm_single<<<oGrid, 256, GEMM_SMEM>>>(Cp, wo, bo, out, M, N, Kdim);
}

// round 6
// speedup vs baseline: 3.6893x; 1.1141x over previous
#include <cuda_runtime.h>
#include <cstdint>

// Problem constants
#define BB   2
#define SSQ  2048
#define DDM  1024
#define HH   16
#define DKK  64

// Scratch: intermediates live in __device__ globals (no allocation allowed).
__device__ float g_Q[BB * SSQ * DDM];
__device__ float g_K[BB * SSQ * DDM];
__device__ float g_V[BB * SSQ * DDM];
__device__ float g_C[BB * SSQ * DDM];

// ---------------------------------------------------------------------------
// helpers
// ---------------------------------------------------------------------------
__device__ __forceinline__ uint32_t f2tf32(float x) {
    uint32_t r;
    asm("cvt.rna.tf32.f32 %0, %1;" : "=r"(r) : "f"(x));
    return r;
}

__device__ __forceinline__ void mma_tf32(float d[4], const uint32_t a[4],
                                         const uint32_t b[2]) {
    asm volatile(
        "mma.sync.aligned.m16n8k8.row.col.f32.tf32.tf32.f32 "
        "{%0,%1,%2,%3}, {%4,%5,%6,%7}, {%8,%9}, {%0,%1,%2,%3};"
        : "+f"(d[0]), "+f"(d[1]), "+f"(d[2]), "+f"(d[3])
        : "r"(a[0]), "r"(a[1]), "r"(a[2]), "r"(a[3]), "r"(b[0]), "r"(b[1]));
}

__device__ __forceinline__ void cp16(void* smem_dst, const void* gsrc) {
    asm volatile("cp.async.ca.shared.global [%0], [%1], 16;"
                 :: "r"((uint32_t)__cvta_generic_to_shared(smem_dst)),
                    "l"(gsrc));
}
#define CP_COMMIT() asm volatile("cp.async.commit_group;")
#define CP_WAIT1()  asm volatile("cp.async.wait_group 1;")

// ---------------------------------------------------------------------------
// tf32 GEMM: C[M,N] = A[M,K] @ W[N,K]^T + bias[N]   (unchanged from R4)
// ---------------------------------------------------------------------------
#define GP 36
#define GA_STRIDE (128 * GP)

__device__ __forceinline__ void gemm_tf32_core(
    const float* __restrict__ A, const float* __restrict__ W,
    const float* __restrict__ bias, float* __restrict__ C,
    int M, int N, int K)
{
    extern __shared__ float gsm[];
    float* Aa = gsm;
    float* Ww = gsm + 2 * GA_STRIDE;

    const int tid  = threadIdx.x;
    const int warp = tid >> 5;
    const int lane = tid & 31;
    const int wm   = warp >> 2;
    const int wn   = warp & 3;
    const int gid  = lane >> 2;
    const int tig  = lane & 3;
    const int m0   = blockIdx.y * 128;
    const int n0   = blockIdx.x * 128;

    float acc[4][4][4];
    #pragma unroll
    for (int mt = 0; mt < 4; mt++)
        #pragma unroll
        for (int nt = 0; nt < 4; nt++)
            #pragma unroll
            for (int i = 0; i < 4; i++)
                acc[mt][nt][i] = 0.0f;

    const int nchunk = K >> 5;

    auto stage = [&](int ck, int buf) {
        int k0 = ck * 32;
        #pragma unroll
        for (int it = 0; it < 4; it++) {
            int slot = tid + it * 256;
            int r    = slot >> 3;
            int c4   = (slot & 7) * 4;
            cp16(&Aa[buf * GA_STRIDE + r * GP + c4],
                 A + (size_t)(m0 + r) * K + k0 + c4);
            cp16(&Ww[buf * GA_STRIDE + r * GP + c4],
                 W + (size_t)(n0 + r) * K + k0 + c4);
        }
    };

    stage(0, 0);
    CP_COMMIT();

    for (int ck = 0; ck < nchunk; ck++) {
        int cur = ck & 1;
        if (ck + 1 < nchunk) stage(ck + 1, cur ^ 1);
        CP_COMMIT();
        CP_WAIT1();
        __syncthreads();

        const float* Af = Aa + cur * GA_STRIDE;
        const float* Wf = Ww + cur * GA_STRIDE;
        #pragma unroll
        for (int kk = 0; kk < 32; kk += 8) {
            uint32_t a[4][4], b[4][2];
            #pragma unroll
            for (int mt = 0; mt < 4; mt++) {
                int r = wm * 64 + mt * 16 + gid;
                a[mt][0] = f2tf32(Af[r * GP + kk + tig]);
                a[mt][1] = f2tf32(Af[(r + 8) * GP + kk + tig]);
                a[mt][2] = f2tf32(Af[r * GP + kk + tig + 4]);
                a[mt][3] = f2tf32(Af[(r + 8) * GP + kk + tig + 4]);
            }
            #pragma unroll
            for (int nt = 0; nt < 4; nt++) {
                int cn = wn * 32 + nt * 8 + gid;
                b[nt][0] = f2tf32(Wf[cn * GP + kk + tig]);
                b[nt][1] = f2tf32(Wf[cn * GP + kk + tig + 4]);
            }
            #pragma unroll
            for (int mt = 0; mt < 4; mt++)
                #pragma unroll
                for (int nt = 0; nt < 4; nt++)
                    mma_tf32(acc[mt][nt], a[mt], b[nt]);
        }
        __syncthreads();
    }

    #pragma unroll
    for (int mt = 0; mt < 4; mt++) {
        int r0 = m0 + wm * 64 + mt * 16 + gid;
        #pragma unroll
        for (int nt = 0; nt < 4; nt++) {
            int c = n0 + wn * 32 + nt * 8 + tig * 2;
            float bx = bias[c], by = bias[c + 1];
            float2 v0 = { acc[mt][nt][0] + bx, acc[mt][nt][1] + by };
            float2 v1 = { acc[mt][nt][2] + bx, acc[mt][nt][3] + by };
            *(float2*)(C + (size_t)r0 * N + c) = v0;
            *(float2*)(C + (size_t)(r0 + 8) * N + c) = v1;
        }
    }
}

#define GEMM_SMEM (4 * GA_STRIDE * (int)sizeof(float))   // 73728 B

__global__ __launch_bounds__(256, 2) void gemm_qkv(
    const float* __restrict__ xq, const float* __restrict__ xk,
    const float* __restrict__ xv,
    const float* __restrict__ wq, const float* __restrict__ wk,
    const float* __restrict__ wv,
    const float* __restrict__ bq, const float* __restrict__ bk,
    const float* __restrict__ bv,
    float* __restrict__ Q, float* __restrict__ K, float* __restrict__ V,
    int M, int N, int Kd)
{
    const float *A, *W, *bias;
    float* C;
    if (blockIdx.z == 0)      { A = xq; W = wq; bias = bq; C = Q; }
    else if (blockIdx.z == 1) { A = xk; W = wk; bias = bk; C = K; }
    else                      { A = xv; W = wv; bias = bv; C = V; }
    gemm_tf32_core(A, W, bias, C, M, N, Kd);
}

__global__ __launch_bounds__(256, 2) void gemm_single(
    const float* __restrict__ A, const float* __restrict__ W,
    const float* __restrict__ bias, float* __restrict__ C,
    int M, int N, int Kd)
{
    gemm_tf32_core(A, W, bias, C, M, N, Kd);
}

// ---------------------------------------------------------------------------
// Flash attention, tf32 mma, 32 query rows per warp (2 m-tiles).
// CTA = 256 query rows, 256 threads (8 warps). Bk = 64, dk = 64.
// K staged [key][d] pad 68; V staged [key][d] pad 72 (both conflict-free).
// P never touches smem: QK-acc -> PV-A-operand relayout via quad shuffles.
// racing_bias cancels in softmax -> skipped.
// ---------------------------------------------------------------------------
#define KP 68
#define VP 72
#define KSTR (64 * KP)
#define VSTR (64 * VP)
#define FLASH_SMEM ((2 * KSTR + 2 * VSTR) * (int)sizeof(float))   // 71680

__global__ __launch_bounds__(256, 1) void flash_mma(
    const float* __restrict__ Q, const float* __restrict__ K,
    const float* __restrict__ V, float* __restrict__ O)
{
    extern __shared__ float fsm[];
    float* Kf = fsm;                 // [2][64][KP]
    float* Vf = fsm + 2 * KSTR;      // [2][64][VP]

    const int tid  = threadIdx.x;
    const int warp = tid >> 5;
    const int lane = tid & 31;
    const int gid  = lane >> 2;
    const int tig  = lane & 3;
    const int b    = blockIdx.y / HH;
    const int h    = blockIdx.y % HH;
    const int q0   = blockIdx.x * 256;

    // shuffle sources for the P relayout (within quad of this gid)
    const int srcA = (lane & ~3) | (tig >> 1);
    const int srcB = srcA + 2;
    const bool oddt = (tig & 1);

    const float* Qb = Q + ((size_t)(b * SSQ + q0 + warp * 32)) * DDM + h * DKK;
    const float* Kb = K + ((size_t)(b * SSQ)) * DDM + h * DKK;
    const float* Vb = V + ((size_t)(b * SSQ)) * DDM + h * DKK;

    // Q fragments for both m-tiles, resident all loop, pre-scaled by 1/8.
    uint32_t qf[2][8][4];
    #pragma unroll
    for (int mt = 0; mt < 2; mt++) {
        const float* Qm = Qb + (size_t)(mt * 16) * DDM;
        #pragma unroll
        for (int kk = 0; kk < 8; kk++) {
            int c = kk * 8 + tig;
            qf[mt][kk][0] = f2tf32(0.125f * Qm[(size_t)gid * DDM + c]);
            qf[mt][kk][1] = f2tf32(0.125f * Qm[(size_t)(gid + 8) * DDM + c]);
            qf[mt][kk][2] = f2tf32(0.125f * Qm[(size_t)gid * DDM + c + 4]);
            qf[mt][kk][3] = f2tf32(0.125f * Qm[(size_t)(gid + 8) * DDM + c + 4]);
        }
    }

    float mrow[2][2], lrow[2][2];
    float o[2][8][4];
    #pragma unroll
    for (int mt = 0; mt < 2; mt++) {
        mrow[mt][0] = -1e30f; mrow[mt][1] = -1e30f;
        lrow[mt][0] = 0.0f;   lrow[mt][1] = 0.0f;
        #pragma unroll
        for (int nt = 0; nt < 8; nt++)
            #pragma unroll
            for (int i = 0; i < 4; i++) o[mt][nt][i] = 0.0f;
    }

    auto stage = [&](int ck, int buf) {
        const float* Kg = Kb + (size_t)(ck * 64) * DDM;
        const float* Vg = Vb + (size_t)(ck * 64) * DDM;
        #pragma unroll
        for (int it = 0; it < 4; it++) {
            int seg = tid + it * 256;       // 0..1023
            int r   = seg >> 4;             // key 0..63
            int c   = (seg & 15) * 4;       // d 0..60
            cp16(&Kf[buf * KSTR + r * KP + c], Kg + (size_t)r * DDM + c);
            cp16(&Vf[buf * VSTR + r * VP + c], Vg + (size_t)r * DDM + c);
        }
    };

    stage(0, 0);
    CP_COMMIT();

    const int niter = SSQ / 64;   // 32
    for (int ck = 0; ck < niter; ck++) {
        int cur = ck & 1;
        if (ck + 1 < niter) stage(ck + 1, cur ^ 1);
        CP_COMMIT();
        CP_WAIT1();
        __syncthreads();

        const float* Kc = Kf + cur * KSTR;
        const float* Vc = Vf + cur * VSTR;

        // S = (Q/8) @ K^T for both m-tiles; B-frags shared across mt.
        float s[2][8][4];
        #pragma unroll
        for (int mt = 0; mt < 2; mt++)
            #pragma unroll
            for (int nt = 0; nt < 8; nt++)
                #pragma unroll
                for (int i = 0; i < 4; i++) s[mt][nt][i] = 0.0f;

        #pragma unroll
        for (int kk = 0; kk < 8; kk++) {
            #pragma unroll
            for (int nt = 0; nt < 8; nt++) {
                uint32_t bf[2];
                bf[0] = f2tf32(Kc[(nt * 8 + gid) * KP + kk * 8 + tig]);
                bf[1] = f2tf32(Kc[(nt * 8 + gid) * KP + kk * 8 + tig + 4]);
                mma_tf32(s[0][nt], qf[0][kk], bf);
                mma_tf32(s[1][nt], qf[1][kk], bf);
            }
        }

        // Online softmax per m-tile; P (tf32-rounded) kept in s registers.
        #pragma unroll
        for (int mt = 0; mt < 2; mt++) {
            float mx0 = -1e30f, mx1 = -1e30f;
            #pragma unroll
            for (int nt = 0; nt < 8; nt++) {
                mx0 = fmaxf(mx0, fmaxf(s[mt][nt][0], s[mt][nt][1]));
                mx1 = fmaxf(mx1, fmaxf(s[mt][nt][2], s[mt][nt][3]));
            }
            mx0 = fmaxf(mx0, __shfl_xor_sync(0xffffffffu, mx0, 1));
            mx0 = fmaxf(mx0, __shfl_xor_sync(0xffffffffu, mx0, 2));
            mx1 = fmaxf(mx1, __shfl_xor_sync(0xffffffffu, mx1, 1));
            mx1 = fmaxf(mx1, __shfl_xor_sync(0xffffffffu, mx1, 2));

            float nm0 = fmaxf(mrow[mt][0], mx0);
            float nm1 = fmaxf(mrow[mt][1], mx1);
            float cr0 = __expf(mrow[mt][0] - nm0);
            float cr1 = __expf(mrow[mt][1] - nm1);
            float rs0 = 0.0f, rs1 = 0.0f;

            #pragma unroll
            for (int nt = 0; nt < 8; nt++) {
                uint32_t t0 = f2tf32(__expf(s[mt][nt][0] - nm0));
                uint32_t t1 = f2tf32(__expf(s[mt][nt][1] - nm0));
                uint32_t t2 = f2tf32(__expf(s[mt][nt][2] - nm1));
                uint32_t t3 = f2tf32(__expf(s[mt][nt][3] - nm1));
                rs0 += __uint_as_float(t0) + __uint_as_float(t1);
                rs1 += __uint_as_float(t2) + __uint_as_float(t3);
                s[mt][nt][0] = __uint_as_float(t0);
                s[mt][nt][1] = __uint_as_float(t1);
                s[mt][nt][2] = __uint_as_float(t2);
                s[mt][nt][3] = __uint_as_float(t3);
            }
            rs0 += __shfl_xor_sync(0xffffffffu, rs0, 1);
            rs0 += __shfl_xor_sync(0xffffffffu, rs0, 2);
            rs1 += __shfl_xor_sync(0xffffffffu, rs1, 1);
            rs1 += __shfl_xor_sync(0xffffffffu, rs1, 2);

            lrow[mt][0] = lrow[mt][0] * cr0 + rs0;  mrow[mt][0] = nm0;
            lrow[mt][1] = lrow[mt][1] * cr1 + rs1;  mrow[mt][1] = nm1;
            #pragma unroll
            for (int nt = 0; nt < 8; nt++) {
                o[mt][nt][0] *= cr0; o[mt][nt][1] *= cr0;
                o[mt][nt][2] *= cr1; o[mt][nt][3] *= cr1;
            }
        }

        // O += P @ V. A-frags built from s via quad shuffles (no smem).
        #pragma unroll
        for (int kk = 0; kk < 8; kk++) {
            uint32_t af[2][4];
            #pragma unroll
            for (int mt = 0; mt < 2; mt++) {
                float pa0 = __shfl_sync(0xffffffffu, s[mt][kk][0], srcA);
                float pa1 = __shfl_sync(0xffffffffu, s[mt][kk][1], srcA);
                float pa2 = __shfl_sync(0xffffffffu, s[mt][kk][2], srcA);
                float pa3 = __shfl_sync(0xffffffffu, s[mt][kk][3], srcA);
                float pb0 = __shfl_sync(0xffffffffu, s[mt][kk][0], srcB);
                float pb1 = __shfl_sync(0xffffffffu, s[mt][kk][1], srcB);
                float pb2 = __shfl_sync(0xffffffffu, s[mt][kk][2], srcB);
                float pb3 = __shfl_sync(0xffffffffu, s[mt][kk][3], srcB);
                af[mt][0] = __float_as_uint(oddt ? pa1 : pa0);
                af[mt][1] = __float_as_uint(oddt ? pa3 : pa2);
                af[mt][2] = __float_as_uint(oddt ? pb1 : pb0);
                af[mt][3] = __float_as_uint(oddt ? pb3 : pb2);
            }
            #pragma unroll
            for (int nt = 0; nt < 8; nt++) {
                uint32_t bf[2];
                bf[0] = f2tf32(Vc[(kk * 8 + tig) * VP + nt * 8 + gid]);
                bf[1] = f2tf32(Vc[(kk * 8 + tig + 4) * VP + nt * 8 + gid]);
                mma_tf32(o[0][nt], af[0], bf);
                mma_tf32(o[1][nt], af[1], bf);
            }
        }
        __syncthreads();   // all reads of buf `cur` done before restage
    }

    // Epilogue: normalize, store ctx.
    #pragma unroll
    for (int mt = 0; mt < 2; mt++) {
        float il0 = 1.0f / lrow[mt][0], il1 = 1.0f / lrow[mt][1];
        float* Ob = O + ((size_t)(b * SSQ + q0 + warp * 32 + mt * 16)) * DDM
                      + h * DKK;
        #pragma unroll
        for (int nt = 0; nt < 8; nt++) {
            int c = nt * 8 + tig * 2;
            float2 v0 = { o[mt][nt][0] * il0, o[mt][nt][1] * il0 };
            float2 v1 = { o[mt][nt][2] * il1, o[mt][nt][3] * il1 };
            *(float2*)(Ob + (size_t)gid * DDM + c) = v0;
            *(float2*)(Ob + (size_t)(gid + 8) * DDM + c) = v1;
        }
    }
}

// ---------------------------------------------------------------------------
extern "C" void kernel_launch(void* const* d_in, const int* in_sizes, int n_in,
                              void* d_out, int out_size)
{
    (void)in_sizes; (void)n_in; (void)out_size;
    const float* query = (const float*)d_in[0];
    const float* key_  = (const float*)d_in[1];
    const float* value = (const float*)d_in[2];
    const float* wq = (const float*)d_in[3];
    const float* bq = (const float*)d_in[4];
    const float* wk = (const float*)d_in[5];
    const float* bk = (const float*)d_in[6];
    const float* wv = (const float*)d_in[7];
    const float* bv = (const float*)d_in[8];
    const float* wo = (const float*)d_in[9];
    const float* bo = (const float*)d_in[10];
    // d_in[11] = racing_bias: constant over softmax axis -> cancels exactly.
    float* out = (float*)d_out;

    float *Qp, *Kp, *Vp, *Cp;
    cudaGetSymbolAddress((void**)&Qp, g_Q);
    cudaGetSymbolAddress((void**)&Kp, g_K);
    cudaGetSymbolAddress((void**)&Vp, g_V);
    cudaGetSymbolAddress((void**)&Cp, g_C);

    const int M = BB * SSQ;
    const int N = DDM;
    const int Kdim = DDM;

    cudaFuncSetAttribute(gemm_qkv,
        cudaFuncAttributeMaxDynamicSharedMemorySize, GEMM_SMEM);
    cudaFuncSetAttribute(gemm_single,
        cudaFuncAttributeMaxDynamicSharedMemorySize, GEMM_SMEM);
    cudaFuncSetAttribute(flash_mma,
        cudaFuncAttributeMaxDynamicSharedMemorySize, FLASH_SMEM);

    // Fused Q/K/V projections (tf32 tensor cores, cp.async pipelined).
    dim3 qkvGrid(N / 128, M / 128, 3);
    gemm_qkv<<<qkvGrid, 256, GEMM_SMEM>>>(query, key_, value, wq, wk, wv,
                                          bq, bk, bv, Qp, Kp, Vp, M, N, Kdim);

    // Flash attention (tf32 mma, shuffle P relayout, cp.async pipelined).
    dim3 fGrid(SSQ / 256, BB * HH);   // (8, 32) = 256 CTAs
    flash_mma<<<fGrid, 256, FLASH_SMEM>>>(Qp, Kp, Vp, Cp);

    // Output projection.
    dim3 oGrid(N / 128, M / 128, 1);
    gemm_single<<<oGrid, 256, GEMM_SMEM>>>(Cp, wo, bo, out, M, N, Kdim);
}

// round 7
// speedup vs baseline: 3.7172x; 1.0076x over previous
#include <cuda_runtime.h>
#include <cstdint>

// Problem constants
#define BB   2
#define SSQ  2048
#define DDM  1024
#define HH   16
#define DKK  64

// Scratch (no allocation allowed -> device globals).
__device__ float g_Q[BB * SSQ * DDM];
__device__ float g_K[BB * SSQ * DDM];
__device__ float g_V[BB * SSQ * DDM];
__device__ float g_C[BB * SSQ * DDM];
// tf32-pre-rounded copies of inputs and weights
__device__ float g_Xq[BB * SSQ * DDM];
__device__ float g_Xk[BB * SSQ * DDM];
__device__ float g_Xv[BB * SSQ * DDM];
__device__ float g_Wr[4 * DDM * DDM];   // wq | wk | wv | wo

// ---------------------------------------------------------------------------
// helpers
// ---------------------------------------------------------------------------
__device__ __forceinline__ uint32_t f2tf32(float x) {
    uint32_t r;
    asm("cvt.rna.tf32.f32 %0, %1;" : "=r"(r) : "f"(x));
    return r;
}

__device__ __forceinline__ void mma_tf32(float d[4], const uint32_t a[4],
                                         const uint32_t b[2]) {
    asm volatile(
        "mma.sync.aligned.m16n8k8.row.col.f32.tf32.tf32.f32 "
        "{%0,%1,%2,%3}, {%4,%5,%6,%7}, {%8,%9}, {%0,%1,%2,%3};"
        : "+f"(d[0]), "+f"(d[1]), "+f"(d[2]), "+f"(d[3])
        : "r"(a[0]), "r"(a[1]), "r"(a[2]), "r"(a[3]), "r"(b[0]), "r"(b[1]));
}

__device__ __forceinline__ void cp16(void* smem_dst, const void* gsrc) {
    asm volatile("cp.async.ca.shared.global [%0], [%1], 16;"
                 :: "r"((uint32_t)__cvta_generic_to_shared(smem_dst)),
                    "l"(gsrc));
}
#define CP_COMMIT() asm volatile("cp.async.commit_group;")
#define CP_WAIT1()  asm volatile("cp.async.wait_group 1;")

// ---------------------------------------------------------------------------
// Pre-round: dst[i] = tf32(src[i]). Rounding point identical to the old
// cvt-at-consume, so overall numerics are bit-identical.
// ---------------------------------------------------------------------------
__global__ __launch_bounds__(256) void preround(const float* __restrict__ src,
                                                float* __restrict__ dst, int n)
{
    int i = (blockIdx.x * 256 + threadIdx.x) * 4;
    if (i >= n) return;
    float4 v = *(const float4*)(src + i);
    uint4 t = { f2tf32(v.x), f2tf32(v.y), f2tf32(v.z), f2tf32(v.w) };
    *(uint4*)(dst + i) = t;
}

// ---------------------------------------------------------------------------
// tf32 GEMM: C[M,N] = A[M,K] @ W[N,K]^T + bias[N]
// A and W are PRE-ROUNDED to tf32 -> raw-bit fragment loads, no cvt.
// ROUND_STORE: round the output to tf32 (for tensors later consumed as
// tf32 mma operands).
// ---------------------------------------------------------------------------
#define GP 36
#define GA_STRIDE (128 * GP)

template <bool ROUND_STORE>
__device__ __forceinline__ void gemm_tf32_core(
    const float* __restrict__ A, const float* __restrict__ W,
    const float* __restrict__ bias, float* __restrict__ C,
    int M, int N, int K)
{
    extern __shared__ float gsm[];
    float* Aa = gsm;
    float* Ww = gsm + 2 * GA_STRIDE;

    const int tid  = threadIdx.x;
    const int warp = tid >> 5;
    const int lane = tid & 31;
    const int wm   = warp >> 2;
    const int wn   = warp & 3;
    const int gid  = lane >> 2;
    const int tig  = lane & 3;
    const int m0   = blockIdx.y * 128;
    const int n0   = blockIdx.x * 128;

    float acc[4][4][4];
    #pragma unroll
    for (int mt = 0; mt < 4; mt++)
        #pragma unroll
        for (int nt = 0; nt < 4; nt++)
            #pragma unroll
            for (int i = 0; i < 4; i++)
                acc[mt][nt][i] = 0.0f;

    const int nchunk = K >> 5;

    auto stage = [&](int ck, int buf) {
        int k0 = ck * 32;
        #pragma unroll
        for (int it = 0; it < 4; it++) {
            int slot = tid + it * 256;
            int r    = slot >> 3;
            int c4   = (slot & 7) * 4;
            cp16(&Aa[buf * GA_STRIDE + r * GP + c4],
                 A + (size_t)(m0 + r) * K + k0 + c4);
            cp16(&Ww[buf * GA_STRIDE + r * GP + c4],
                 W + (size_t)(n0 + r) * K + k0 + c4);
        }
    };

    stage(0, 0);
    CP_COMMIT();

    for (int ck = 0; ck < nchunk; ck++) {
        int cur = ck & 1;
        if (ck + 1 < nchunk) stage(ck + 1, cur ^ 1);
        CP_COMMIT();
        CP_WAIT1();
        __syncthreads();

        const uint32_t* Af = (const uint32_t*)(Aa + cur * GA_STRIDE);
        const uint32_t* Wf = (const uint32_t*)(Ww + cur * GA_STRIDE);
        #pragma unroll
        for (int kk = 0; kk < 32; kk += 8) {
            uint32_t a[4][4], b[4][2];
            #pragma unroll
            for (int mt = 0; mt < 4; mt++) {
                int r = wm * 64 + mt * 16 + gid;
                a[mt][0] = Af[r * GP + kk + tig];
                a[mt][1] = Af[(r + 8) * GP + kk + tig];
                a[mt][2] = Af[r * GP + kk + tig + 4];
                a[mt][3] = Af[(r + 8) * GP + kk + tig + 4];
            }
            #pragma unroll
            for (int nt = 0; nt < 4; nt++) {
                int cn = wn * 32 + nt * 8 + gid;
                b[nt][0] = Wf[cn * GP + kk + tig];
                b[nt][1] = Wf[cn * GP + kk + tig + 4];
            }
            #pragma unroll
            for (int mt = 0; mt < 4; mt++)
                #pragma unroll
                for (int nt = 0; nt < 4; nt++)
                    mma_tf32(acc[mt][nt], a[mt], b[nt]);
        }
        __syncthreads();
    }

    #pragma unroll
    for (int mt = 0; mt < 4; mt++) {
        int r0 = m0 + wm * 64 + mt * 16 + gid;
        #pragma unroll
        for (int nt = 0; nt < 4; nt++) {
            int c = n0 + wn * 32 + nt * 8 + tig * 2;
            float bx = bias[c], by = bias[c + 1];
            float r00 = acc[mt][nt][0] + bx, r01 = acc[mt][nt][1] + by;
            float r10 = acc[mt][nt][2] + bx, r11 = acc[mt][nt][3] + by;
            if (ROUND_STORE) {
                r00 = __uint_as_float(f2tf32(r00));
                r01 = __uint_as_float(f2tf32(r01));
                r10 = __uint_as_float(f2tf32(r10));
                r11 = __uint_as_float(f2tf32(r11));
            }
            float2 v0 = { r00, r01 };
            float2 v1 = { r10, r11 };
            *(float2*)(C + (size_t)r0 * N + c) = v0;
            *(float2*)(C + (size_t)(r0 + 8) * N + c) = v1;
        }
    }
}

#define GEMM_SMEM (4 * GA_STRIDE * (int)sizeof(float))   // 73728 B

__global__ __launch_bounds__(256, 2) void gemm_qkv(
    const float* __restrict__ xq, const float* __restrict__ xk,
    const float* __restrict__ xv, const float* __restrict__ w3,
    const float* __restrict__ bq, const float* __restrict__ bk,
    const float* __restrict__ bv,
    float* __restrict__ Q, float* __restrict__ K, float* __restrict__ V,
    int M, int N, int Kd)
{
    const float *A, *W, *bias;
    float* C;
    if (blockIdx.z == 0)      { A = xq; W = w3;                bias = bq; C = Q; }
    else if (blockIdx.z == 1) { A = xk; W = w3 + DDM * DDM;     bias = bk; C = K; }
    else                      { A = xv; W = w3 + 2 * DDM * DDM; bias = bv; C = V; }
    gemm_tf32_core<true>(A, W, bias, C, M, N, Kd);
}

__global__ __launch_bounds__(256, 2) void gemm_single(
    const float* __restrict__ A, const float* __restrict__ W,
    const float* __restrict__ bias, float* __restrict__ C,
    int M, int N, int Kd)
{
    gemm_tf32_core<false>(A, W, bias, C, M, N, Kd);
}

// ---------------------------------------------------------------------------
// Flash attention, tf32 mma, 32 query rows per warp (2 m-tiles).
// Q/K/V are tf32-pre-rounded by the projection epilogue -> raw-bit loads.
// 3-stage cp.async ring -> single __syncthreads per iteration.
// P never touches smem (quad-shuffle relayout). racing_bias cancels.
// ---------------------------------------------------------------------------
#define KP 68
#define VP 72
#define KSTR (64 * KP)
#define VSTR (64 * VP)
#define STG  (KSTR + VSTR)
#define FLASH_SMEM (3 * STG * (int)sizeof(float))   // 107520

__global__ __launch_bounds__(256, 1) void flash_mma(
    const float* __restrict__ Q, const float* __restrict__ K,
    const float* __restrict__ V, float* __restrict__ O)
{
    extern __shared__ float fsm[];

    const int tid  = threadIdx.x;
    const int warp = tid >> 5;
    const int lane = tid & 31;
    const int gid  = lane >> 2;
    const int tig  = lane & 3;
    const int b    = blockIdx.y / HH;
    const int h    = blockIdx.y % HH;
    const int q0   = blockIdx.x * 256;

    const int srcA = (lane & ~3) | (tig >> 1);
    const int srcB = srcA + 2;
    const bool oddt = (tig & 1);

    const float* Qb = Q + ((size_t)(b * SSQ + q0 + warp * 32)) * DDM + h * DKK;
    const float* Kb = K + ((size_t)(b * SSQ)) * DDM + h * DKK;
    const float* Vb = V + ((size_t)(b * SSQ)) * DDM + h * DKK;

    // Q fragments (already tf32-rounded in global; *0.125f is exact).
    uint32_t qf[2][8][4];
    #pragma unroll
    for (int mt = 0; mt < 2; mt++) {
        const float* Qm = Qb + (size_t)(mt * 16) * DDM;
        #pragma unroll
        for (int kk = 0; kk < 8; kk++) {
            int c = kk * 8 + tig;
            qf[mt][kk][0] = __float_as_uint(0.125f * Qm[(size_t)gid * DDM + c]);
            qf[mt][kk][1] = __float_as_uint(0.125f * Qm[(size_t)(gid + 8) * DDM + c]);
            qf[mt][kk][2] = __float_as_uint(0.125f * Qm[(size_t)gid * DDM + c + 4]);
            qf[mt][kk][3] = __float_as_uint(0.125f * Qm[(size_t)(gid + 8) * DDM + c + 4]);
        }
    }

    float mrow[2][2], lrow[2][2];
    float o[2][8][4];
    #pragma unroll
    for (int mt = 0; mt < 2; mt++) {
        mrow[mt][0] = -1e30f; mrow[mt][1] = -1e30f;
        lrow[mt][0] = 0.0f;   lrow[mt][1] = 0.0f;
        #pragma unroll
        for (int nt = 0; nt < 8; nt++)
            #pragma unroll
            for (int i = 0; i < 4; i++) o[mt][nt][i] = 0.0f;
    }

    auto stage = [&](int ck, int buf) {
        const float* Kg = Kb + (size_t)(ck * 64) * DDM;
        const float* Vg = Vb + (size_t)(ck * 64) * DDM;
        float* Kd = fsm + buf * STG;
        float* Vd = fsm + buf * STG + KSTR;
        #pragma unroll
        for (int it = 0; it < 4; it++) {
            int seg = tid + it * 256;       // 0..1023
            int r   = seg >> 4;             // key 0..63
            int c   = (seg & 15) * 4;       // d 0..60
            cp16(&Kd[r * KP + c], Kg + (size_t)r * DDM + c);
            cp16(&Vd[r * VP + c], Vg + (size_t)r * DDM + c);
        }
    };

    stage(0, 0); CP_COMMIT();
    stage(1, 1); CP_COMMIT();

    const int niter = SSQ / 64;   // 32
    for (int ck = 0; ck < niter; ck++) {
        int cur = ck % 3;
        CP_WAIT1();            // stage(ck) complete
        __syncthreads();       // also fences: all reads of buf (ck%3) from
                               // iter ck-3 finished before its restage below
        if (ck + 2 < niter) stage(ck + 2, (ck + 2) % 3);
        CP_COMMIT();

        const uint32_t* Kc = (const uint32_t*)(fsm + cur * STG);
        const uint32_t* Vc = (const uint32_t*)(fsm + cur * STG + KSTR);

        // S = (Q/8) @ K^T for both m-tiles; B-frags shared across mt.
        float s[2][8][4];
        #pragma unroll
        for (int mt = 0; mt < 2; mt++)
            #pragma unroll
            for (int nt = 0; nt < 8; nt++)
                #pragma unroll
                for (int i = 0; i < 4; i++) s[mt][nt][i] = 0.0f;

        #pragma unroll
        for (int kk = 0; kk < 8; kk++) {
            #pragma unroll
            for (int nt = 0; nt < 8; nt++) {
                uint32_t bf[2];
                bf[0] = Kc[(nt * 8 + gid) * KP + kk * 8 + tig];
                bf[1] = Kc[(nt * 8 + gid) * KP + kk * 8 + tig + 4];
                mma_tf32(s[0][nt], qf[0][kk], bf);
                mma_tf32(s[1][nt], qf[1][kk], bf);
            }
        }

        // Online softmax per m-tile; P (tf32-rounded) kept in s registers.
        #pragma unroll
        for (int mt = 0; mt < 2; mt++) {
            float mx0 = -1e30f, mx1 = -1e30f;
            #pragma unroll
            for (int nt = 0; nt < 8; nt++) {
                mx0 = fmaxf(mx0, fmaxf(s[mt][nt][0], s[mt][nt][1]));
                mx1 = fmaxf(mx1, fmaxf(s[mt][nt][2], s[mt][nt][3]));
            }
            mx0 = fmaxf(mx0, __shfl_xor_sync(0xffffffffu, mx0, 1));
            mx0 = fmaxf(mx0, __shfl_xor_sync(0xffffffffu, mx0, 2));
            mx1 = fmaxf(mx1, __shfl_xor_sync(0xffffffffu, mx1, 1));
            mx1 = fmaxf(mx1, __shfl_xor_sync(0xffffffffu, mx1, 2));

            float nm0 = fmaxf(mrow[mt][0], mx0);
            float nm1 = fmaxf(mrow[mt][1], mx1);
            float cr0 = __expf(mrow[mt][0] - nm0);
            float cr1 = __expf(mrow[mt][1] - nm1);
            float rs0 = 0.0f, rs1 = 0.0f;

            #pragma unroll
            for (int nt = 0; nt < 8; nt++) {
                uint32_t t0 = f2tf32(__expf(s[mt][nt][0] - nm0));
                uint32_t t1 = f2tf32(__expf(s[mt][nt][1] - nm0));
                uint32_t t2 = f2tf32(__expf(s[mt][nt][2] - nm1));
                uint32_t t3 = f2tf32(__expf(s[mt][nt][3] - nm1));
                rs0 += __uint_as_float(t0) + __uint_as_float(t1);
                rs1 += __uint_as_float(t2) + __uint_as_float(t3);
                s[mt][nt][0] = __uint_as_float(t0);
                s[mt][nt][1] = __uint_as_float(t1);
                s[mt][nt][2] = __uint_as_float(t2);
                s[mt][nt][3] = __uint_as_float(t3);
            }
            rs0 += __shfl_xor_sync(0xffffffffu, rs0, 1);
            rs0 += __shfl_xor_sync(0xffffffffu, rs0, 2);
            rs1 += __shfl_xor_sync(0xffffffffu, rs1, 1);
            rs1 += __shfl_xor_sync(0xffffffffu, rs1, 2);

            lrow[mt][0] = lrow[mt][0] * cr0 + rs0;  mrow[mt][0] = nm0;
            lrow[mt][1] = lrow[mt][1] * cr1 + rs1;  mrow[mt][1] = nm1;
            #pragma unroll
            for (int nt = 0; nt < 8; nt++) {
                o[mt][nt][0] *= cr0; o[mt][nt][1] *= cr0;
                o[mt][nt][2] *= cr1; o[mt][nt][3] *= cr1;
            }
        }

        // O += P @ V. A-frags built from s via quad shuffles (no smem).
        #pragma unroll
        for (int kk = 0; kk < 8; kk++) {
            uint32_t af[2][4];
            #pragma unroll
            for (int mt = 0; mt < 2; mt++) {
                float pa0 = __shfl_sync(0xffffffffu, s[mt][kk][0], srcA);
                float pa1 = __shfl_sync(0xffffffffu, s[mt][kk][1], srcA);
                float pa2 = __shfl_sync(0xffffffffu, s[mt][kk][2], srcA);
                float pa3 = __shfl_sync(0xffffffffu, s[mt][kk][3], srcA);
                float pb0 = __shfl_sync(0xffffffffu, s[mt][kk][0], srcB);
                float pb1 = __shfl_sync(0xffffffffu, s[mt][kk][1], srcB);
                float pb2 = __shfl_sync(0xffffffffu, s[mt][kk][2], srcB);
                float pb3 = __shfl_sync(0xffffffffu, s[mt][kk][3], srcB);
                af[mt][0] = __float_as_uint(oddt ? pa1 : pa0);
                af[mt][1] = __float_as_uint(oddt ? pa3 : pa2);
                af[mt][2] = __float_as_uint(oddt ? pb1 : pb0);
                af[mt][3] = __float_as_uint(oddt ? pb3 : pb2);
            }
            #pragma unroll
            for (int nt = 0; nt < 8; nt++) {
                uint32_t bf[2];
                bf[0] = Vc[(kk * 8 + tig) * VP + nt * 8 + gid];
                bf[1] = Vc[(kk * 8 + tig + 4) * VP + nt * 8 + gid];
                mma_tf32(o[0][nt], af[0], bf);
                mma_tf32(o[1][nt], af[1], bf);
            }
        }
    }

    // Epilogue: normalize, round to tf32 (O-proj consumes raw bits), store.
    #pragma unroll
    for (int mt = 0; mt < 2; mt++) {
        float il0 = 1.0f / lrow[mt][0], il1 = 1.0f / lrow[mt][1];
        float* Ob = O + ((size_t)(b * SSQ + q0 + warp * 32 + mt * 16)) * DDM
                      + h * DKK;
        #pragma unroll
        for (int nt = 0; nt < 8; nt++) {
            int c = nt * 8 + tig * 2;
            float2 v0 = { __uint_as_float(f2tf32(o[mt][nt][0] * il0)),
                          __uint_as_float(f2tf32(o[mt][nt][1] * il0)) };
            float2 v1 = { __uint_as_float(f2tf32(o[mt][nt][2] * il1)),
                          __uint_as_float(f2tf32(o[mt][nt][3] * il1)) };
            *(float2*)(Ob + (size_t)gid * DDM + c) = v0;
            *(float2*)(Ob + (size_t)(gid + 8) * DDM + c) = v1;
        }
    }
}

// ---------------------------------------------------------------------------
extern "C" void kernel_launch(void* const* d_in, const int* in_sizes, int n_in,
                              void* d_out, int out_size)
{
    (void)in_sizes; (void)n_in; (void)out_size;
    const float* query = (const float*)d_in[0];
    const float* key_  = (const float*)d_in[1];
    const float* value = (const float*)d_in[2];
    const float* wq = (const float*)d_in[3];
    const float* bq = (const float*)d_in[4];
    const float* wk = (const float*)d_in[5];
    const float* bk = (const float*)d_in[6];
    const float* wv = (const float*)d_in[7];
    const float* bv = (const float*)d_in[8];
    const float* wo = (const float*)d_in[9];
    const float* bo = (const float*)d_in[10];
    // d_in[11] = racing_bias: constant over softmax axis -> cancels exactly.
    float* out = (float*)d_out;

    float *Qp, *Kp, *Vp, *Cp, *Xq, *Xk, *Xv, *Wr;
    cudaGetSymbolAddress((void**)&Qp, g_Q);
    cudaGetSymbolAddress((void**)&Kp, g_K);
    cudaGetSymbolAddress((void**)&Vp, g_V);
    cudaGetSymbolAddress((void**)&Cp, g_C);
    cudaGetSymbolAddress((void**)&Xq, g_Xq);
    cudaGetSymbolAddress((void**)&Xk, g_Xk);
    cudaGetSymbolAddress((void**)&Xv, g_Xv);
    cudaGetSymbolAddress((void**)&Wr, g_Wr);

    const int M = BB * SSQ;
    const int N = DDM;
    const int Kdim = DDM;

    cudaFuncSetAttribute(gemm_qkv,
        cudaFuncAttributeMaxDynamicSharedMemorySize, GEMM_SMEM);
    cudaFuncSetAttribute(gemm_single,
        cudaFuncAttributeMaxDynamicSharedMemorySize, GEMM_SMEM);
    cudaFuncSetAttribute(flash_mma,
        cudaFuncAttributeMaxDynamicSharedMemorySize, FLASH_SMEM);

    // Pre-round inputs + weights to tf32 (one-time rounding point).
    const int nIn = M * DDM;            // 4,194,304
    const int nW  = DDM * DDM;          // 1,048,576
    preround<<<nIn / 1024, 256>>>(query, Xq, nIn);
    preround<<<nIn / 1024, 256>>>(key_,  Xk, nIn);
    preround<<<nIn / 1024, 256>>>(value, Xv, nIn);
    preround<<<nW / 1024, 256>>>(wq, Wr,              nW);
    preround<<<nW / 1024, 256>>>(wk, Wr + nW,         nW);
    preround<<<nW / 1024, 256>>>(wv, Wr + 2 * nW,     nW);
    preround<<<nW / 1024, 256>>>(wo, Wr + 3 * nW,     nW);

    // Fused Q/K/V projections (tf32 tensor cores, cp.async pipelined).
    dim3 qkvGrid(N / 128, M / 128, 3);
    gemm_qkv<<<qkvGrid, 256, GEMM_SMEM>>>(Xq, Xk, Xv, Wr, bq, bk, bv,
                                          Qp, Kp, Vp, M, N, Kdim);

    // Flash attention (tf32 mma, raw-bit operands, 3-stage cp.async).
    dim3 fGrid(SSQ / 256, BB * HH);   // (8, 32) = 256 CTAs
    flash_mma<<<fGrid, 256, FLASH_SMEM>>>(Qp, Kp, Vp, Cp);

    // Output projection.
    dim3 oGrid(N / 128, M / 128, 1);
    gemm_single<<<oGrid, 256, GEMM_SMEM>>>(Cp, Wr + 3 * nW, bo, out,
                                           M, N, Kdim);
}

// round 8
// speedup vs baseline: 5.7767x; 1.5540x over previous
#include <cuda_runtime.h>
#include <cuda_fp16.h>
#include <cstdint>

// Problem constants
#define BB   2
#define SSQ  2048
#define DDM  1024
#define HH   16
#define DKK  64

// Scratch (no allocation allowed -> device globals).
__device__ __half g_Q[BB * SSQ * DDM];       // pre-scaled by 1/8
__device__ __half g_K[BB * SSQ * DDM];
__device__ __half g_V[BB * SSQ * DDM];
__device__ __half g_C[BB * SSQ * DDM];       // ctx
__device__ __half g_Xq[BB * SSQ * DDM];      // half inputs
__device__ __half g_Xk[BB * SSQ * DDM];
__device__ __half g_Xv[BB * SSQ * DDM];
__device__ __half g_Wr[4 * DDM * DDM];       // wq | wk | wv | wo (half)

// ---------------------------------------------------------------------------
// helpers
// ---------------------------------------------------------------------------
__device__ __forceinline__ void mma_f16(float d[4], const uint32_t a[4],
                                        const uint32_t b[2]) {
    asm volatile(
        "mma.sync.aligned.m16n8k16.row.col.f32.f16.f16.f32 "
        "{%0,%1,%2,%3}, {%4,%5,%6,%7}, {%8,%9}, {%0,%1,%2,%3};"
        : "+f"(d[0]), "+f"(d[1]), "+f"(d[2]), "+f"(d[3])
        : "r"(a[0]), "r"(a[1]), "r"(a[2]), "r"(a[3]), "r"(b[0]), "r"(b[1]));
}

__device__ __forceinline__ void cp16(void* smem_dst, const void* gsrc) {
    asm volatile("cp.async.ca.shared.global [%0], [%1], 16;"
                 :: "r"((uint32_t)__cvta_generic_to_shared(smem_dst)),
                    "l"(gsrc));
}
#define CP_COMMIT() asm volatile("cp.async.commit_group;")
#define CP_WAIT1()  asm volatile("cp.async.wait_group 1;")

__device__ __forceinline__ uint32_t pack_h2(float lo, float hi) {
    __half2 h = __float22half2_rn(make_float2(lo, hi));
    return *(uint32_t*)&h;
}

// ---------------------------------------------------------------------------
// prehalf: dst[i] = half(src[i]) — one-time rounding point.
// ---------------------------------------------------------------------------
__global__ __launch_bounds__(256) void prehalf(const float* __restrict__ src,
                                               __half* __restrict__ dst, int n)
{
    int i = (blockIdx.x * 256 + threadIdx.x) * 8;
    if (i >= n) return;
    float4 v0 = *(const float4*)(src + i);
    float4 v1 = *(const float4*)(src + i + 4);
    uint4 t;
    t.x = pack_h2(v0.x, v0.y);
    t.y = pack_h2(v0.z, v0.w);
    t.z = pack_h2(v1.x, v1.y);
    t.w = pack_h2(v1.z, v1.w);
    *(uint4*)(dst + i) = t;
}

// ---------------------------------------------------------------------------
// fp16 GEMM: C[M,N] = A[M,K] @ W[N,K]^T + bias[N], optional scale + half out.
// Block tile 128x128, k-chunk 32 (2 k-steps of m16n8k16), 256 threads,
// 2-stage cp.async pipeline. A,W half; acc fp32.
// Smem rows padded to 40 halves (20 words): gid*20 mod 32 spans all banks.
// ---------------------------------------------------------------------------
#define GPH 40
#define GA_STRIDE (128 * GPH)    // halves per stage per matrix

template <bool HALF_OUT>
__device__ __forceinline__ void gemm_f16_core(
    const __half* __restrict__ A, const __half* __restrict__ W,
    const float* __restrict__ bias, void* __restrict__ Cout,
    int M, int N, int K, float scale)
{
    extern __shared__ __half gsm[];
    __half* Aa = gsm;                       // [2][128][GPH]
    __half* Ww = gsm + 2 * GA_STRIDE;       // [2][128][GPH]

    const int tid  = threadIdx.x;
    const int warp = tid >> 5;
    const int lane = tid & 31;
    const int wm   = warp >> 2;
    const int wn   = warp & 3;
    const int gid  = lane >> 2;
    const int tig  = lane & 3;
    const int m0   = blockIdx.y * 128;
    const int n0   = blockIdx.x * 128;

    float acc[4][4][4];
    #pragma unroll
    for (int mt = 0; mt < 4; mt++)
        #pragma unroll
        for (int nt = 0; nt < 4; nt++)
            #pragma unroll
            for (int i = 0; i < 4; i++)
                acc[mt][nt][i] = 0.0f;

    const int nchunk = K >> 5;

    auto stage = [&](int ck, int buf) {
        int k0 = ck * 32;
        #pragma unroll
        for (int it = 0; it < 2; it++) {
            int slot = tid + it * 256;       // 0..511
            int r    = slot >> 2;            // 0..127
            int c8   = (slot & 3) * 8;       // 0,8,16,24 halves
            cp16(&Aa[buf * GA_STRIDE + r * GPH + c8],
                 A + (size_t)(m0 + r) * K + k0 + c8);
            cp16(&Ww[buf * GA_STRIDE + r * GPH + c8],
                 W + (size_t)(n0 + r) * K + k0 + c8);
        }
    };

    stage(0, 0);
    CP_COMMIT();

    for (int ck = 0; ck < nchunk; ck++) {
        int cur = ck & 1;
        if (ck + 1 < nchunk) stage(ck + 1, cur ^ 1);
        CP_COMMIT();
        CP_WAIT1();
        __syncthreads();

        const uint32_t* Af = (const uint32_t*)(Aa + cur * GA_STRIDE);
        const uint32_t* Wf = (const uint32_t*)(Ww + cur * GA_STRIDE);
        #pragma unroll
        for (int ks = 0; ks < 2; ks++) {      // two k16 steps per chunk
            int ksw = ks * 8;                 // word offset of k-step
            uint32_t a[4][4], b[4][2];
            #pragma unroll
            for (int mt = 0; mt < 4; mt++) {
                int r = wm * 64 + mt * 16 + gid;
                a[mt][0] = Af[r * 20 + ksw + tig];
                a[mt][1] = Af[(r + 8) * 20 + ksw + tig];
                a[mt][2] = Af[r * 20 + ksw + tig + 4];
                a[mt][3] = Af[(r + 8) * 20 + ksw + tig + 4];
            }
            #pragma unroll
            for (int nt = 0; nt < 4; nt++) {
                int cn = wn * 32 + nt * 8 + gid;
                b[nt][0] = Wf[cn * 20 + ksw + tig];
                b[nt][1] = Wf[cn * 20 + ksw + tig + 4];
            }
            #pragma unroll
            for (int mt = 0; mt < 4; mt++)
                #pragma unroll
                for (int nt = 0; nt < 4; nt++)
                    mma_f16(acc[mt][nt], a[mt], b[nt]);
        }
        __syncthreads();
    }

    #pragma unroll
    for (int mt = 0; mt < 4; mt++) {
        int r0 = m0 + wm * 64 + mt * 16 + gid;
        #pragma unroll
        for (int nt = 0; nt < 4; nt++) {
            int c = n0 + wn * 32 + nt * 8 + tig * 2;
            float bx = bias[c], by = bias[c + 1];
            float r00 = (acc[mt][nt][0] + bx) * scale;
            float r01 = (acc[mt][nt][1] + by) * scale;
            float r10 = (acc[mt][nt][2] + bx) * scale;
            float r11 = (acc[mt][nt][3] + by) * scale;
            if (HALF_OUT) {
                __half* C = (__half*)Cout;
                *(uint32_t*)(C + (size_t)r0 * N + c)       = pack_h2(r00, r01);
                *(uint32_t*)(C + (size_t)(r0 + 8) * N + c) = pack_h2(r10, r11);
            } else {
                float* C = (float*)Cout;
                float2 v0 = { r00, r01 };
                float2 v1 = { r10, r11 };
                *(float2*)(C + (size_t)r0 * N + c) = v0;
                *(float2*)(C + (size_t)(r0 + 8) * N + c) = v1;
            }
        }
    }
}

#define GEMM_SMEM (4 * GA_STRIDE * (int)sizeof(__half))   // 40960 B

__global__ __launch_bounds__(256, 2) void gemm_qkv(
    const __half* __restrict__ xq, const __half* __restrict__ xk,
    const __half* __restrict__ xv, const __half* __restrict__ w3,
    const float* __restrict__ bq, const float* __restrict__ bk,
    const float* __restrict__ bv,
    __half* __restrict__ Q, __half* __restrict__ K, __half* __restrict__ V,
    int M, int N, int Kd)
{
    const __half *A, *W;
    const float* bias;
    __half* C;
    float scale;
    if (blockIdx.z == 0) {
        A = xq; W = w3;                bias = bq; C = Q; scale = 0.125f;
    } else if (blockIdx.z == 1) {
        A = xk; W = w3 + DDM * DDM;     bias = bk; C = K; scale = 1.0f;
    } else {
        A = xv; W = w3 + 2 * DDM * DDM; bias = bv; C = V; scale = 1.0f;
    }
    gemm_f16_core<true>(A, W, bias, C, M, N, Kd, scale);
}

__global__ __launch_bounds__(256, 2) void gemm_out(
    const __half* __restrict__ A, const __half* __restrict__ W,
    const float* __restrict__ bias, float* __restrict__ C,
    int M, int N, int Kd)
{
    gemm_f16_core<false>(A, W, bias, C, M, N, Kd, 1.0f);
}

// ---------------------------------------------------------------------------
// Flash attention, fp16 m16n8k16, 32 query rows per warp (2 m-tiles).
// CTA = 256 query rows, 256 threads (8 warps). Bk = 64, dk = 64.
// Q pre-scaled by 1/8 at projection. K,V staged natural [key][d] half,
// rows padded to 72 halves (36 words) -> conflict-free fragment loads.
// P: fp16 QK accumulator pairs ARE the PV A-operand registers (no relayout).
// racing_bias cancels in softmax -> skipped.
// ---------------------------------------------------------------------------
#define KPH 72
#define TSTR (64 * KPH)            // halves per K (or V) tile
#define STG  (2 * TSTR)            // halves per stage (K + V)
#define FLASH_SMEM (3 * STG * (int)sizeof(__half))   // 55296 B

__global__ __launch_bounds__(256, 1) void flash_f16(
    const __half* __restrict__ Q, const __half* __restrict__ K,
    const __half* __restrict__ V, __half* __restrict__ O)
{
    extern __shared__ __half fsm[];

    const int tid  = threadIdx.x;
    const int warp = tid >> 5;
    const int lane = tid & 31;
    const int gid  = lane >> 2;
    const int tig  = lane & 3;
    const int b    = blockIdx.y / HH;
    const int h    = blockIdx.y % HH;
    const int q0   = blockIdx.x * 256;

    const __half* Qb = Q + ((size_t)(b * SSQ + q0 + warp * 32)) * DDM + h * DKK;
    const __half* Kb = K + ((size_t)(b * SSQ)) * DDM + h * DKK;
    const __half* Vb = V + ((size_t)(b * SSQ)) * DDM + h * DKK;

    // Q fragments (half, pre-scaled): 4 k-chunks of 16, 4 regs each.
    uint32_t qf[2][4][4];
    #pragma unroll
    for (int mt = 0; mt < 2; mt++) {
        const uint32_t* Qr0 = (const uint32_t*)(Qb + (size_t)(mt * 16 + gid) * DDM);
        const uint32_t* Qr1 = (const uint32_t*)(Qb + (size_t)(mt * 16 + gid + 8) * DDM);
        #pragma unroll
        for (int c = 0; c < 4; c++) {
            qf[mt][c][0] = Qr0[c * 8 + tig];
            qf[mt][c][1] = Qr1[c * 8 + tig];
            qf[mt][c][2] = Qr0[c * 8 + tig + 4];
            qf[mt][c][3] = Qr1[c * 8 + tig + 4];
        }
    }

    float mrow[2][2], lrow[2][2];
    float o[2][8][4];
    #pragma unroll
    for (int mt = 0; mt < 2; mt++) {
        mrow[mt][0] = -1e30f; mrow[mt][1] = -1e30f;
        lrow[mt][0] = 0.0f;   lrow[mt][1] = 0.0f;
        #pragma unroll
        for (int nt = 0; nt < 8; nt++)
            #pragma unroll
            for (int i = 0; i < 4; i++) o[mt][nt][i] = 0.0f;
    }

    auto stage = [&](int ck, int buf) {
        const __half* Kg = Kb + (size_t)(ck * 64) * DDM;
        const __half* Vg = Vb + (size_t)(ck * 64) * DDM;
        __half* Kd = fsm + buf * STG;
        __half* Vd = fsm + buf * STG + TSTR;
        #pragma unroll
        for (int it = 0; it < 2; it++) {
            int seg = tid + it * 256;        // 0..511
            int r   = seg >> 3;              // key 0..63
            int c8  = (seg & 7) * 8;         // d 0..56 halves
            cp16(&Kd[r * KPH + c8], Kg + (size_t)r * DDM + c8);
            cp16(&Vd[r * KPH + c8], Vg + (size_t)r * DDM + c8);
        }
    };

    stage(0, 0); CP_COMMIT();
    stage(1, 1); CP_COMMIT();

    const int niter = SSQ / 64;   // 32
    for (int ck = 0; ck < niter; ck++) {
        int cur = ck % 3;
        CP_WAIT1();
        __syncthreads();
        if (ck + 2 < niter) stage(ck + 2, (ck + 2) % 3);
        CP_COMMIT();

        const uint32_t* Kw = (const uint32_t*)(fsm + cur * STG);
        const __half*   Vh = fsm + cur * STG + TSTR;

        // S = (Q/8) @ K^T : 4 k16-steps x 8 n-tiles, both m-tiles.
        float s[2][8][4];
        #pragma unroll
        for (int mt = 0; mt < 2; mt++)
            #pragma unroll
            for (int nt = 0; nt < 8; nt++)
                #pragma unroll
                for (int i = 0; i < 4; i++) s[mt][nt][i] = 0.0f;

        #pragma unroll
        for (int c = 0; c < 4; c++) {
            #pragma unroll
            for (int nt = 0; nt < 8; nt++) {
                uint32_t bf[2];
                bf[0] = Kw[(nt * 8 + gid) * 36 + c * 8 + tig];
                bf[1] = Kw[(nt * 8 + gid) * 36 + c * 8 + tig + 4];
                mma_f16(s[0][nt], qf[0][c], bf);
                mma_f16(s[1][nt], qf[1][c], bf);
            }
        }

        // Online softmax; P stored as packed half2 (exact PV A-operands).
        uint32_t sh[2][8][2];
        #pragma unroll
        for (int mt = 0; mt < 2; mt++) {
            float mx0 = -1e30f, mx1 = -1e30f;
            #pragma unroll
            for (int nt = 0; nt < 8; nt++) {
                mx0 = fmaxf(mx0, fmaxf(s[mt][nt][0], s[mt][nt][1]));
                mx1 = fmaxf(mx1, fmaxf(s[mt][nt][2], s[mt][nt][3]));
            }
            mx0 = fmaxf(mx0, __shfl_xor_sync(0xffffffffu, mx0, 1));
            mx0 = fmaxf(mx0, __shfl_xor_sync(0xffffffffu, mx0, 2));
            mx1 = fmaxf(mx1, __shfl_xor_sync(0xffffffffu, mx1, 1));
            mx1 = fmaxf(mx1, __shfl_xor_sync(0xffffffffu, mx1, 2));

            float nm0 = fmaxf(mrow[mt][0], mx0);
            float nm1 = fmaxf(mrow[mt][1], mx1);
            float cr0 = __expf(mrow[mt][0] - nm0);
            float cr1 = __expf(mrow[mt][1] - nm1);
            float rs0 = 0.0f, rs1 = 0.0f;

            #pragma unroll
            for (int nt = 0; nt < 8; nt++) {
                float e0 = __expf(s[mt][nt][0] - nm0);
                float e1 = __expf(s[mt][nt][1] - nm0);
                float e2 = __expf(s[mt][nt][2] - nm1);
                float e3 = __expf(s[mt][nt][3] - nm1);
                __half2 h01 = __float22half2_rn(make_float2(e0, e1));
                __half2 h23 = __float22half2_rn(make_float2(e2, e3));
                sh[mt][nt][0] = *(uint32_t*)&h01;
                sh[mt][nt][1] = *(uint32_t*)&h23;
                // accumulate the exact half-rounded values used by PV
                float2 f01 = __half22float2(h01);
                float2 f23 = __half22float2(h23);
                rs0 += f01.x + f01.y;
                rs1 += f23.x + f23.y;
            }
            rs0 += __shfl_xor_sync(0xffffffffu, rs0, 1);
            rs0 += __shfl_xor_sync(0xffffffffu, rs0, 2);
            rs1 += __shfl_xor_sync(0xffffffffu, rs1, 1);
            rs1 += __shfl_xor_sync(0xffffffffu, rs1, 2);

            lrow[mt][0] = lrow[mt][0] * cr0 + rs0;  mrow[mt][0] = nm0;
            lrow[mt][1] = lrow[mt][1] * cr1 + rs1;  mrow[mt][1] = nm1;
            #pragma unroll
            for (int nt = 0; nt < 8; nt++) {
                o[mt][nt][0] *= cr0; o[mt][nt][1] *= cr0;
                o[mt][nt][2] *= cr1; o[mt][nt][3] *= cr1;
            }
        }

        // O += P @ V : 4 k16-chunks (keys) x 8 n-tiles (dk).
        #pragma unroll
        for (int j = 0; j < 4; j++) {
            uint32_t af[2][4];
            #pragma unroll
            for (int mt = 0; mt < 2; mt++) {
                af[mt][0] = sh[mt][2 * j][0];
                af[mt][1] = sh[mt][2 * j][1];
                af[mt][2] = sh[mt][2 * j + 1][0];
                af[mt][3] = sh[mt][2 * j + 1][1];
            }
            const int k0 = 16 * j + 2 * tig;
            #pragma unroll
            for (int nt = 0; nt < 8; nt++) {
                int col = nt * 8 + gid;
                uint32_t bf[2];
                __half2 b0 = __halves2half2(Vh[(k0)     * KPH + col],
                                            Vh[(k0 + 1) * KPH + col]);
                __half2 b1 = __halves2half2(Vh[(k0 + 8) * KPH + col],
                                            Vh[(k0 + 9) * KPH + col]);
                bf[0] = *(uint32_t*)&b0;
                bf[1] = *(uint32_t*)&b1;
                mma_f16(o[0][nt], af[0], bf);
                mma_f16(o[1][nt], af[1], bf);
            }
        }
    }

    // Epilogue: normalize, round to half (O-proj consumes half), store.
    #pragma unroll
    for (int mt = 0; mt < 2; mt++) {
        float il0 = 1.0f / lrow[mt][0], il1 = 1.0f / lrow[mt][1];
        __half* Ob = O + ((size_t)(b * SSQ + q0 + warp * 32 + mt * 16)) * DDM
                       + h * DKK;
        #pragma unroll
        for (int nt = 0; nt < 8; nt++) {
            int c = nt * 8 + tig * 2;
            *(uint32_t*)(Ob + (size_t)gid * DDM + c) =
                pack_h2(o[mt][nt][0] * il0, o[mt][nt][1] * il0);
            *(uint32_t*)(Ob + (size_t)(gid + 8) * DDM + c) =
                pack_h2(o[mt][nt][2] * il1, o[mt][nt][3] * il1);
        }
    }
}

// ---------------------------------------------------------------------------
extern "C" void kernel_launch(void* const* d_in, const int* in_sizes, int n_in,
                              void* d_out, int out_size)
{
    (void)in_sizes; (void)n_in; (void)out_size;
    const float* query = (const float*)d_in[0];
    const float* key_  = (const float*)d_in[1];
    const float* value = (const float*)d_in[2];
    const float* wq = (const float*)d_in[3];
    const float* bq = (const float*)d_in[4];
    const float* wk = (const float*)d_in[5];
    const float* bk = (const float*)d_in[6];
    const float* wv = (const float*)d_in[7];
    const float* bv = (const float*)d_in[8];
    const float* wo = (const float*)d_in[9];
    const float* bo = (const float*)d_in[10];
    // d_in[11] = racing_bias: constant over softmax axis -> cancels exactly.
    float* out = (float*)d_out;

    __half *Qp, *Kp, *Vp, *Cp, *Xq, *Xk, *Xv, *Wr;
    cudaGetSymbolAddress((void**)&Qp, g_Q);
    cudaGetSymbolAddress((void**)&Kp, g_K);
    cudaGetSymbolAddress((void**)&Vp, g_V);
    cudaGetSymbolAddress((void**)&Cp, g_C);
    cudaGetSymbolAddress((void**)&Xq, g_Xq);
    cudaGetSymbolAddress((void**)&Xk, g_Xk);
    cudaGetSymbolAddress((void**)&Xv, g_Xv);
    cudaGetSymbolAddress((void**)&Wr, g_Wr);

    const int M = BB * SSQ;
    const int N = DDM;
    const int Kdim = DDM;

    cudaFuncSetAttribute(flash_f16,
        cudaFuncAttributeMaxDynamicSharedMemorySize, FLASH_SMEM);

    // Convert inputs + weights to half (one-time rounding point).
    const int nIn = M * DDM;            // 4,194,304
    const int nW  = DDM * DDM;          // 1,048,576
    prehalf<<<nIn / 2048, 256>>>(query, Xq, nIn);
    prehalf<<<nIn / 2048, 256>>>(key_,  Xk, nIn);
    prehalf<<<nIn / 2048, 256>>>(value, Xv, nIn);
    prehalf<<<nW / 2048, 256>>>(wq, Wr,          nW);
    prehalf<<<nW / 2048, 256>>>(wk, Wr + nW,     nW);
    prehalf<<<nW / 2048, 256>>>(wv, Wr + 2 * nW, nW);
    prehalf<<<nW / 2048, 256>>>(wo, Wr + 3 * nW, nW);

    // Fused Q/K/V projections (fp16 tensor cores, cp.async pipelined).
    dim3 qkvGrid(N / 128, M / 128, 3);
    gemm_qkv<<<qkvGrid, 256, GEMM_SMEM>>>(Xq, Xk, Xv, Wr, bq, bk, bv,
                                          Qp, Kp, Vp, M, N, Kdim);

    // Flash attention (fp16 mma, zero-cost P relayout, 3-stage cp.async).
    dim3 fGrid(SSQ / 256, BB * HH);   // (8, 32) = 256 CTAs
    flash_f16<<<fGrid, 256, FLASH_SMEM>>>(Qp, Kp, Vp, Cp);

    // Output projection (fp16 in, fp32 out).
    dim3 oGrid(N / 128, M / 128, 1);
    gemm_out<<<oGrid, 256, GEMM_SMEM>>>(Cp, Wr + 3 * nW, bo, out,
                                        M, N, Kdim);
}

// round 9
// speedup vs baseline: 7.3103x; 1.2655x over previous
#include <cuda_runtime.h>
#include <cuda_fp16.h>
#include <cstdint>

// Problem constants
#define BB   2
#define SSQ  2048
#define DDM  1024
#define HH   16
#define DKK  64

// Scratch (no allocation allowed -> device globals).
__device__ __half g_Q[BB * SSQ * DDM];       // pre-scaled by 1/8
__device__ __half g_K[BB * SSQ * DDM];
__device__ __half g_V[BB * SSQ * DDM];
__device__ __half g_C[BB * SSQ * DDM];       // ctx
__device__ __half g_Xq[BB * SSQ * DDM];      // half inputs
__device__ __half g_Xk[BB * SSQ * DDM];
__device__ __half g_Xv[BB * SSQ * DDM];
__device__ __half g_Wr[4 * DDM * DDM];       // wq | wk | wv | wo (half)

// ---------------------------------------------------------------------------
// helpers
// ---------------------------------------------------------------------------
__device__ __forceinline__ void mma_f16(float d[4], const uint32_t a[4],
                                        const uint32_t b[2]) {
    asm volatile(
        "mma.sync.aligned.m16n8k16.row.col.f32.f16.f16.f32 "
        "{%0,%1,%2,%3}, {%4,%5,%6,%7}, {%8,%9}, {%0,%1,%2,%3};"
        : "+f"(d[0]), "+f"(d[1]), "+f"(d[2]), "+f"(d[3])
        : "r"(a[0]), "r"(a[1]), "r"(a[2]), "r"(a[3]), "r"(b[0]), "r"(b[1]));
}

__device__ __forceinline__ void ldmx4(uint32_t& r0, uint32_t& r1,
                                      uint32_t& r2, uint32_t& r3,
                                      const void* p) {
    uint32_t a = (uint32_t)__cvta_generic_to_shared(p);
    asm volatile("ldmatrix.sync.aligned.m8n8.x4.shared.b16 {%0,%1,%2,%3}, [%4];"
                 : "=r"(r0), "=r"(r1), "=r"(r2), "=r"(r3) : "r"(a));
}

__device__ __forceinline__ void ldmx4t(uint32_t& r0, uint32_t& r1,
                                       uint32_t& r2, uint32_t& r3,
                                       const void* p) {
    uint32_t a = (uint32_t)__cvta_generic_to_shared(p);
    asm volatile("ldmatrix.sync.aligned.m8n8.x4.trans.shared.b16 {%0,%1,%2,%3}, [%4];"
                 : "=r"(r0), "=r"(r1), "=r"(r2), "=r"(r3) : "r"(a));
}

__device__ __forceinline__ void cp16(void* smem_dst, const void* gsrc) {
    asm volatile("cp.async.ca.shared.global [%0], [%1], 16;"
                 :: "r"((uint32_t)__cvta_generic_to_shared(smem_dst)),
                    "l"(gsrc));
}
#define CP_COMMIT() asm volatile("cp.async.commit_group;")
#define CP_WAIT1()  asm volatile("cp.async.wait_group 1;")

__device__ __forceinline__ uint32_t pack_h2(float lo, float hi) {
    __half2 h = __float22half2_rn(make_float2(lo, hi));
    return *(uint32_t*)&h;
}

// ---------------------------------------------------------------------------
// prehalf (z-indexed, 2 launches total): dst[i] = half(src[i]).
// ---------------------------------------------------------------------------
__global__ __launch_bounds__(256) void prehalf3(
    const float* __restrict__ s0, const float* __restrict__ s1,
    const float* __restrict__ s2,
    __half* __restrict__ d0, __half* __restrict__ d1, __half* __restrict__ d2,
    int n)
{
    const float* s; __half* d;
    if (blockIdx.z == 0)      { s = s0; d = d0; }
    else if (blockIdx.z == 1) { s = s1; d = d1; }
    else                      { s = s2; d = d2; }
    int i = (blockIdx.x * 256 + threadIdx.x) * 8;
    if (i >= n) return;
    float4 v0 = *(const float4*)(s + i);
    float4 v1 = *(const float4*)(s + i + 4);
    uint4 t = { pack_h2(v0.x, v0.y), pack_h2(v0.z, v0.w),
                pack_h2(v1.x, v1.y), pack_h2(v1.z, v1.w) };
    *(uint4*)(d + i) = t;
}

__global__ __launch_bounds__(256) void prehalf4(
    const float* __restrict__ s0, const float* __restrict__ s1,
    const float* __restrict__ s2, const float* __restrict__ s3,
    __half* __restrict__ dst, int n)
{
    const float* s;
    if (blockIdx.z == 0)      s = s0;
    else if (blockIdx.z == 1) s = s1;
    else if (blockIdx.z == 2) s = s2;
    else                      s = s3;
    __half* d = dst + (size_t)blockIdx.z * n;
    int i = (blockIdx.x * 256 + threadIdx.x) * 8;
    if (i >= n) return;
    float4 v0 = *(const float4*)(s + i);
    float4 v1 = *(const float4*)(s + i + 4);
    uint4 t = { pack_h2(v0.x, v0.y), pack_h2(v0.z, v0.w),
                pack_h2(v1.x, v1.y), pack_h2(v1.z, v1.w) };
    *(uint4*)(d + i) = t;
}

// ---------------------------------------------------------------------------
// fp16 GEMM: C[M,N] = A[M,K] @ W[N,K]^T + bias[N], optional scale + half out.
// Block tile 128x128, k-chunk 64 (4 k16 steps), 256 threads, 2-stage
// cp.async pipeline, ldmatrix fragment loads. Rows padded to 72 halves
// (144 B stride -> ldmatrix phase-conflict-free).
// ---------------------------------------------------------------------------
#define GPH 72
#define GA_STRIDE (128 * GPH)    // halves per stage per matrix

template <bool HALF_OUT>
__device__ __forceinline__ void gemm_f16_core(
    const __half* __restrict__ A, const __half* __restrict__ W,
    const float* __restrict__ bias, void* __restrict__ Cout,
    int M, int N, int K, float scale)
{
    extern __shared__ __half gsm[];
    __half* Aa = gsm;                       // [2][128][GPH]
    __half* Ww = gsm + 2 * GA_STRIDE;       // [2][128][GPH]

    const int tid  = threadIdx.x;
    const int warp = tid >> 5;
    const int lane = tid & 31;
    const int wm   = warp >> 2;
    const int wn   = warp & 3;
    const int gid  = lane >> 2;
    const int tig  = lane & 3;
    const int m0   = blockIdx.y * 128;
    const int n0   = blockIdx.x * 128;

    // ldmatrix per-lane offsets
    const int aRow = (lane & 15);
    const int aCol = (lane >> 4) * 8;
    const int bRow = (lane & 7) + ((lane >> 4) & 1) * 8;
    const int bCol = ((lane >> 3) & 1) * 8;

    float acc[4][4][4];
    #pragma unroll
    for (int mt = 0; mt < 4; mt++)
        #pragma unroll
        for (int nt = 0; nt < 4; nt++)
            #pragma unroll
            for (int i = 0; i < 4; i++)
                acc[mt][nt][i] = 0.0f;

    const int nchunk = K >> 6;   // 16

    auto stage = [&](int ck, int buf) {
        int k0 = ck * 64;
        #pragma unroll
        for (int it = 0; it < 4; it++) {
            int slot = tid + it * 256;       // 0..1023
            int r    = slot >> 3;            // 0..127
            int c8   = (slot & 7) * 8;       // 0..56 halves
            cp16(&Aa[buf * GA_STRIDE + r * GPH + c8],
                 A + (size_t)(m0 + r) * K + k0 + c8);
            cp16(&Ww[buf * GA_STRIDE + r * GPH + c8],
                 W + (size_t)(n0 + r) * K + k0 + c8);
        }
    };

    stage(0, 0);
    CP_COMMIT();

    for (int ck = 0; ck < nchunk; ck++) {
        int cur = ck & 1;
        if (ck + 1 < nchunk) stage(ck + 1, cur ^ 1);
        CP_COMMIT();
        CP_WAIT1();
        __syncthreads();

        const __half* Af = Aa + cur * GA_STRIDE;
        const __half* Wf = Ww + cur * GA_STRIDE;
        #pragma unroll
        for (int ks = 0; ks < 4; ks++) {
            uint32_t a[4][4], b[4][2];
            #pragma unroll
            for (int mt = 0; mt < 4; mt++)
                ldmx4(a[mt][0], a[mt][1], a[mt][2], a[mt][3],
                      &Af[(wm * 64 + mt * 16 + aRow) * GPH + ks * 16 + aCol]);
            #pragma unroll
            for (int pr = 0; pr < 2; pr++)
                ldmx4(b[pr * 2][0], b[pr * 2][1], b[pr * 2 + 1][0], b[pr * 2 + 1][1],
                      &Wf[(wn * 32 + pr * 16 + bRow) * GPH + ks * 16 + bCol]);
            #pragma unroll
            for (int mt = 0; mt < 4; mt++)
                #pragma unroll
                for (int nt = 0; nt < 4; nt++)
                    mma_f16(acc[mt][nt], a[mt], b[nt]);
        }
        __syncthreads();
    }

    #pragma unroll
    for (int mt = 0; mt < 4; mt++) {
        int r0 = m0 + wm * 64 + mt * 16 + gid;
        #pragma unroll
        for (int nt = 0; nt < 4; nt++) {
            int c = n0 + wn * 32 + nt * 8 + tig * 2;
            float bx = bias[c], by = bias[c + 1];
            float r00 = (acc[mt][nt][0] + bx) * scale;
            float r01 = (acc[mt][nt][1] + by) * scale;
            float r10 = (acc[mt][nt][2] + bx) * scale;
            float r11 = (acc[mt][nt][3] + by) * scale;
            if (HALF_OUT) {
                __half* C = (__half*)Cout;
                *(uint32_t*)(C + (size_t)r0 * N + c)       = pack_h2(r00, r01);
                *(uint32_t*)(C + (size_t)(r0 + 8) * N + c) = pack_h2(r10, r11);
            } else {
                float* C = (float*)Cout;
                float2 v0 = { r00, r01 };
                float2 v1 = { r10, r11 };
                *(float2*)(C + (size_t)r0 * N + c) = v0;
                *(float2*)(C + (size_t)(r0 + 8) * N + c) = v1;
            }
        }
    }
}

#define GEMM_SMEM (4 * GA_STRIDE * (int)sizeof(__half))   // 73728 B

__global__ __launch_bounds__(256, 2) void gemm_qkv(
    const __half* __restrict__ xq, const __half* __restrict__ xk,
    const __half* __restrict__ xv, const __half* __restrict__ w3,
    const float* __restrict__ bq, const float* __restrict__ bk,
    const float* __restrict__ bv,
    __half* __restrict__ Q, __half* __restrict__ K, __half* __restrict__ V,
    int M, int N, int Kd)
{
    const __half *A, *W;
    const float* bias;
    __half* C;
    float scale;
    if (blockIdx.z == 0) {
        A = xq; W = w3;                bias = bq; C = Q; scale = 0.125f;
    } else if (blockIdx.z == 1) {
        A = xk; W = w3 + DDM * DDM;     bias = bk; C = K; scale = 1.0f;
    } else {
        A = xv; W = w3 + 2 * DDM * DDM; bias = bv; C = V; scale = 1.0f;
    }
    gemm_f16_core<true>(A, W, bias, C, M, N, Kd, scale);
}

__global__ __launch_bounds__(256, 2) void gemm_out(
    const __half* __restrict__ A, const __half* __restrict__ W,
    const float* __restrict__ bias, float* __restrict__ C,
    int M, int N, int Kd)
{
    gemm_f16_core<false>(A, W, bias, C, M, N, Kd, 1.0f);
}

// ---------------------------------------------------------------------------
// Flash attention, fp16 m16n8k16, 32 query rows per warp (2 m-tiles).
// CTA = 256 query rows, 256 threads. Bk = 64, dk = 64.
// K,V staged natural [key][d], rows padded to 72 halves.
// K b-frags via ldmatrix.x4; V b-frags via ldmatrix.x4.trans.
// P: fp16 QK accumulator pairs ARE the PV A-operands. racing_bias cancels.
// ---------------------------------------------------------------------------
#define KPH 72
#define TSTR (64 * KPH)
#define STG  (2 * TSTR)
#define FLASH_SMEM (3 * STG * (int)sizeof(__half))   // 55296 B

__global__ __launch_bounds__(256, 1) void flash_f16(
    const __half* __restrict__ Q, const __half* __restrict__ K,
    const __half* __restrict__ V, __half* __restrict__ O)
{
    extern __shared__ __half fsm[];

    const int tid  = threadIdx.x;
    const int warp = tid >> 5;
    const int lane = tid & 31;
    const int gid  = lane >> 2;
    const int tig  = lane & 3;
    const int b    = blockIdx.y / HH;
    const int h    = blockIdx.y % HH;
    const int q0   = blockIdx.x * 256;

    // ldmatrix per-lane offsets
    const int bRow = (lane & 7) + ((lane >> 4) & 1) * 8;   // K (non-trans)
    const int bCol = ((lane >> 3) & 1) * 8;
    const int vKey = (lane & 7) + ((lane >> 3) & 1) * 8;   // V (trans)
    const int vCol = ((lane >> 4) & 1) * 8;

    const __half* Qb = Q + ((size_t)(b * SSQ + q0 + warp * 32)) * DDM + h * DKK;
    const __half* Kb = K + ((size_t)(b * SSQ)) * DDM + h * DKK;
    const __half* Vb = V + ((size_t)(b * SSQ)) * DDM + h * DKK;

    // Q fragments (half, pre-scaled): 4 k16-chunks, 4 regs each.
    uint32_t qf[2][4][4];
    #pragma unroll
    for (int mt = 0; mt < 2; mt++) {
        const uint32_t* Qr0 = (const uint32_t*)(Qb + (size_t)(mt * 16 + gid) * DDM);
        const uint32_t* Qr1 = (const uint32_t*)(Qb + (size_t)(mt * 16 + gid + 8) * DDM);
        #pragma unroll
        for (int c = 0; c < 4; c++) {
            qf[mt][c][0] = Qr0[c * 8 + tig];
            qf[mt][c][1] = Qr1[c * 8 + tig];
            qf[mt][c][2] = Qr0[c * 8 + tig + 4];
            qf[mt][c][3] = Qr1[c * 8 + tig + 4];
        }
    }

    float mrow[2][2], lrow[2][2];
    float o[2][8][4];
    #pragma unroll
    for (int mt = 0; mt < 2; mt++) {
        mrow[mt][0] = -1e30f; mrow[mt][1] = -1e30f;
        lrow[mt][0] = 0.0f;   lrow[mt][1] = 0.0f;
        #pragma unroll
        for (int nt = 0; nt < 8; nt++)
            #pragma unroll
            for (int i = 0; i < 4; i++) o[mt][nt][i] = 0.0f;
    }

    auto stage = [&](int ck, int buf) {
        const __half* Kg = Kb + (size_t)(ck * 64) * DDM;
        const __half* Vg = Vb + (size_t)(ck * 64) * DDM;
        __half* Kd = fsm + buf * STG;
        __half* Vd = fsm + buf * STG + TSTR;
        #pragma unroll
        for (int it = 0; it < 2; it++) {
            int seg = tid + it * 256;        // 0..511
            int r   = seg >> 3;              // key 0..63
            int c8  = (seg & 7) * 8;         // d 0..56 halves
            cp16(&Kd[r * KPH + c8], Kg + (size_t)r * DDM + c8);
            cp16(&Vd[r * KPH + c8], Vg + (size_t)r * DDM + c8);
        }
    };

    stage(0, 0); CP_COMMIT();
    stage(1, 1); CP_COMMIT();

    const int niter = SSQ / 64;   // 32
    for (int ck = 0; ck < niter; ck++) {
        int cur = ck % 3;
        CP_WAIT1();
        __syncthreads();
        if (ck + 2 < niter) stage(ck + 2, (ck + 2) % 3);
        CP_COMMIT();

        const __half* Kh = fsm + cur * STG;
        const __half* Vh = fsm + cur * STG + TSTR;

        // S = (Q/8) @ K^T : 4 k16-steps x 8 n-tiles, both m-tiles.
        float s[2][8][4];
        #pragma unroll
        for (int mt = 0; mt < 2; mt++)
            #pragma unroll
            for (int nt = 0; nt < 8; nt++)
                #pragma unroll
                for (int i = 0; i < 4; i++) s[mt][nt][i] = 0.0f;

        #pragma unroll
        for (int c = 0; c < 4; c++) {
            #pragma unroll
            for (int ntp = 0; ntp < 4; ntp++) {
                uint32_t b0[2], b1[2];
                ldmx4(b0[0], b0[1], b1[0], b1[1],
                      &Kh[(ntp * 16 + bRow) * KPH + c * 16 + bCol]);
                mma_f16(s[0][ntp * 2],     qf[0][c], b0);
                mma_f16(s[1][ntp * 2],     qf[1][c], b0);
                mma_f16(s[0][ntp * 2 + 1], qf[0][c], b1);
                mma_f16(s[1][ntp * 2 + 1], qf[1][c], b1);
            }
        }

        // Online softmax; P stored as packed half2 (exact PV A-operands).
        uint32_t sh[2][8][2];
        #pragma unroll
        for (int mt = 0; mt < 2; mt++) {
            float mx0 = -1e30f, mx1 = -1e30f;
            #pragma unroll
            for (int nt = 0; nt < 8; nt++) {
                mx0 = fmaxf(mx0, fmaxf(s[mt][nt][0], s[mt][nt][1]));
                mx1 = fmaxf(mx1, fmaxf(s[mt][nt][2], s[mt][nt][3]));
            }
            mx0 = fmaxf(mx0, __shfl_xor_sync(0xffffffffu, mx0, 1));
            mx0 = fmaxf(mx0, __shfl_xor_sync(0xffffffffu, mx0, 2));
            mx1 = fmaxf(mx1, __shfl_xor_sync(0xffffffffu, mx1, 1));
            mx1 = fmaxf(mx1, __shfl_xor_sync(0xffffffffu, mx1, 2));

            float nm0 = fmaxf(mrow[mt][0], mx0);
            float nm1 = fmaxf(mrow[mt][1], mx1);
            float cr0 = __expf(mrow[mt][0] - nm0);
            float cr1 = __expf(mrow[mt][1] - nm1);
            float rs0 = 0.0f, rs1 = 0.0f;

            #pragma unroll
            for (int nt = 0; nt < 8; nt++) {
                float e0 = __expf(s[mt][nt][0] - nm0);
                float e1 = __expf(s[mt][nt][1] - nm0);
                float e2 = __expf(s[mt][nt][2] - nm1);
                float e3 = __expf(s[mt][nt][3] - nm1);
                __half2 h01 = __float22half2_rn(make_float2(e0, e1));
                __half2 h23 = __float22half2_rn(make_float2(e2, e3));
                sh[mt][nt][0] = *(uint32_t*)&h01;
                sh[mt][nt][1] = *(uint32_t*)&h23;
                float2 f01 = __half22float2(h01);
                float2 f23 = __half22float2(h23);
                rs0 += f01.x + f01.y;
                rs1 += f23.x + f23.y;
            }
            rs0 += __shfl_xor_sync(0xffffffffu, rs0, 1);
            rs0 += __shfl_xor_sync(0xffffffffu, rs0, 2);
            rs1 += __shfl_xor_sync(0xffffffffu, rs1, 1);
            rs1 += __shfl_xor_sync(0xffffffffu, rs1, 2);

            lrow[mt][0] = lrow[mt][0] * cr0 + rs0;  mrow[mt][0] = nm0;
            lrow[mt][1] = lrow[mt][1] * cr1 + rs1;  mrow[mt][1] = nm1;
            #pragma unroll
            for (int nt = 0; nt < 8; nt++) {
                o[mt][nt][0] *= cr0; o[mt][nt][1] *= cr0;
                o[mt][nt][2] *= cr1; o[mt][nt][3] *= cr1;
            }
        }

        // O += P @ V : 4 k16-chunks (keys) x 8 n-tiles (dk), V via ldmatrix.trans
        #pragma unroll
        for (int j = 0; j < 4; j++) {
            uint32_t af[2][4];
            #pragma unroll
            for (int mt = 0; mt < 2; mt++) {
                af[mt][0] = sh[mt][2 * j][0];
                af[mt][1] = sh[mt][2 * j][1];
                af[mt][2] = sh[mt][2 * j + 1][0];
                af[mt][3] = sh[mt][2 * j + 1][1];
            }
            #pragma unroll
            for (int dtp = 0; dtp < 4; dtp++) {
                uint32_t b0[2], b1[2];
                ldmx4t(b0[0], b0[1], b1[0], b1[1],
                       &Vh[(j * 16 + vKey) * KPH + dtp * 16 + vCol]);
                mma_f16(o[0][dtp * 2],     af[0], b0);
                mma_f16(o[1][dtp * 2],     af[1], b0);
                mma_f16(o[0][dtp * 2 + 1], af[0], b1);
                mma_f16(o[1][dtp * 2 + 1], af[1], b1);
            }
        }
    }

    // Epilogue: normalize, round to half (O-proj consumes half), store.
    #pragma unroll
    for (int mt = 0; mt < 2; mt++) {
        float il0 = 1.0f / lrow[mt][0], il1 = 1.0f / lrow[mt][1];
        __half* Ob = O + ((size_t)(b * SSQ + q0 + warp * 32 + mt * 16)) * DDM
                       + h * DKK;
        #pragma unroll
        for (int nt = 0; nt < 8; nt++) {
            int c = nt * 8 + tig * 2;
            *(uint32_t*)(Ob + (size_t)gid * DDM + c) =
                pack_h2(o[mt][nt][0] * il0, o[mt][nt][1] * il0);
            *(uint32_t*)(Ob + (size_t)(gid + 8) * DDM + c) =
                pack_h2(o[mt][nt][2] * il1, o[mt][nt][3] * il1);
        }
    }
}

// ---------------------------------------------------------------------------
extern "C" void kernel_launch(void* const* d_in, const int* in_sizes, int n_in,
                              void* d_out, int out_size)
{
    (void)in_sizes; (void)n_in; (void)out_size;
    const float* query = (const float*)d_in[0];
    const float* key_  = (const float*)d_in[1];
    const float* value = (const float*)d_in[2];
    const float* wq = (const float*)d_in[3];
    const float* bq = (const float*)d_in[4];
    const float* wk = (const float*)d_in[5];
    const float* bk = (const float*)d_in[6];
    const float* wv = (const float*)d_in[7];
    const float* bv = (const float*)d_in[8];
    const float* wo = (const float*)d_in[9];
    const float* bo = (const float*)d_in[10];
    // d_in[11] = racing_bias: constant over softmax axis -> cancels exactly.
    float* out = (float*)d_out;

    __half *Qp, *Kp, *Vp, *Cp, *Xq, *Xk, *Xv, *Wr;
    cudaGetSymbolAddress((void**)&Qp, g_Q);
    cudaGetSymbolAddress((void**)&Kp, g_K);
    cudaGetSymbolAddress((void**)&Vp, g_V);
    cudaGetSymbolAddress((void**)&Cp, g_C);
    cudaGetSymbolAddress((void**)&Xq, g_Xq);
    cudaGetSymbolAddress((void**)&Xk, g_Xk);
    cudaGetSymbolAddress((void**)&Xv, g_Xv);
    cudaGetSymbolAddress((void**)&Wr, g_Wr);

    const int M = BB * SSQ;
    const int N = DDM;
    const int Kdim = DDM;

    cudaFuncSetAttribute(gemm_qkv,
        cudaFuncAttributeMaxDynamicSharedMemorySize, GEMM_SMEM);
    cudaFuncSetAttribute(gemm_out,
        cudaFuncAttributeMaxDynamicSharedMemorySize, GEMM_SMEM);
    cudaFuncSetAttribute(flash_f16,
        cudaFuncAttributeMaxDynamicSharedMemorySize, FLASH_SMEM);

    // Convert inputs + weights to half (one-time rounding point, 2 launches).
    const int nIn = M * DDM;            // 4,194,304
    const int nW  = DDM * DDM;          // 1,048,576
    {
        dim3 g3(nIn / 2048, 1, 3);
        prehalf3<<<g3, 256>>>(query, key_, value, Xq, Xk, Xv, nIn);
        dim3 g4(nW / 2048, 1, 4);
        prehalf4<<<g4, 256>>>(wq, wk, wv, wo, Wr, nW);
    }

    // Fused Q/K/V projections (fp16 tensor cores, ldmatrix, cp.async).
    dim3 qkvGrid(N / 128, M / 128, 3);
    gemm_qkv<<<qkvGrid, 256, GEMM_SMEM>>>(Xq, Xk, Xv, Wr, bq, bk, bv,
                                          Qp, Kp, Vp, M, N, Kdim);

    // Flash attention (fp16 mma, ldmatrix/ldmatrix.trans, 3-stage cp.async).
    dim3 fGrid(SSQ / 256, BB * HH);   // (8, 32) = 256 CTAs
    flash_f16<<<fGrid, 256, FLASH_SMEM>>>(Qp, Kp, Vp, Cp);

    // Output projection (fp16 in, fp32 out).
    dim3 oGrid(N / 128, M / 128, 1);
    gemm_out<<<oGrid, 256, GEMM_SMEM>>>(Cp, Wr + 3 * nW, bo, out,
                                        M, N, Kdim);
}

// round 10
// speedup vs baseline: 7.3810x; 1.0097x over previous
#include <cuda_runtime.h>
#include <cuda_fp16.h>
#include <cstdint>

// Problem constants
#define BB   2
#define SSQ  2048
#define DDM  1024
#define HH   16
#define DKK  64

// Scratch (no allocation allowed -> device globals).
__device__ __half g_Q[BB * SSQ * DDM];       // pre-scaled by 0.125*log2(e)
__device__ __half g_K[BB * SSQ * DDM];
__device__ __half g_V[BB * SSQ * DDM];
__device__ __half g_C[BB * SSQ * DDM];       // ctx
__device__ __half g_Xq[BB * SSQ * DDM];      // half inputs
__device__ __half g_Xk[BB * SSQ * DDM];
__device__ __half g_Xv[BB * SSQ * DDM];
__device__ __half g_Wr[4 * DDM * DDM];       // wq | wk | wv | wo (half)

#define QSCALE (0.125f * 1.4426950408889634f)   // 1/sqrt(dk) * log2(e)

// ---------------------------------------------------------------------------
// helpers
// ---------------------------------------------------------------------------
__device__ __forceinline__ void mma_f16(float d[4], const uint32_t a[4],
                                        const uint32_t b[2]) {
    asm volatile(
        "mma.sync.aligned.m16n8k16.row.col.f32.f16.f16.f32 "
        "{%0,%1,%2,%3}, {%4,%5,%6,%7}, {%8,%9}, {%0,%1,%2,%3};"
        : "+f"(d[0]), "+f"(d[1]), "+f"(d[2]), "+f"(d[3])
        : "r"(a[0]), "r"(a[1]), "r"(a[2]), "r"(a[3]), "r"(b[0]), "r"(b[1]));
}

__device__ __forceinline__ void ldmx4(uint32_t& r0, uint32_t& r1,
                                      uint32_t& r2, uint32_t& r3,
                                      const void* p) {
    uint32_t a = (uint32_t)__cvta_generic_to_shared(p);
    asm volatile("ldmatrix.sync.aligned.m8n8.x4.shared.b16 {%0,%1,%2,%3}, [%4];"
                 : "=r"(r0), "=r"(r1), "=r"(r2), "=r"(r3) : "r"(a));
}

__device__ __forceinline__ void ldmx4t(uint32_t& r0, uint32_t& r1,
                                       uint32_t& r2, uint32_t& r3,
                                       const void* p) {
    uint32_t a = (uint32_t)__cvta_generic_to_shared(p);
    asm volatile("ldmatrix.sync.aligned.m8n8.x4.trans.shared.b16 {%0,%1,%2,%3}, [%4];"
                 : "=r"(r0), "=r"(r1), "=r"(r2), "=r"(r3) : "r"(a));
}

__device__ __forceinline__ void cp16(void* smem_dst, const void* gsrc) {
    asm volatile("cp.async.ca.shared.global [%0], [%1], 16;"
                 :: "r"((uint32_t)__cvta_generic_to_shared(smem_dst)),
                    "l"(gsrc));
}
#define CP_COMMIT() asm volatile("cp.async.commit_group;")
#define CP_WAIT1()  asm volatile("cp.async.wait_group 1;")

__device__ __forceinline__ uint32_t pack_h2(float lo, float hi) {
    __half2 h = __float22half2_rn(make_float2(lo, hi));
    return *(uint32_t*)&h;
}

__device__ __forceinline__ float ex2(float x) {
    float y;
    asm("ex2.approx.f32 %0, %1;" : "=f"(y) : "f"(x));
    return y;
}

// ---------------------------------------------------------------------------
// prehalf (z-indexed, 2 launches total): dst[i] = half(src[i]).
// ---------------------------------------------------------------------------
__global__ __launch_bounds__(256) void prehalf3(
    const float* __restrict__ s0, const float* __restrict__ s1,
    const float* __restrict__ s2,
    __half* __restrict__ d0, __half* __restrict__ d1, __half* __restrict__ d2,
    int n)
{
    const float* s; __half* d;
    if (blockIdx.z == 0)      { s = s0; d = d0; }
    else if (blockIdx.z == 1) { s = s1; d = d1; }
    else                      { s = s2; d = d2; }
    int i = (blockIdx.x * 256 + threadIdx.x) * 8;
    if (i >= n) return;
    float4 v0 = *(const float4*)(s + i);
    float4 v1 = *(const float4*)(s + i + 4);
    uint4 t = { pack_h2(v0.x, v0.y), pack_h2(v0.z, v0.w),
                pack_h2(v1.x, v1.y), pack_h2(v1.z, v1.w) };
    *(uint4*)(d + i) = t;
}

__global__ __launch_bounds__(256) void prehalf4(
    const float* __restrict__ s0, const float* __restrict__ s1,
    const float* __restrict__ s2, const float* __restrict__ s3,
    __half* __restrict__ dst, int n)
{
    const float* s;
    if (blockIdx.z == 0)      s = s0;
    else if (blockIdx.z == 1) s = s1;
    else if (blockIdx.z == 2) s = s2;
    else                      s = s3;
    __half* d = dst + (size_t)blockIdx.z * n;
    int i = (blockIdx.x * 256 + threadIdx.x) * 8;
    if (i >= n) return;
    float4 v0 = *(const float4*)(s + i);
    float4 v1 = *(const float4*)(s + i + 4);
    uint4 t = { pack_h2(v0.x, v0.y), pack_h2(v0.z, v0.w),
                pack_h2(v1.x, v1.y), pack_h2(v1.z, v1.w) };
    *(uint4*)(d + i) = t;
}

// ---------------------------------------------------------------------------
// fp16 GEMM: C[M,N] = A[M,K] @ W[N,K]^T + bias[N], optional scale + half out.
// Block tile 128x128, k-chunk 64 (4 k16 steps), 256 threads, 2-stage
// cp.async pipeline, ldmatrix fragment loads. Rows padded to 72 halves.
// ---------------------------------------------------------------------------
#define GPH 72
#define GA_STRIDE (128 * GPH)

template <bool HALF_OUT>
__device__ __forceinline__ void gemm_f16_core(
    const __half* __restrict__ A, const __half* __restrict__ W,
    const float* __restrict__ bias, void* __restrict__ Cout,
    int M, int N, int K, float scale)
{
    extern __shared__ __half gsm[];
    __half* Aa = gsm;
    __half* Ww = gsm + 2 * GA_STRIDE;

    const int tid  = threadIdx.x;
    const int warp = tid >> 5;
    const int lane = tid & 31;
    const int wm   = warp >> 2;
    const int wn   = warp & 3;
    const int gid  = lane >> 2;
    const int tig  = lane & 3;
    const int m0   = blockIdx.y * 128;
    const int n0   = blockIdx.x * 128;

    const int aRow = (lane & 15);
    const int aCol = (lane >> 4) * 8;
    const int bRow = (lane & 7) + ((lane >> 4) & 1) * 8;
    const int bCol = ((lane >> 3) & 1) * 8;

    float acc[4][4][4];
    #pragma unroll
    for (int mt = 0; mt < 4; mt++)
        #pragma unroll
        for (int nt = 0; nt < 4; nt++)
            #pragma unroll
            for (int i = 0; i < 4; i++)
                acc[mt][nt][i] = 0.0f;

    const int nchunk = K >> 6;   // 16

    auto stage = [&](int ck, int buf) {
        int k0 = ck * 64;
        #pragma unroll
        for (int it = 0; it < 4; it++) {
            int slot = tid + it * 256;
            int r    = slot >> 3;
            int c8   = (slot & 7) * 8;
            cp16(&Aa[buf * GA_STRIDE + r * GPH + c8],
                 A + (size_t)(m0 + r) * K + k0 + c8);
            cp16(&Ww[buf * GA_STRIDE + r * GPH + c8],
                 W + (size_t)(n0 + r) * K + k0 + c8);
        }
    };

    stage(0, 0);
    CP_COMMIT();

    for (int ck = 0; ck < nchunk; ck++) {
        int cur = ck & 1;
        if (ck + 1 < nchunk) stage(ck + 1, cur ^ 1);
        CP_COMMIT();
        CP_WAIT1();
        __syncthreads();

        const __half* Af = Aa + cur * GA_STRIDE;
        const __half* Wf = Ww + cur * GA_STRIDE;
        #pragma unroll
        for (int ks = 0; ks < 4; ks++) {
            uint32_t a[4][4], b[4][2];
            #pragma unroll
            for (int mt = 0; mt < 4; mt++)
                ldmx4(a[mt][0], a[mt][1], a[mt][2], a[mt][3],
                      &Af[(wm * 64 + mt * 16 + aRow) * GPH + ks * 16 + aCol]);
            #pragma unroll
            for (int pr = 0; pr < 2; pr++)
                ldmx4(b[pr * 2][0], b[pr * 2][1], b[pr * 2 + 1][0], b[pr * 2 + 1][1],
                      &Wf[(wn * 32 + pr * 16 + bRow) * GPH + ks * 16 + bCol]);
            #pragma unroll
            for (int mt = 0; mt < 4; mt++)
                #pragma unroll
                for (int nt = 0; nt < 4; nt++)
                    mma_f16(acc[mt][nt], a[mt], b[nt]);
        }
        __syncthreads();
    }

    #pragma unroll
    for (int mt = 0; mt < 4; mt++) {
        int r0 = m0 + wm * 64 + mt * 16 + gid;
        #pragma unroll
        for (int nt = 0; nt < 4; nt++) {
            int c = n0 + wn * 32 + nt * 8 + tig * 2;
            float bx = bias[c], by = bias[c + 1];
            float r00 = (acc[mt][nt][0] + bx) * scale;
            float r01 = (acc[mt][nt][1] + by) * scale;
            float r10 = (acc[mt][nt][2] + bx) * scale;
            float r11 = (acc[mt][nt][3] + by) * scale;
            if (HALF_OUT) {
                __half* C = (__half*)Cout;
                *(uint32_t*)(C + (size_t)r0 * N + c)       = pack_h2(r00, r01);
                *(uint32_t*)(C + (size_t)(r0 + 8) * N + c) = pack_h2(r10, r11);
            } else {
                float* C = (float*)Cout;
                float2 v0 = { r00, r01 };
                float2 v1 = { r10, r11 };
                *(float2*)(C + (size_t)r0 * N + c) = v0;
                *(float2*)(C + (size_t)(r0 + 8) * N + c) = v1;
            }
        }
    }
}

#define GEMM_SMEM (4 * GA_STRIDE * (int)sizeof(__half))   // 73728 B

__global__ __launch_bounds__(256, 2) void gemm_qkv(
    const __half* __restrict__ xq, const __half* __restrict__ xk,
    const __half* __restrict__ xv, const __half* __restrict__ w3,
    const float* __restrict__ bq, const float* __restrict__ bk,
    const float* __restrict__ bv,
    __half* __restrict__ Q, __half* __restrict__ K, __half* __restrict__ V,
    int M, int N, int Kd)
{
    const __half *A, *W;
    const float* bias;
    __half* C;
    float scale;
    if (blockIdx.z == 0) {
        A = xq; W = w3;                bias = bq; C = Q; scale = QSCALE;
    } else if (blockIdx.z == 1) {
        A = xk; W = w3 + DDM * DDM;     bias = bk; C = K; scale = 1.0f;
    } else {
        A = xv; W = w3 + 2 * DDM * DDM; bias = bv; C = V; scale = 1.0f;
    }
    gemm_f16_core<true>(A, W, bias, C, M, N, Kd, scale);
}

__global__ __launch_bounds__(256, 2) void gemm_out(
    const __half* __restrict__ A, const __half* __restrict__ W,
    const float* __restrict__ bias, float* __restrict__ C,
    int M, int N, int Kd)
{
    gemm_f16_core<false>(A, W, bias, C, M, N, Kd, 1.0f);
}

// ---------------------------------------------------------------------------
// Flash attention, fp16 m16n8k16, 32 query rows per warp (2 m-tiles).
// CTA = 128 query rows, 128 threads (4 warps), 2 CTAs/SM. Bk = 64, dk = 64.
// Base-2 softmax (Q pre-scaled by 0.125*log2 e). O-rescale skipped when the
// running max is unchanged (multiply-by-1.0 identity -> bit-exact skip).
// K b-frags via ldmatrix.x4; V b-frags via ldmatrix.x4.trans.
// P: fp16 QK accumulator pairs ARE the PV A-operands. racing_bias cancels.
// ---------------------------------------------------------------------------
#define KPH 72
#define TSTR (64 * KPH)
#define STG  (2 * TSTR)
#define FLASH_SMEM (3 * STG * (int)sizeof(__half))   // 55296 B

__global__ __launch_bounds__(128, 2) void flash_f16(
    const __half* __restrict__ Q, const __half* __restrict__ K,
    const __half* __restrict__ V, __half* __restrict__ O)
{
    extern __shared__ __half fsm[];

    const int tid  = threadIdx.x;
    const int warp = tid >> 5;
    const int lane = tid & 31;
    const int gid  = lane >> 2;
    const int tig  = lane & 3;
    const int b    = blockIdx.y / HH;
    const int h    = blockIdx.y % HH;
    const int q0   = blockIdx.x * 128;

    const int bRow = (lane & 7) + ((lane >> 4) & 1) * 8;   // K (non-trans)
    const int bCol = ((lane >> 3) & 1) * 8;
    const int vKey = (lane & 7) + ((lane >> 3) & 1) * 8;   // V (trans)
    const int vCol = ((lane >> 4) & 1) * 8;

    const __half* Qb = Q + ((size_t)(b * SSQ + q0 + warp * 32)) * DDM + h * DKK;
    const __half* Kb = K + ((size_t)(b * SSQ)) * DDM + h * DKK;
    const __half* Vb = V + ((size_t)(b * SSQ)) * DDM + h * DKK;

    // Q fragments (half, pre-scaled by QSCALE): 4 k16-chunks, 4 regs each.
    uint32_t qf[2][4][4];
    #pragma unroll
    for (int mt = 0; mt < 2; mt++) {
        const uint32_t* Qr0 = (const uint32_t*)(Qb + (size_t)(mt * 16 + gid) * DDM);
        const uint32_t* Qr1 = (const uint32_t*)(Qb + (size_t)(mt * 16 + gid + 8) * DDM);
        #pragma unroll
        for (int c = 0; c < 4; c++) {
            qf[mt][c][0] = Qr0[c * 8 + tig];
            qf[mt][c][1] = Qr1[c * 8 + tig];
            qf[mt][c][2] = Qr0[c * 8 + tig + 4];
            qf[mt][c][3] = Qr1[c * 8 + tig + 4];
        }
    }

    float mrow[2][2], lrow[2][2];
    float o[2][8][4];
    #pragma unroll
    for (int mt = 0; mt < 2; mt++) {
        mrow[mt][0] = -1e30f; mrow[mt][1] = -1e30f;
        lrow[mt][0] = 0.0f;   lrow[mt][1] = 0.0f;
        #pragma unroll
        for (int nt = 0; nt < 8; nt++)
            #pragma unroll
            for (int i = 0; i < 4; i++) o[mt][nt][i] = 0.0f;
    }

    auto stage = [&](int ck, int buf) {
        const __half* Kg = Kb + (size_t)(ck * 64) * DDM;
        const __half* Vg = Vb + (size_t)(ck * 64) * DDM;
        __half* Kd = fsm + buf * STG;
        __half* Vd = fsm + buf * STG + TSTR;
        #pragma unroll
        for (int it = 0; it < 4; it++) {
            int seg = tid + it * 128;        // 0..511
            int r   = seg >> 3;              // key 0..63
            int c8  = (seg & 7) * 8;         // d 0..56 halves
            cp16(&Kd[r * KPH + c8], Kg + (size_t)r * DDM + c8);
            cp16(&Vd[r * KPH + c8], Vg + (size_t)r * DDM + c8);
        }
    };

    stage(0, 0); CP_COMMIT();
    stage(1, 1); CP_COMMIT();

    const int niter = SSQ / 64;   // 32
    for (int ck = 0; ck < niter; ck++) {
        int cur = ck % 3;
        CP_WAIT1();
        __syncthreads();
        if (ck + 2 < niter) stage(ck + 2, (ck + 2) % 3);
        CP_COMMIT();

        const __half* Kh = fsm + cur * STG;
        const __half* Vh = fsm + cur * STG + TSTR;

        // S (base-2 logits) = (Q * 0.125*log2 e) @ K^T
        float s[2][8][4];
        #pragma unroll
        for (int mt = 0; mt < 2; mt++)
            #pragma unroll
            for (int nt = 0; nt < 8; nt++)
                #pragma unroll
                for (int i = 0; i < 4; i++) s[mt][nt][i] = 0.0f;

        #pragma unroll
        for (int c = 0; c < 4; c++) {
            #pragma unroll
            for (int ntp = 0; ntp < 4; ntp++) {
                uint32_t b0[2], b1[2];
                ldmx4(b0[0], b0[1], b1[0], b1[1],
                      &Kh[(ntp * 16 + bRow) * KPH + c * 16 + bCol]);
                mma_f16(s[0][ntp * 2],     qf[0][c], b0);
                mma_f16(s[1][ntp * 2],     qf[1][c], b0);
                mma_f16(s[0][ntp * 2 + 1], qf[0][c], b1);
                mma_f16(s[1][ntp * 2 + 1], qf[1][c], b1);
            }
        }

        // Online softmax (base 2); P packed half2 = exact PV A-operands.
        uint32_t sh[2][8][2];
        #pragma unroll
        for (int mt = 0; mt < 2; mt++) {
            float mx0 = -1e30f, mx1 = -1e30f;
            #pragma unroll
            for (int nt = 0; nt < 8; nt++) {
                mx0 = fmaxf(mx0, fmaxf(s[mt][nt][0], s[mt][nt][1]));
                mx1 = fmaxf(mx1, fmaxf(s[mt][nt][2], s[mt][nt][3]));
            }
            mx0 = fmaxf(mx0, __shfl_xor_sync(0xffffffffu, mx0, 1));
            mx0 = fmaxf(mx0, __shfl_xor_sync(0xffffffffu, mx0, 2));
            mx1 = fmaxf(mx1, __shfl_xor_sync(0xffffffffu, mx1, 1));
            mx1 = fmaxf(mx1, __shfl_xor_sync(0xffffffffu, mx1, 2));

            float m0 = mrow[mt][0], m1 = mrow[mt][1];
            float nm0 = fmaxf(m0, mx0), nm1 = fmaxf(m1, mx1);
            bool chg = (nm0 > m0) || (nm1 > m1);
            float rs0 = 0.0f, rs1 = 0.0f;

            #pragma unroll
            for (int nt = 0; nt < 8; nt++) {
                float e0 = ex2(s[mt][nt][0] - nm0);
                float e1 = ex2(s[mt][nt][1] - nm0);
                float e2 = ex2(s[mt][nt][2] - nm1);
                float e3 = ex2(s[mt][nt][3] - nm1);
                __half2 h01 = __float22half2_rn(make_float2(e0, e1));
                __half2 h23 = __float22half2_rn(make_float2(e2, e3));
                sh[mt][nt][0] = *(uint32_t*)&h01;
                sh[mt][nt][1] = *(uint32_t*)&h23;
                float2 f01 = __half22float2(h01);
                float2 f23 = __half22float2(h23);
                rs0 += f01.x + f01.y;
                rs1 += f23.x + f23.y;
            }
            rs0 += __shfl_xor_sync(0xffffffffu, rs0, 1);
            rs0 += __shfl_xor_sync(0xffffffffu, rs0, 2);
            rs1 += __shfl_xor_sync(0xffffffffu, rs1, 1);
            rs1 += __shfl_xor_sync(0xffffffffu, rs1, 2);

            if (__any_sync(0xffffffffu, chg)) {
                float cr0 = ex2(m0 - nm0), cr1 = ex2(m1 - nm1);
                lrow[mt][0] = lrow[mt][0] * cr0 + rs0;
                lrow[mt][1] = lrow[mt][1] * cr1 + rs1;
                mrow[mt][0] = nm0;  mrow[mt][1] = nm1;
                #pragma unroll
                for (int nt = 0; nt < 8; nt++) {
                    o[mt][nt][0] *= cr0; o[mt][nt][1] *= cr0;
                    o[mt][nt][2] *= cr1; o[mt][nt][3] *= cr1;
                }
            } else {
                lrow[mt][0] += rs0;
                lrow[mt][1] += rs1;
            }
        }

        // O += P @ V : 4 k16-chunks (keys) x 8 n-tiles (dk), V via ldmatrix.trans
        #pragma unroll
        for (int j = 0; j < 4; j++) {
            uint32_t af[2][4];
            #pragma unroll
            for (int mt = 0; mt < 2; mt++) {
                af[mt][0] = sh[mt][2 * j][0];
                af[mt][1] = sh[mt][2 * j][1];
                af[mt][2] = sh[mt][2 * j + 1][0];
                af[mt][3] = sh[mt][2 * j + 1][1];
            }
            #pragma unroll
            for (int dtp = 0; dtp < 4; dtp++) {
                uint32_t b0[2], b1[2];
                ldmx4t(b0[0], b0[1], b1[0], b1[1],
                       &Vh[(j * 16 + vKey) * KPH + dtp * 16 + vCol]);
                mma_f16(o[0][dtp * 2],     af[0], b0);
                mma_f16(o[1][dtp * 2],     af[1], b0);
                mma_f16(o[0][dtp * 2 + 1], af[0], b1);
                mma_f16(o[1][dtp * 2 + 1], af[1], b1);
            }
        }
    }

    // Epilogue: normalize, round to half (O-proj consumes half), store.
    #pragma unroll
    for (int mt = 0; mt < 2; mt++) {
        float il0 = 1.0f / lrow[mt][0], il1 = 1.0f / lrow[mt][1];
        __half* Ob = O + ((size_t)(b * SSQ + q0 + warp * 32 + mt * 16)) * DDM
                       + h * DKK;
        #pragma unroll
        for (int nt = 0; nt < 8; nt++) {
            int c = nt * 8 + tig * 2;
            *(uint32_t*)(Ob + (size_t)gid * DDM + c) =
                pack_h2(o[mt][nt][0] * il0, o[mt][nt][1] * il0);
            *(uint32_t*)(Ob + (size_t)(gid + 8) * DDM + c) =
                pack_h2(o[mt][nt][2] * il1, o[mt][nt][3] * il1);
        }
    }
}

// ---------------------------------------------------------------------------
extern "C" void kernel_launch(void* const* d_in, const int* in_sizes, int n_in,
                              void* d_out, int out_size)
{
    (void)in_sizes; (void)n_in; (void)out_size;
    const float* query = (const float*)d_in[0];
    const float* key_  = (const float*)d_in[1];
    const float* value = (const float*)d_in[2];
    const float* wq = (const float*)d_in[3];
    const float* bq = (const float*)d_in[4];
    const float* wk = (const float*)d_in[5];
    const float* bk = (const float*)d_in[6];
    const float* wv = (const float*)d_in[7];
    const float* bv = (const float*)d_in[8];
    const float* wo = (const float*)d_in[9];
    const float* bo = (const float*)d_in[10];
    // d_in[11] = racing_bias: constant over softmax axis -> cancels exactly.
    float* out = (float*)d_out;

    __half *Qp, *Kp, *Vp, *Cp, *Xq, *Xk, *Xv, *Wr;
    cudaGetSymbolAddress((void**)&Qp, g_Q);
    cudaGetSymbolAddress((void**)&Kp, g_K);
    cudaGetSymbolAddress((void**)&Vp, g_V);
    cudaGetSymbolAddress((void**)&Cp, g_C);
    cudaGetSymbolAddress((void**)&Xq, g_Xq);
    cudaGetSymbolAddress((void**)&Xk, g_Xk);
    cudaGetSymbolAddress((void**)&Xv, g_Xv);
    cudaGetSymbolAddress((void**)&Wr, g_Wr);

    const int M = BB * SSQ;
    const int N = DDM;
    const int Kdim = DDM;

    cudaFuncSetAttribute(gemm_qkv,
        cudaFuncAttributeMaxDynamicSharedMemorySize, GEMM_SMEM);
    cudaFuncSetAttribute(gemm_out,
        cudaFuncAttributeMaxDynamicSharedMemorySize, GEMM_SMEM);
    cudaFuncSetAttribute(flash_f16,
        cudaFuncAttributeMaxDynamicSharedMemorySize, FLASH_SMEM);

    // Convert inputs + weights to half (one-time rounding point, 2 launches).
    const int nIn = M * DDM;
    const int nW  = DDM * DDM;
    {
        dim3 g3(nIn / 2048, 1, 3);
        prehalf3<<<g3, 256>>>(query, key_, value, Xq, Xk, Xv, nIn);
        dim3 g4(nW / 2048, 1, 4);
        prehalf4<<<g4, 256>>>(wq, wk, wv, wo, Wr, nW);
    }

    // Fused Q/K/V projections (fp16 tensor cores, ldmatrix, cp.async).
    dim3 qkvGrid(N / 128, M / 128, 3);
    gemm_qkv<<<qkvGrid, 256, GEMM_SMEM>>>(Xq, Xk, Xv, Wr, bq, bk, bv,
                                          Qp, Kp, Vp, M, N, Kdim);

    // Flash attention (fp16 mma, base-2 softmax, 128-thread CTAs).
    dim3 fGrid(SSQ / 128, BB * HH);   // (16, 32) = 512 CTAs
    flash_f16<<<fGrid, 128, FLASH_SMEM>>>(Qp, Kp, Vp, Cp);

    // Output projection (fp16 in, fp32 out).
    dim3 oGrid(N / 128, M / 128, 1);
    gemm_out<<<oGrid, 256, GEMM_SMEM>>>(Cp, Wr + 3 * nW, bo, out,
                                        M, N, Kdim);
}

// round 11
// speedup vs baseline: 7.4981x; 1.0159x over previous
#include <cuda_runtime.h>
#include <cuda_fp16.h>
#include <cstdint>

// Problem constants
#define BB   2
#define SSQ  2048
#define DDM  1024
#define HH   16
#define DKK  64

// Scratch (no allocation allowed -> device globals).
__device__ __half g_Q[BB * SSQ * DDM];       // pre-scaled by 0.125*log2(e)
__device__ __half g_K[BB * SSQ * DDM];
__device__ __half g_V[BB * SSQ * DDM];
__device__ __half g_C[BB * SSQ * DDM];       // ctx
__device__ __half g_Xq[BB * SSQ * DDM];      // half inputs
__device__ __half g_Xk[BB * SSQ * DDM];
__device__ __half g_Xv[BB * SSQ * DDM];
__device__ __half g_Wr[4 * DDM * DDM];       // wq | wk | wv | wo (half)

#define QSCALE (0.125f * 1.4426950408889634f)   // 1/sqrt(dk) * log2(e)

// ---------------------------------------------------------------------------
// helpers
// ---------------------------------------------------------------------------
__device__ __forceinline__ void mma_f16(float d[4], const uint32_t a[4],
                                        const uint32_t b[2]) {
    asm volatile(
        "mma.sync.aligned.m16n8k16.row.col.f32.f16.f16.f32 "
        "{%0,%1,%2,%3}, {%4,%5,%6,%7}, {%8,%9}, {%0,%1,%2,%3};"
        : "+f"(d[0]), "+f"(d[1]), "+f"(d[2]), "+f"(d[3])
        : "r"(a[0]), "r"(a[1]), "r"(a[2]), "r"(a[3]), "r"(b[0]), "r"(b[1]));
}

__device__ __forceinline__ void ldmx4(uint32_t& r0, uint32_t& r1,
                                      uint32_t& r2, uint32_t& r3,
                                      const void* p) {
    uint32_t a = (uint32_t)__cvta_generic_to_shared(p);
    asm volatile("ldmatrix.sync.aligned.m8n8.x4.shared.b16 {%0,%1,%2,%3}, [%4];"
                 : "=r"(r0), "=r"(r1), "=r"(r2), "=r"(r3) : "r"(a));
}

__device__ __forceinline__ void ldmx4t(uint32_t& r0, uint32_t& r1,
                                       uint32_t& r2, uint32_t& r3,
                                       const void* p) {
    uint32_t a = (uint32_t)__cvta_generic_to_shared(p);
    asm volatile("ldmatrix.sync.aligned.m8n8.x4.trans.shared.b16 {%0,%1,%2,%3}, [%4];"
                 : "=r"(r0), "=r"(r1), "=r"(r2), "=r"(r3) : "r"(a));
}

__device__ __forceinline__ void cp16(void* smem_dst, const void* gsrc) {
    asm volatile("cp.async.ca.shared.global [%0], [%1], 16;"
                 :: "r"((uint32_t)__cvta_generic_to_shared(smem_dst)),
                    "l"(gsrc));
}
#define CP_COMMIT() asm volatile("cp.async.commit_group;")
#define CP_WAIT1()  asm volatile("cp.async.wait_group 1;")

__device__ __forceinline__ uint32_t pack_h2(float lo, float hi) {
    __half2 h = __float22half2_rn(make_float2(lo, hi));
    return *(uint32_t*)&h;
}

__device__ __forceinline__ float ex2(float x) {
    float y;
    asm("ex2.approx.f32 %0, %1;" : "=f"(y) : "f"(x));
    return y;
}

// ---------------------------------------------------------------------------
// prehalf (z-indexed, 2 launches total): dst[i] = half(src[i]).
// ---------------------------------------------------------------------------
__global__ __launch_bounds__(256) void prehalf3(
    const float* __restrict__ s0, const float* __restrict__ s1,
    const float* __restrict__ s2,
    __half* __restrict__ d0, __half* __restrict__ d1, __half* __restrict__ d2,
    int n)
{
    const float* s; __half* d;
    if (blockIdx.z == 0)      { s = s0; d = d0; }
    else if (blockIdx.z == 1) { s = s1; d = d1; }
    else                      { s = s2; d = d2; }
    int i = (blockIdx.x * 256 + threadIdx.x) * 8;
    if (i >= n) return;
    float4 v0 = *(const float4*)(s + i);
    float4 v1 = *(const float4*)(s + i + 4);
    uint4 t = { pack_h2(v0.x, v0.y), pack_h2(v0.z, v0.w),
                pack_h2(v1.x, v1.y), pack_h2(v1.z, v1.w) };
    *(uint4*)(d + i) = t;
}

__global__ __launch_bounds__(256) void prehalf4(
    const float* __restrict__ s0, const float* __restrict__ s1,
    const float* __restrict__ s2, const float* __restrict__ s3,
    __half* __restrict__ dst, int n)
{
    const float* s;
    if (blockIdx.z == 0)      s = s0;
    else if (blockIdx.z == 1) s = s1;
    else if (blockIdx.z == 2) s = s2;
    else                      s = s3;
    __half* d = dst + (size_t)blockIdx.z * n;
    int i = (blockIdx.x * 256 + threadIdx.x) * 8;
    if (i >= n) return;
    float4 v0 = *(const float4*)(s + i);
    float4 v1 = *(const float4*)(s + i + 4);
    uint4 t = { pack_h2(v0.x, v0.y), pack_h2(v0.z, v0.w),
                pack_h2(v1.x, v1.y), pack_h2(v1.z, v1.w) };
    *(uint4*)(d + i) = t;
}

// ---------------------------------------------------------------------------
// fp16 GEMM: C[M,N] = A[M,K] @ W[N,K]^T + bias[N], optional scale + half out.
// Block tile 128x128, k-chunk 64 (4 k16 steps), 256 threads, 2-stage
// cp.async pipeline, ldmatrix fragment loads. Rows padded to 72 halves.
// ---------------------------------------------------------------------------
#define GPH 72
#define GA_STRIDE (128 * GPH)

template <bool HALF_OUT>
__device__ __forceinline__ void gemm_f16_core(
    const __half* __restrict__ A, const __half* __restrict__ W,
    const float* __restrict__ bias, void* __restrict__ Cout,
    int M, int N, int K, float scale)
{
    extern __shared__ __half gsm[];
    __half* Aa = gsm;
    __half* Ww = gsm + 2 * GA_STRIDE;

    const int tid  = threadIdx.x;
    const int warp = tid >> 5;
    const int lane = tid & 31;
    const int wm   = warp >> 2;
    const int wn   = warp & 3;
    const int gid  = lane >> 2;
    const int tig  = lane & 3;
    const int m0   = blockIdx.y * 128;
    const int n0   = blockIdx.x * 128;

    const int aRow = (lane & 15);
    const int aCol = (lane >> 4) * 8;
    const int bRow = (lane & 7) + ((lane >> 4) & 1) * 8;
    const int bCol = ((lane >> 3) & 1) * 8;

    float acc[4][4][4];
    #pragma unroll
    for (int mt = 0; mt < 4; mt++)
        #pragma unroll
        for (int nt = 0; nt < 4; nt++)
            #pragma unroll
            for (int i = 0; i < 4; i++)
                acc[mt][nt][i] = 0.0f;

    const int nchunk = K >> 6;   // 16

    auto stage = [&](int ck, int buf) {
        int k0 = ck * 64;
        #pragma unroll
        for (int it = 0; it < 4; it++) {
            int slot = tid + it * 256;
            int r    = slot >> 3;
            int c8   = (slot & 7) * 8;
            cp16(&Aa[buf * GA_STRIDE + r * GPH + c8],
                 A + (size_t)(m0 + r) * K + k0 + c8);
            cp16(&Ww[buf * GA_STRIDE + r * GPH + c8],
                 W + (size_t)(n0 + r) * K + k0 + c8);
        }
    };

    stage(0, 0);
    CP_COMMIT();

    for (int ck = 0; ck < nchunk; ck++) {
        int cur = ck & 1;
        if (ck + 1 < nchunk) stage(ck + 1, cur ^ 1);
        CP_COMMIT();
        CP_WAIT1();
        __syncthreads();

        const __half* Af = Aa + cur * GA_STRIDE;
        const __half* Wf = Ww + cur * GA_STRIDE;
        #pragma unroll
        for (int ks = 0; ks < 4; ks++) {
            uint32_t a[4][4], b[4][2];
            #pragma unroll
            for (int mt = 0; mt < 4; mt++)
                ldmx4(a[mt][0], a[mt][1], a[mt][2], a[mt][3],
                      &Af[(wm * 64 + mt * 16 + aRow) * GPH + ks * 16 + aCol]);
            #pragma unroll
            for (int pr = 0; pr < 2; pr++)
                ldmx4(b[pr * 2][0], b[pr * 2][1], b[pr * 2 + 1][0], b[pr * 2 + 1][1],
                      &Wf[(wn * 32 + pr * 16 + bRow) * GPH + ks * 16 + bCol]);
            #pragma unroll
            for (int mt = 0; mt < 4; mt++)
                #pragma unroll
                for (int nt = 0; nt < 4; nt++)
                    mma_f16(acc[mt][nt], a[mt], b[nt]);
        }
        __syncthreads();
    }

    #pragma unroll
    for (int mt = 0; mt < 4; mt++) {
        int r0 = m0 + wm * 64 + mt * 16 + gid;
        #pragma unroll
        for (int nt = 0; nt < 4; nt++) {
            int c = n0 + wn * 32 + nt * 8 + tig * 2;
            float bx = bias[c], by = bias[c + 1];
            float r00 = (acc[mt][nt][0] + bx) * scale;
            float r01 = (acc[mt][nt][1] + by) * scale;
            float r10 = (acc[mt][nt][2] + bx) * scale;
            float r11 = (acc[mt][nt][3] + by) * scale;
            if (HALF_OUT) {
                __half* C = (__half*)Cout;
                *(uint32_t*)(C + (size_t)r0 * N + c)       = pack_h2(r00, r01);
                *(uint32_t*)(C + (size_t)(r0 + 8) * N + c) = pack_h2(r10, r11);
            } else {
                float* C = (float*)Cout;
                float2 v0 = { r00, r01 };
                float2 v1 = { r10, r11 };
                *(float2*)(C + (size_t)r0 * N + c) = v0;
                *(float2*)(C + (size_t)(r0 + 8) * N + c) = v1;
            }
        }
    }
}

#define GEMM_SMEM (4 * GA_STRIDE * (int)sizeof(__half))   // 73728 B

__global__ __launch_bounds__(256, 2) void gemm_qkv(
    const __half* __restrict__ xq, const __half* __restrict__ xk,
    const __half* __restrict__ xv, const __half* __restrict__ w3,
    const float* __restrict__ bq, const float* __restrict__ bk,
    const float* __restrict__ bv,
    __half* __restrict__ Q, __half* __restrict__ K, __half* __restrict__ V,
    int M, int N, int Kd)
{
    const __half *A, *W;
    const float* bias;
    __half* C;
    float scale;
    if (blockIdx.z == 0) {
        A = xq; W = w3;                bias = bq; C = Q; scale = QSCALE;
    } else if (blockIdx.z == 1) {
        A = xk; W = w3 + DDM * DDM;     bias = bk; C = K; scale = 1.0f;
    } else {
        A = xv; W = w3 + 2 * DDM * DDM; bias = bv; C = V; scale = 1.0f;
    }
    gemm_f16_core<true>(A, W, bias, C, M, N, Kd, scale);
}

__global__ __launch_bounds__(256, 2) void gemm_out(
    const __half* __restrict__ A, const __half* __restrict__ W,
    const float* __restrict__ bias, float* __restrict__ C,
    int M, int N, int Kd)
{
    gemm_f16_core<false>(A, W, bias, C, M, N, Kd, 1.0f);
}

// ---------------------------------------------------------------------------
// Flash attention, fp16 m16n8k16, ONE 16-row m-tile per warp (low-reg).
// CTA = 64 query rows, 128 threads (4 warps), target 4 CTAs/SM = 16 warps.
// 2-stage cp.async pipeline (smem 36.9 KB -> 4 CTAs fit). Bk = 64, dk = 64.
// Base-2 softmax (Q pre-scaled by 0.125*log2 e); rescale skipped when the
// running max is unchanged (multiply-by-1.0 identity -> bit-exact skip).
// K b-frags via ldmatrix.x4; V b-frags via ldmatrix.x4.trans.
// P: fp16 QK accumulator pairs ARE the PV A-operands. racing_bias cancels.
// ---------------------------------------------------------------------------
#define KPH 72
#define TSTR (64 * KPH)
#define STG  (2 * TSTR)
#define FLASH_SMEM (2 * STG * (int)sizeof(__half))   // 36864 B

__global__ __launch_bounds__(128, 4) void flash_f16(
    const __half* __restrict__ Q, const __half* __restrict__ K,
    const __half* __restrict__ V, __half* __restrict__ O)
{
    extern __shared__ __half fsm[];

    const int tid  = threadIdx.x;
    const int warp = tid >> 5;
    const int lane = tid & 31;
    const int gid  = lane >> 2;
    const int tig  = lane & 3;
    const int b    = blockIdx.y / HH;
    const int h    = blockIdx.y % HH;
    const int q0   = blockIdx.x * 64;

    const int bRow = (lane & 7) + ((lane >> 4) & 1) * 8;   // K (non-trans)
    const int bCol = ((lane >> 3) & 1) * 8;
    const int vKey = (lane & 7) + ((lane >> 3) & 1) * 8;   // V (trans)
    const int vCol = ((lane >> 4) & 1) * 8;

    const __half* Qb = Q + ((size_t)(b * SSQ + q0 + warp * 16)) * DDM + h * DKK;
    const __half* Kb = K + ((size_t)(b * SSQ)) * DDM + h * DKK;
    const __half* Vb = V + ((size_t)(b * SSQ)) * DDM + h * DKK;

    // Q fragments (half, pre-scaled by QSCALE): 4 k16-chunks, 4 regs each.
    uint32_t qf[4][4];
    {
        const uint32_t* Qr0 = (const uint32_t*)(Qb + (size_t)gid * DDM);
        const uint32_t* Qr1 = (const uint32_t*)(Qb + (size_t)(gid + 8) * DDM);
        #pragma unroll
        for (int c = 0; c < 4; c++) {
            qf[c][0] = Qr0[c * 8 + tig];
            qf[c][1] = Qr1[c * 8 + tig];
            qf[c][2] = Qr0[c * 8 + tig + 4];
            qf[c][3] = Qr1[c * 8 + tig + 4];
        }
    }

    float m0r = -1e30f, m1r = -1e30f, l0r = 0.0f, l1r = 0.0f;
    float o[8][4];
    #pragma unroll
    for (int nt = 0; nt < 8; nt++)
        #pragma unroll
        for (int i = 0; i < 4; i++) o[nt][i] = 0.0f;

    auto stage = [&](int ck, int buf) {
        const __half* Kg = Kb + (size_t)(ck * 64) * DDM;
        const __half* Vg = Vb + (size_t)(ck * 64) * DDM;
        __half* Kd = fsm + buf * STG;
        __half* Vd = fsm + buf * STG + TSTR;
        #pragma unroll
        for (int it = 0; it < 4; it++) {
            int seg = tid + it * 128;        // 0..511
            int r   = seg >> 3;              // key 0..63
            int c8  = (seg & 7) * 8;         // d 0..56 halves
            cp16(&Kd[r * KPH + c8], Kg + (size_t)r * DDM + c8);
            cp16(&Vd[r * KPH + c8], Vg + (size_t)r * DDM + c8);
        }
    };

    stage(0, 0);
    CP_COMMIT();

    const int niter = SSQ / 64;   // 32
    for (int ck = 0; ck < niter; ck++) {
        int cur = ck & 1;
        if (ck + 1 < niter) stage(ck + 1, cur ^ 1);
        CP_COMMIT();
        CP_WAIT1();
        __syncthreads();

        const __half* Kh = fsm + cur * STG;
        const __half* Vh = fsm + cur * STG + TSTR;

        // S (base-2 logits) = (Q * QSCALE) @ K^T : 4 k16-steps x 8 n-tiles.
        float s[8][4];
        #pragma unroll
        for (int nt = 0; nt < 8; nt++)
            #pragma unroll
            for (int i = 0; i < 4; i++) s[nt][i] = 0.0f;

        #pragma unroll
        for (int c = 0; c < 4; c++) {
            #pragma unroll
            for (int ntp = 0; ntp < 4; ntp++) {
                uint32_t b0[2], b1[2];
                ldmx4(b0[0], b0[1], b1[0], b1[1],
                      &Kh[(ntp * 16 + bRow) * KPH + c * 16 + bCol]);
                mma_f16(s[ntp * 2],     qf[c], b0);
                mma_f16(s[ntp * 2 + 1], qf[c], b1);
            }
        }

        // Online softmax (base 2); P packed half2 = exact PV A-operands.
        uint32_t sh[8][2];
        {
            float mx0 = -1e30f, mx1 = -1e30f;
            #pragma unroll
            for (int nt = 0; nt < 8; nt++) {
                mx0 = fmaxf(mx0, fmaxf(s[nt][0], s[nt][1]));
                mx1 = fmaxf(mx1, fmaxf(s[nt][2], s[nt][3]));
            }
            mx0 = fmaxf(mx0, __shfl_xor_sync(0xffffffffu, mx0, 1));
            mx0 = fmaxf(mx0, __shfl_xor_sync(0xffffffffu, mx0, 2));
            mx1 = fmaxf(mx1, __shfl_xor_sync(0xffffffffu, mx1, 1));
            mx1 = fmaxf(mx1, __shfl_xor_sync(0xffffffffu, mx1, 2));

            float nm0 = fmaxf(m0r, mx0), nm1 = fmaxf(m1r, mx1);
            bool chg = (nm0 > m0r) || (nm1 > m1r);
            float rs0 = 0.0f, rs1 = 0.0f;

            #pragma unroll
            for (int nt = 0; nt < 8; nt++) {
                float e0 = ex2(s[nt][0] - nm0);
                float e1 = ex2(s[nt][1] - nm0);
                float e2 = ex2(s[nt][2] - nm1);
                float e3 = ex2(s[nt][3] - nm1);
                __half2 h01 = __float22half2_rn(make_float2(e0, e1));
                __half2 h23 = __float22half2_rn(make_float2(e2, e3));
                sh[nt][0] = *(uint32_t*)&h01;
                sh[nt][1] = *(uint32_t*)&h23;
                float2 f01 = __half22float2(h01);
                float2 f23 = __half22float2(h23);
                rs0 += f01.x + f01.y;
                rs1 += f23.x + f23.y;
            }
            rs0 += __shfl_xor_sync(0xffffffffu, rs0, 1);
            rs0 += __shfl_xor_sync(0xffffffffu, rs0, 2);
            rs1 += __shfl_xor_sync(0xffffffffu, rs1, 1);
            rs1 += __shfl_xor_sync(0xffffffffu, rs1, 2);

            if (__any_sync(0xffffffffu, chg)) {
                float cr0 = ex2(m0r - nm0), cr1 = ex2(m1r - nm1);
                l0r = l0r * cr0 + rs0;
                l1r = l1r * cr1 + rs1;
                m0r = nm0;  m1r = nm1;
                #pragma unroll
                for (int nt = 0; nt < 8; nt++) {
                    o[nt][0] *= cr0; o[nt][1] *= cr0;
                    o[nt][2] *= cr1; o[nt][3] *= cr1;
                }
            } else {
                l0r += rs0;
                l1r += rs1;
            }
        }

        // O += P @ V : 4 k16-chunks (keys) x 8 n-tiles (dk), V via ldmatrix.trans
        #pragma unroll
        for (int j = 0; j < 4; j++) {
            uint32_t af[4];
            af[0] = sh[2 * j][0];
            af[1] = sh[2 * j][1];
            af[2] = sh[2 * j + 1][0];
            af[3] = sh[2 * j + 1][1];
            #pragma unroll
            for (int dtp = 0; dtp < 4; dtp++) {
                uint32_t b0[2], b1[2];
                ldmx4t(b0[0], b0[1], b1[0], b1[1],
                       &Vh[(j * 16 + vKey) * KPH + dtp * 16 + vCol]);
                mma_f16(o[dtp * 2],     af, b0);
                mma_f16(o[dtp * 2 + 1], af, b1);
            }
        }
        __syncthreads();   // all reads of buf `cur` done before its restage
    }

    // Epilogue: normalize, round to half (O-proj consumes half), store.
    {
        float il0 = 1.0f / l0r, il1 = 1.0f / l1r;
        __half* Ob = O + ((size_t)(b * SSQ + q0 + warp * 16)) * DDM + h * DKK;
        #pragma unroll
        for (int nt = 0; nt < 8; nt++) {
            int c = nt * 8 + tig * 2;
            *(uint32_t*)(Ob + (size_t)gid * DDM + c) =
                pack_h2(o[nt][0] * il0, o[nt][1] * il0);
            *(uint32_t*)(Ob + (size_t)(gid + 8) * DDM + c) =
                pack_h2(o[nt][2] * il1, o[nt][3] * il1);
        }
    }
}

// ---------------------------------------------------------------------------
extern "C" void kernel_launch(void* const* d_in, const int* in_sizes, int n_in,
                              void* d_out, int out_size)
{
    (void)in_sizes; (void)n_in; (void)out_size;
    const float* query = (const float*)d_in[0];
    const float* key_  = (const float*)d_in[1];
    const float* value = (const float*)d_in[2];
    const float* wq = (const float*)d_in[3];
    const float* bq = (const float*)d_in[4];
    const float* wk = (const float*)d_in[5];
    const float* bk = (const float*)d_in[6];
    const float* wv = (const float*)d_in[7];
    const float* bv = (const float*)d_in[8];
    const float* wo = (const float*)d_in[9];
    const float* bo = (const float*)d_in[10];
    // d_in[11] = racing_bias: constant over softmax axis -> cancels exactly.
    float* out = (float*)d_out;

    __half *Qp, *Kp, *Vp, *Cp, *Xq, *Xk, *Xv, *Wr;
    cudaGetSymbolAddress((void**)&Qp, g_Q);
    cudaGetSymbolAddress((void**)&Kp, g_K);
    cudaGetSymbolAddress((void**)&Vp, g_V);
    cudaGetSymbolAddress((void**)&Cp, g_C);
    cudaGetSymbolAddress((void**)&Xq, g_Xq);
    cudaGetSymbolAddress((void**)&Xk, g_Xk);
    cudaGetSymbolAddress((void**)&Xv, g_Xv);
    cudaGetSymbolAddress((void**)&Wr, g_Wr);

    const int M = BB * SSQ;
    const int N = DDM;
    const int Kdim = DDM;

    cudaFuncSetAttribute(gemm_qkv,
        cudaFuncAttributeMaxDynamicSharedMemorySize, GEMM_SMEM);
    cudaFuncSetAttribute(gemm_out,
        cudaFuncAttributeMaxDynamicSharedMemorySize, GEMM_SMEM);
    cudaFuncSetAttribute(flash_f16,
        cudaFuncAttributeMaxDynamicSharedMemorySize, FLASH_SMEM);

    // Convert inputs + weights to half (one-time rounding point, 2 launches).
    const int nIn = M * DDM;
    const int nW  = DDM * DDM;
    {
        dim3 g3(nIn / 2048, 1, 3);
        prehalf3<<<g3, 256>>>(query, key_, value, Xq, Xk, Xv, nIn);
        dim3 g4(nW / 2048, 1, 4);
        prehalf4<<<g4, 256>>>(wq, wk, wv, wo, Wr, nW);
    }

    // Fused Q/K/V projections (fp16 tensor cores, ldmatrix, cp.async).
    dim3 qkvGrid(N / 128, M / 128, 3);
    gemm_qkv<<<qkvGrid, 256, GEMM_SMEM>>>(Xq, Xk, Xv, Wr, bq, bk, bv,
                                          Qp, Kp, Vp, M, N, Kdim);

    // Flash attention (fp16 mma, 16 rows/warp, 4 CTAs/SM target).
    dim3 fGrid(SSQ / 64, BB * HH);   // (32, 32) = 1024 CTAs
    flash_f16<<<fGrid, 128, FLASH_SMEM>>>(Qp, Kp, Vp, Cp);

    // Output projection (fp16 in, fp32 out).
    dim3 oGrid(N / 128, M / 128, 1);
    gemm_out<<<oGrid, 256, GEMM_SMEM>>>(Cp, Wr + 3 * nW, bo, out,
                                        M, N, Kdim);
}